// round 1
// baseline (speedup 1.0000x reference)
#include <cuda_runtime.h>
#include <math.h>

#define B_   2
#define L_   2048
#define E_   1024
#define H_   16
#define DH_  64
#define HID_ 4096
#define BH_  (B_*H_)    /* 32   */
#define ML_  (B_*L_)    /* 4096 */

// ---------------- scratch (device globals; no allocation allowed) ----------------
__device__ float g_Q [(size_t)ML_ * E_];            // 16 MB
__device__ float g_K [(size_t)ML_ * E_];
__device__ float g_V [(size_t)ML_ * E_];
__device__ float g_ST[(size_t)BH_ * L_ * L_];       // 536 MB, layout [bh][j][i] = S^T
__device__ float g_m [(size_t)BH_ * L_];            // column max m_j
__device__ float g_U [(size_t)BH_ * L_ * DH_];      // U[bh][j][d] = x_j * V / denom_j
__device__ float g_O [(size_t)ML_ * E_];            // attention output, row-major (B*L, E)
__device__ float g_Y1[(size_t)ML_ * HID_];          // 64 MB, gelu(O@W1+b1)

// ---------------- helpers ----------------
__device__ __forceinline__ float gelu_exact(float v) {
    return 0.5f * v * (1.0f + erff(v * 0.7071067811865476f));
}

// 256-thread block reductions (8 warps). sh must hold >= 8 floats.
__device__ __forceinline__ float blockMax256(float v, float* sh) {
    #pragma unroll
    for (int o = 16; o > 0; o >>= 1) v = fmaxf(v, __shfl_xor_sync(0xffffffffu, v, o));
    if ((threadIdx.x & 31) == 0) sh[threadIdx.x >> 5] = v;
    __syncthreads();
    if (threadIdx.x == 0) {
        float m = sh[0];
        #pragma unroll
        for (int i = 1; i < 8; i++) m = fmaxf(m, sh[i]);
        sh[0] = m;
    }
    __syncthreads();
    float r = sh[0];
    __syncthreads();
    return r;
}
__device__ __forceinline__ float blockSum256(float v, float* sh) {
    #pragma unroll
    for (int o = 16; o > 0; o >>= 1) v += __shfl_xor_sync(0xffffffffu, v, o);
    if ((threadIdx.x & 31) == 0) sh[threadIdx.x >> 5] = v;
    __syncthreads();
    if (threadIdx.x == 0) {
        float s = sh[0];
        #pragma unroll
        for (int i = 1; i < 8; i++) s += sh[i];
        sh[0] = s;
    }
    __syncthreads();
    float r = sh[0];
    __syncthreads();
    return r;
}

// ---------------- 1) generic SGEMM (row-major A[MxK] @ B[KxN] + bias, opt. exact GELU) ----------------
template<bool GELU>
__global__ void __launch_bounds__(256) sgemm_bias(const float* __restrict__ A,
                                                  const float* __restrict__ B,
                                                  const float* __restrict__ bias,
                                                  float* __restrict__ C,
                                                  int M, int N, int K)
{
    __shared__ float As[8][128];
    __shared__ float Bs[8][128];
    const int tid  = threadIdx.x;
    const int aRow = tid >> 1, aCol = (tid & 1) << 2;
    const int bRow = tid >> 5, bCol = (tid & 31) << 2;
    const float* Ab = A + (size_t)(blockIdx.y * 128) * K;
    const float* Bb = B + blockIdx.x * 128;
    float acc[8][8] = {};
    const int rowBase = (tid >> 4) << 3;
    const int colBase = (tid & 15) << 3;

    for (int k0 = 0; k0 < K; k0 += 8) {
        float4 a = *(const float4*)(Ab + (size_t)aRow * K + k0 + aCol);
        As[aCol + 0][aRow] = a.x; As[aCol + 1][aRow] = a.y;
        As[aCol + 2][aRow] = a.z; As[aCol + 3][aRow] = a.w;
        *(float4*)&Bs[bRow][bCol] = *(const float4*)(Bb + (size_t)(k0 + bRow) * N + bCol);
        __syncthreads();
        #pragma unroll
        for (int kk = 0; kk < 8; kk++) {
            float ra[8], rb[8];
            *(float4*)&ra[0] = *(float4*)&As[kk][rowBase];
            *(float4*)&ra[4] = *(float4*)&As[kk][rowBase + 4];
            *(float4*)&rb[0] = *(float4*)&Bs[kk][colBase];
            *(float4*)&rb[4] = *(float4*)&Bs[kk][colBase + 4];
            #pragma unroll
            for (int i = 0; i < 8; i++)
                #pragma unroll
                for (int j = 0; j < 8; j++)
                    acc[i][j] = fmaf(ra[i], rb[j], acc[i][j]);
        }
        __syncthreads();
    }
    const int crow0 = blockIdx.y * 128 + rowBase;
    const int ccol0 = blockIdx.x * 128 + colBase;
    #pragma unroll
    for (int i = 0; i < 8; i++) {
        #pragma unroll
        for (int j = 0; j < 8; j += 4) {
            float4 v;
            v.x = acc[i][j + 0] + bias[ccol0 + j + 0];
            v.y = acc[i][j + 1] + bias[ccol0 + j + 1];
            v.z = acc[i][j + 2] + bias[ccol0 + j + 2];
            v.w = acc[i][j + 3] + bias[ccol0 + j + 3];
            if (GELU) {
                v.x = gelu_exact(v.x); v.y = gelu_exact(v.y);
                v.z = gelu_exact(v.z); v.w = gelu_exact(v.w);
            }
            *(float4*)(C + (size_t)(crow0 + i) * N + ccol0 + j) = v;
        }
    }
}

// ---------------- 2) S^T[bh][j][i] = (K_j . Q_i) / 8   (NT GEMM, K'=64) ----------------
__global__ void __launch_bounds__(256) qk_kernel()
{
    const int bh = blockIdx.z;
    const int b = bh >> 4;            // /H_
    const int h = bh & 15;
    const int it = blockIdx.x, jt = blockIdx.y;
    __shared__ float Ks[16][128];
    __shared__ float Qs[16][128];
    const float* Kb = g_K + (size_t)b * L_ * E_ + h * DH_;  // row stride E_
    const float* Qb = g_Q + (size_t)b * L_ * E_ + h * DH_;
    const int tid = threadIdx.x;
    float acc[8][8] = {};
    const int rowBase = (tid >> 4) << 3;  // j
    const int colBase = (tid & 15) << 3;  // i

    for (int k0 = 0; k0 < DH_; k0 += 16) {
        #pragma unroll
        for (int t = 0; t < 2; t++) {
            int id = tid + t * 256;             // 0..511
            int r  = id >> 2;                   // 0..127
            int c4 = (id & 3) << 2;             // 0,4,8,12
            float4 kv = *(const float4*)(Kb + (size_t)(jt * 128 + r) * E_ + k0 + c4);
            Ks[c4 + 0][r] = kv.x; Ks[c4 + 1][r] = kv.y;
            Ks[c4 + 2][r] = kv.z; Ks[c4 + 3][r] = kv.w;
            float4 qv = *(const float4*)(Qb + (size_t)(it * 128 + r) * E_ + k0 + c4);
            Qs[c4 + 0][r] = qv.x; Qs[c4 + 1][r] = qv.y;
            Qs[c4 + 2][r] = qv.z; Qs[c4 + 3][r] = qv.w;
        }
        __syncthreads();
        #pragma unroll
        for (int kk = 0; kk < 16; kk++) {
            float ra[8], rb[8];
            *(float4*)&ra[0] = *(float4*)&Ks[kk][rowBase];
            *(float4*)&ra[4] = *(float4*)&Ks[kk][rowBase + 4];
            *(float4*)&rb[0] = *(float4*)&Qs[kk][colBase];
            *(float4*)&rb[4] = *(float4*)&Qs[kk][colBase + 4];
            #pragma unroll
            for (int i = 0; i < 8; i++)
                #pragma unroll
                for (int j = 0; j < 8; j++)
                    acc[i][j] = fmaf(ra[i], rb[j], acc[i][j]);
        }
        __syncthreads();
    }
    float* Cb = g_ST + ((size_t)bh * L_ + jt * 128 + rowBase) * L_ + it * 128 + colBase;
    #pragma unroll
    for (int i = 0; i < 8; i++) {
        #pragma unroll
        for (int j = 0; j < 8; j += 4) {
            float4 v;
            v.x = acc[i][j + 0] * 0.125f; v.y = acc[i][j + 1] * 0.125f;
            v.z = acc[i][j + 2] * 0.125f; v.w = acc[i][j + 3] * 0.125f;
            *(float4*)(Cb + (size_t)i * L_ + j) = v;
        }
    }
}

// ---------------- 3) per-column stats: m_j, denom_j; U[bh][j][d] = x_j*V/denom ----------------
__global__ void __launch_bounds__(256) stats_kernel(const float* __restrict__ x)
{
    __shared__ float red[8];
    const int row = blockIdx.x;          // bh*L + j
    const int bh = row >> 11;            // /L_
    const int j  = row & (L_ - 1);
    const int b = bh >> 4, h = bh & 15;
    const float* S  = g_ST + (size_t)row * L_;
    const float* xb = x + b * L_;
    const int tid = threadIdx.x;

    float v[8];
    float4 a0 = *(const float4*)(S + tid * 8);
    float4 a1 = *(const float4*)(S + tid * 8 + 4);
    v[0] = a0.x; v[1] = a0.y; v[2] = a0.z; v[3] = a0.w;
    v[4] = a1.x; v[5] = a1.y; v[6] = a1.z; v[7] = a1.w;

    float mx = v[0];
    #pragma unroll
    for (int q = 1; q < 8; q++) mx = fmaxf(mx, v[q]);
    const float m = blockMax256(mx, red);

    float s = 0.0f;
    #pragma unroll
    for (int q = 0; q < 8; q++) s += xb[tid * 8 + q] * __expf(v[q] - m);
    const float denom = blockSum256(s, red);

    if (tid == 0) g_m[row] = m;
    if (tid < DH_) {
        float vv = g_V[((size_t)b * L_ + j) * E_ + h * DH_ + tid];
        g_U[(size_t)row * DH_ + tid] = xb[j] * vv / denom;
    }
}

// ---------------- 4) O[b,i,h*DH+d] = x_i * sum_j exp(S^T[j,i] - m_j) * U[j,d] ----------------
__global__ void __launch_bounds__(256) attn_out_kernel(const float* __restrict__ x)
{
    const int bh = blockIdx.y;
    const int b = bh >> 4, h = bh & 15;
    const int it = blockIdx.x;                       // i tile (128)
    __shared__ float Es[16][128];
    __shared__ float Us[16][64];
    const float* Sb = g_ST + (size_t)bh * L_ * L_;
    const float* Ub = g_U  + (size_t)bh * L_ * DH_;
    const float* mb = g_m  + (size_t)bh * L_;
    const int tid = threadIdx.x;
    float acc[8][4] = {};
    const int rowBase = (tid >> 4) << 3;  // i
    const int colBase = (tid & 15) << 2;  // d

    for (int j0 = 0; j0 < L_; j0 += 16) {
        #pragma unroll
        for (int t = 0; t < 2; t++) {
            int id = tid + t * 256;          // 0..511
            int jj = id >> 5;                // 0..15
            int ic = (id & 31) << 2;         // 0..124
            float mj = mb[j0 + jj];
            float4 sv = *(const float4*)(Sb + (size_t)(j0 + jj) * L_ + it * 128 + ic);
            float4 ev;
            ev.x = __expf(sv.x - mj); ev.y = __expf(sv.y - mj);
            ev.z = __expf(sv.z - mj); ev.w = __expf(sv.w - mj);
            *(float4*)&Es[jj][ic] = ev;
        }
        {
            int jj = tid >> 4;               // 0..15
            int dc = (tid & 15) << 2;        // 0..60
            *(float4*)&Us[jj][dc] = *(const float4*)(Ub + (size_t)(j0 + jj) * DH_ + dc);
        }
        __syncthreads();
        #pragma unroll
        for (int kk = 0; kk < 16; kk++) {
            float rE[8], rU[4];
            *(float4*)&rE[0] = *(float4*)&Es[kk][rowBase];
            *(float4*)&rE[4] = *(float4*)&Es[kk][rowBase + 4];
            *(float4*)&rU[0] = *(float4*)&Us[kk][colBase];
            #pragma unroll
            for (int i = 0; i < 8; i++)
                #pragma unroll
                for (int j = 0; j < 4; j++)
                    acc[i][j] = fmaf(rE[i], rU[j], acc[i][j]);
        }
        __syncthreads();
    }
    #pragma unroll
    for (int i = 0; i < 8; i++) {
        int gi = it * 128 + rowBase + i;
        float xi = x[b * L_ + gi];
        float4 o;
        o.x = xi * acc[i][0]; o.y = xi * acc[i][1];
        o.z = xi * acc[i][2]; o.w = xi * acc[i][3];
        *(float4*)(g_O + ((size_t)b * L_ + gi) * E_ + h * DH_ + colBase) = o;
    }
}

// ---------------- 5) y[r] = b2 + sum_h Y1[r,h] * W2[h] ----------------
__global__ void __launch_bounds__(256) final_kernel(const float* __restrict__ W2,
                                                    const float* __restrict__ b2,
                                                    float* __restrict__ out)
{
    __shared__ float red[8];
    const int r = blockIdx.x;
    const float* Y = g_Y1 + (size_t)r * HID_;
    float s = 0.0f;
    for (int c = threadIdx.x * 4; c < HID_; c += 256 * 4) {
        float4 y4 = *(const float4*)(Y + c);
        float4 w4 = *(const float4*)(W2 + c);
        s += y4.x * w4.x + y4.y * w4.y + y4.z * w4.z + y4.w * w4.w;
    }
    s = blockSum256(s, red);
    if (threadIdx.x == 0) out[r] = s + b2[0];
}

// ---------------- launch ----------------
extern "C" void kernel_launch(void* const* d_in, const int* in_sizes, int n_in,
                              void* d_out, int out_size)
{
    (void)in_sizes; (void)n_in; (void)out_size;
    const float* x  = (const float*)d_in[0];
    const float* z  = (const float*)d_in[1];
    const float* Wq = (const float*)d_in[2];
    const float* bq = (const float*)d_in[3];
    const float* Wk = (const float*)d_in[4];
    const float* bk = (const float*)d_in[5];
    const float* Wv = (const float*)d_in[6];
    const float* bv = (const float*)d_in[7];
    const float* W1 = (const float*)d_in[8];
    const float* b1 = (const float*)d_in[9];
    const float* W2 = (const float*)d_in[10];
    const float* b2 = (const float*)d_in[11];

    float *pQ, *pK, *pV, *pO, *pY1;
    cudaGetSymbolAddress((void**)&pQ,  g_Q);
    cudaGetSymbolAddress((void**)&pK,  g_K);
    cudaGetSymbolAddress((void**)&pV,  g_V);
    cudaGetSymbolAddress((void**)&pO,  g_O);
    cudaGetSymbolAddress((void**)&pY1, g_Y1);

    // QKV projections
    dim3 gProj(E_ / 128, ML_ / 128);
    sgemm_bias<false><<<gProj, 256>>>(z, Wq, bq, pQ, ML_, E_, E_);
    sgemm_bias<false><<<gProj, 256>>>(z, Wk, bk, pK, ML_, E_, E_);
    sgemm_bias<false><<<gProj, 256>>>(z, Wv, bv, pV, ML_, E_, E_);

    // S^T = K Q^T / 8 per head
    qk_kernel<<<dim3(L_ / 128, L_ / 128, BH_), 256>>>();

    // column softmax stats + U
    stats_kernel<<<BH_ * L_, 256>>>(x);

    // O = x_i * exp(S - m) @ U
    attn_out_kernel<<<dim3(L_ / 128, BH_), 256>>>(x);

    // MLP layer 1 with exact GELU
    sgemm_bias<true><<<dim3(HID_ / 128, ML_ / 128), 256>>>(pO, W1, b1, pY1, ML_, HID_, E_);

    // final projection to scalar per token
    final_kernel<<<ML_, 256>>>(W2, b2, (float*)d_out);
}

// round 5
// speedup vs baseline: 2.1773x; 2.1773x over previous
#include <cuda_runtime.h>
#include <cuda_bf16.h>
#include <math.h>
#include <stdint.h>

#define B_   2
#define L_   2048
#define E_   1024
#define H_   16
#define DH_  64
#define HID_ 4096
#define BH_  (B_*H_)    /* 32   */
#define ML_  (B_*L_)    /* 4096 */

// ---------------- scratch (device globals; no allocation allowed) ----------------
__device__ __align__(128) float g_V [(size_t)ML_ * E_];
__device__ __align__(128) float g_ST[(size_t)BH_ * L_ * L_];   // [bh][j][i] = S^T
__device__ __align__(128) float g_m [(size_t)BH_ * L_];
__device__ __align__(128) float g_O [(size_t)ML_ * E_];
__device__ __align__(128) float g_Y1[(size_t)ML_ * HID_];

__device__ __align__(128) __nv_bfloat16 g_Ahi [(size_t)ML_ * E_];
__device__ __align__(128) __nv_bfloat16 g_Alo [(size_t)ML_ * E_];
__device__ __align__(128) __nv_bfloat16 g_Bthi[(size_t)HID_ * E_];
__device__ __align__(128) __nv_bfloat16 g_Btlo[(size_t)HID_ * E_];
__device__ __align__(128) __nv_bfloat16 g_Qhi [(size_t)ML_ * E_];
__device__ __align__(128) __nv_bfloat16 g_Qlo [(size_t)ML_ * E_];
__device__ __align__(128) __nv_bfloat16 g_Khi [(size_t)ML_ * E_];
__device__ __align__(128) __nv_bfloat16 g_Klo [(size_t)ML_ * E_];
__device__ __align__(128) __nv_bfloat16 g_Uh  [(size_t)BH_ * L_ * DH_];
__device__ __align__(128) __nv_bfloat16 g_Ul  [(size_t)BH_ * L_ * DH_];

// ---------------- ptx helpers (sm_80-compatible PTX only) ----------------
__device__ __forceinline__ uint32_t smem_u32(const void* p) {
    uint32_t a;
    asm("{ .reg .u64 t; cvta.to.shared.u64 t, %1; cvt.u32.u64 %0, t; }" : "=r"(a) : "l"(p));
    return a;
}
__device__ __forceinline__ void cp16(uint32_t saddr, const void* g) {
    asm volatile("cp.async.cg.shared.global [%0], [%1], 16;" :: "r"(saddr), "l"(g));
}
#define CP_COMMIT() asm volatile("cp.async.commit_group;" ::: "memory")
#define CP_WAIT0()  asm volatile("cp.async.wait_group 0;" ::: "memory")
#define CP_WAIT1()  asm volatile("cp.async.wait_group 1;" ::: "memory")

__device__ __forceinline__ void ldsm_x4(uint32_t* r, uint32_t a) {
    asm volatile("ldmatrix.sync.aligned.m8n8.x4.shared.b16 {%0,%1,%2,%3}, [%4];"
        : "=r"(r[0]), "=r"(r[1]), "=r"(r[2]), "=r"(r[3]) : "r"(a));
}
__device__ __forceinline__ void ldsm_x4t(uint32_t* r, uint32_t a) {
    asm volatile("ldmatrix.sync.aligned.m8n8.x4.trans.shared.b16 {%0,%1,%2,%3}, [%4];"
        : "=r"(r[0]), "=r"(r[1]), "=r"(r[2]), "=r"(r[3]) : "r"(a));
}
__device__ __forceinline__ void ldsm_x2(uint32_t* r, uint32_t a) {
    asm volatile("ldmatrix.sync.aligned.m8n8.x2.shared.b16 {%0,%1}, [%2];"
        : "=r"(r[0]), "=r"(r[1]) : "r"(a));
}
__device__ __forceinline__ void ldsm_x2t(uint32_t* r, uint32_t a) {
    asm volatile("ldmatrix.sync.aligned.m8n8.x2.trans.shared.b16 {%0,%1}, [%2];"
        : "=r"(r[0]), "=r"(r[1]) : "r"(a));
}
__device__ __forceinline__ void mma_bf16(float* d, const uint32_t* a, const uint32_t* b) {
    asm volatile("mma.sync.aligned.m16n8k16.row.col.f32.bf16.bf16.f32 "
        "{%0,%1,%2,%3}, {%4,%5,%6,%7}, {%8,%9}, {%0,%1,%2,%3};"
        : "+f"(d[0]), "+f"(d[1]), "+f"(d[2]), "+f"(d[3])
        : "r"(a[0]), "r"(a[1]), "r"(a[2]), "r"(a[3]), "r"(b[0]), "r"(b[1]));
}

__device__ __forceinline__ float gelu_exact(float v) {
    return 0.5f * v * (1.0f + erff(v * 0.7071067811865476f));
}
__device__ __forceinline__ uint32_t pack_bf2(float a, float b) {
    __nv_bfloat162 t = __floats2bfloat162_rn(a, b);
    return *(uint32_t*)&t;
}
__device__ __forceinline__ float blockMax256(float v, float* sh) {
    #pragma unroll
    for (int o = 16; o > 0; o >>= 1) v = fmaxf(v, __shfl_xor_sync(0xffffffffu, v, o));
    if ((threadIdx.x & 31) == 0) sh[threadIdx.x >> 5] = v;
    __syncthreads();
    if (threadIdx.x == 0) {
        float m = sh[0];
        #pragma unroll
        for (int i = 1; i < 8; i++) m = fmaxf(m, sh[i]);
        sh[0] = m;
    }
    __syncthreads();
    float r = sh[0];
    __syncthreads();
    return r;
}
__device__ __forceinline__ float blockSum256(float v, float* sh) {
    #pragma unroll
    for (int o = 16; o > 0; o >>= 1) v += __shfl_xor_sync(0xffffffffu, v, o);
    if ((threadIdx.x & 31) == 0) sh[threadIdx.x >> 5] = v;
    __syncthreads();
    if (threadIdx.x == 0) {
        float s = sh[0];
        #pragma unroll
        for (int i = 1; i < 8; i++) s += sh[i];
        sh[0] = s;
    }
    __syncthreads();
    float r = sh[0];
    __syncthreads();
    return r;
}

// ---------------- conversion kernels ----------------
__global__ void __launch_bounds__(256) split_kernel(const float* __restrict__ in,
                                                    __nv_bfloat16* __restrict__ hi,
                                                    __nv_bfloat16* __restrict__ lo)
{
    size_t i = (size_t)blockIdx.x * 1024 + threadIdx.x * 4;
    float4 v = *(const float4*)(in + i);
    __nv_bfloat16 h0 = __float2bfloat16(v.x), h1 = __float2bfloat16(v.y);
    __nv_bfloat16 h2 = __float2bfloat16(v.z), h3 = __float2bfloat16(v.w);
    __nv_bfloat16 l0 = __float2bfloat16(v.x - __bfloat162float(h0));
    __nv_bfloat16 l1 = __float2bfloat16(v.y - __bfloat162float(h1));
    __nv_bfloat16 l2 = __float2bfloat16(v.z - __bfloat162float(h2));
    __nv_bfloat16 l3 = __float2bfloat16(v.w - __bfloat162float(h3));
    ((__nv_bfloat162*)(hi + i))[0] = __halves2bfloat162(h0, h1);
    ((__nv_bfloat162*)(hi + i))[1] = __halves2bfloat162(h2, h3);
    ((__nv_bfloat162*)(lo + i))[0] = __halves2bfloat162(l0, l1);
    ((__nv_bfloat162*)(lo + i))[1] = __halves2bfloat162(l2, l3);
}

// W[K,N] fp32 -> Th/Tl[N,K] bf16
__global__ void __launch_bounds__(256) transpose_split(const float* __restrict__ W,
                                                       __nv_bfloat16* __restrict__ Th,
                                                       __nv_bfloat16* __restrict__ Tl,
                                                       int K, int N)
{
    __shared__ float sm[32][33];
    const int n0 = blockIdx.x * 32, k0 = blockIdx.y * 32;
    const int tx = threadIdx.x & 31, ty = threadIdx.x >> 5;
    #pragma unroll
    for (int i = 0; i < 4; i++)
        sm[ty + i * 8][tx] = W[(size_t)(k0 + ty + i * 8) * N + n0 + tx];
    __syncthreads();
    #pragma unroll
    for (int i = 0; i < 4; i++) {
        float v = sm[tx][ty + i * 8];
        __nv_bfloat16 h = __float2bfloat16(v);
        __nv_bfloat16 l = __float2bfloat16(v - __bfloat162float(h));
        size_t o = (size_t)(n0 + ty + i * 8) * K + k0 + tx;
        Th[o] = h;
        Tl[o] = l;
    }
}

// ---------------- mma.sync split-bf16 GEMM ----------------
// C[m,n] = scale * sum_k A[m,k]*B[n,k] (+bias[n]) (opt gelu / split-bf16 out)
// blocktile 128x128, 8 warps of 64x32, K chunks of 64, swizzled smem, cp.async 2-stage.
#define G_STAGE 65536   /* Ah 16K | Al 16K | Bh 16K | Bl 16K */
#define G_SMEM  (2*G_STAGE + 1024)

template<bool GELU, bool HAS_BIAS, bool PER_HEAD, bool SPLIT_OUT>
__global__ void __launch_bounds__(256) gemm_mma(
    const __nv_bfloat16* __restrict__ Ahi, const __nv_bfloat16* __restrict__ Alo,
    const __nv_bfloat16* __restrict__ Bhi, const __nv_bfloat16* __restrict__ Blo,
    const float* __restrict__ bias, float* __restrict__ C,
    __nv_bfloat16* __restrict__ Chi, __nv_bfloat16* __restrict__ Clo,
    int lda, int ldb, int ldc, int K, float scale)
{
    extern __shared__ char smraw[];
    uint32_t smb = smem_u32(smraw);
    smb = (smb + 1023u) & ~1023u;

    const int tid = threadIdx.x, lane = tid & 31, warp = tid >> 5;
    const int wm = warp & 1, wn = warp >> 1;

    size_t aOff = 0, bOff = 0, cOff = 0;
    if (PER_HEAD) {
        const int bh = blockIdx.z, b = bh >> 4, h = bh & 15;
        aOff = (size_t)b * L_ * E_ + h * DH_;
        bOff = aOff;
        cOff = (size_t)bh * L_ * L_;
    }
    const int m0g = blockIdx.y * 128, n0g = blockIdx.x * 128;

    const char* gA[2] = { (const char*)(Ahi + aOff + (size_t)m0g * lda),
                          (const char*)(Alo + aOff + (size_t)m0g * lda) };
    const char* gB[2] = { (const char*)(Bhi + bOff + (size_t)n0g * ldb),
                          (const char*)(Blo + bOff + (size_t)n0g * ldb) };

    const int nCh = K >> 6;
    float acc[4][4][4] = {};

    // ---- stage load: 4 arrays of 128 rows x 128B, swizzled ----
    auto loadStage = [&](int st, int k0) {
        #pragma unroll
        for (int arr = 0; arr < 4; arr++) {
            const char* base = (arr < 2) ? gA[arr] : gB[arr - 2];
            const int ld2 = ((arr < 2) ? lda : ldb) * 2;
            const uint32_t sb = smb + st * G_STAGE + arr * 16384;
            #pragma unroll
            for (int q = 0; q < 4; q++) {
                int id = tid + q * 256;
                int row = id >> 3, c16 = (id & 7) << 4;
                uint32_t sa = sb + row * 128 + (c16 ^ ((row & 7) << 4));
                cp16(sa, base + (size_t)row * ld2 + k0 * 2 + c16);
            }
        }
    };

    loadStage(0, 0);
    CP_COMMIT();

    for (int c = 0; c < nCh; c++) {
        const int st = c & 1;
        if (c + 1 < nCh) { loadStage(st ^ 1, (c + 1) << 6); CP_COMMIT(); CP_WAIT1(); }
        else             { CP_WAIT0(); }
        __syncthreads();

        const uint32_t sA = smb + st * G_STAGE;
        const uint32_t sB = sA + 32768;
        #pragma unroll
        for (int s = 0; s < 4; s++) {
            const int kb = s * 32;
            uint32_t aH[4][4], aL[4][4], bH[4][2], bL[4][2];
            const int lr = lane & 15, lc = lane >> 4;
            #pragma unroll
            for (int mt = 0; mt < 4; mt++) {
                int r = wm * 64 + mt * 16 + lr;
                int cb = kb + lc * 16;
                uint32_t ad = sA + r * 128 + (cb ^ ((r & 7) << 4));
                ldsm_x4(aH[mt], ad);
                ldsm_x4(aL[mt], ad + 16384);
            }
            const int br = lane & 7, bc = (lane >> 3) & 1;
            #pragma unroll
            for (int nt = 0; nt < 4; nt++) {
                int r = wn * 32 + nt * 8 + br;
                int cb = kb + bc * 16;
                uint32_t bd = sB + r * 128 + (cb ^ ((r & 7) << 4));
                ldsm_x2(bH[nt], bd);
                ldsm_x2(bL[nt], bd + 16384);
            }
            #pragma unroll
            for (int mt = 0; mt < 4; mt++)
                #pragma unroll
                for (int nt = 0; nt < 4; nt++) {
                    mma_bf16(acc[mt][nt], aH[mt], bH[nt]);
                    mma_bf16(acc[mt][nt], aH[mt], bL[nt]);
                    mma_bf16(acc[mt][nt], aL[mt], bH[nt]);
                }
        }
        __syncthreads();
    }

    // ---- epilogue ----
    #pragma unroll
    for (int mt = 0; mt < 4; mt++) {
        #pragma unroll
        for (int nt = 0; nt < 4; nt++) {
            const int row = m0g + wm * 64 + mt * 16 + (lane >> 2);
            const int col = n0g + wn * 32 + nt * 8 + 2 * (lane & 3);
            float v0 = acc[mt][nt][0] * scale, v1 = acc[mt][nt][1] * scale;
            float v2 = acc[mt][nt][2] * scale, v3 = acc[mt][nt][3] * scale;
            if (HAS_BIAS) {
                float b0 = __ldg(bias + col), b1 = __ldg(bias + col + 1);
                v0 += b0; v1 += b1; v2 += b0; v3 += b1;
            }
            if (GELU) {
                v0 = gelu_exact(v0); v1 = gelu_exact(v1);
                v2 = gelu_exact(v2); v3 = gelu_exact(v3);
            }
            if (SPLIT_OUT) {
                __nv_bfloat16 h0 = __float2bfloat16(v0), h1 = __float2bfloat16(v1);
                __nv_bfloat16 h2 = __float2bfloat16(v2), h3 = __float2bfloat16(v3);
                __nv_bfloat162 hh0 = __halves2bfloat162(h0, h1);
                __nv_bfloat162 hh1 = __halves2bfloat162(h2, h3);
                __nv_bfloat162 ll0 = __halves2bfloat162(
                    __float2bfloat16(v0 - __bfloat162float(h0)),
                    __float2bfloat16(v1 - __bfloat162float(h1)));
                __nv_bfloat162 ll1 = __halves2bfloat162(
                    __float2bfloat16(v2 - __bfloat162float(h2)),
                    __float2bfloat16(v3 - __bfloat162float(h3)));
                *(__nv_bfloat162*)(Chi + (size_t)row * ldc + col)       = hh0;
                *(__nv_bfloat162*)(Chi + (size_t)(row + 8) * ldc + col) = hh1;
                *(__nv_bfloat162*)(Clo + (size_t)row * ldc + col)       = ll0;
                *(__nv_bfloat162*)(Clo + (size_t)(row + 8) * ldc + col) = ll1;
            } else {
                *(float2*)(C + cOff + (size_t)row * ldc + col)       = make_float2(v0, v1);
                *(float2*)(C + cOff + (size_t)(row + 8) * ldc + col) = make_float2(v2, v3);
            }
        }
    }
}

// ---------------- per-column stats: m_j, denom_j; U = x_j*V/denom (bf16 hi/lo) ----------------
__global__ void __launch_bounds__(256) stats_kernel(const float* __restrict__ x)
{
    __shared__ float red[8];
    const int row = blockIdx.x;          // bh*L + j
    const int bh = row >> 11;
    const int j  = row & (L_ - 1);
    const int b = bh >> 4, h = bh & 15;
    const float* S  = g_ST + (size_t)row * L_;
    const float* xb = x + b * L_;
    const int tid = threadIdx.x;

    float v[8];
    float4 a0 = *(const float4*)(S + tid * 8);
    float4 a1 = *(const float4*)(S + tid * 8 + 4);
    v[0] = a0.x; v[1] = a0.y; v[2] = a0.z; v[3] = a0.w;
    v[4] = a1.x; v[5] = a1.y; v[6] = a1.z; v[7] = a1.w;

    float mx = v[0];
    #pragma unroll
    for (int q = 1; q < 8; q++) mx = fmaxf(mx, v[q]);
    const float m = blockMax256(mx, red);

    float s = 0.0f;
    #pragma unroll
    for (int q = 0; q < 8; q++) s += xb[tid * 8 + q] * __expf(v[q] - m);
    const float denom = blockSum256(s, red);

    if (tid == 0) g_m[row] = m;
    if (tid < DH_) {
        float vv = g_V[((size_t)b * L_ + j) * E_ + h * DH_ + tid];
        float u = xb[j] * vv / denom;
        __nv_bfloat16 uh = __float2bfloat16(u);
        g_Uh[(size_t)row * DH_ + tid] = uh;
        g_Ul[(size_t)row * DH_ + tid] = __float2bfloat16(u - __bfloat162float(uh));
    }
}

// ---------------- attention output: O[i,d] = x_i * sum_j exp(ST[j,i]-m_j)*U[j,d] ----------------
// tensorized: E split bf16 hi/lo (ldmatrix.trans), U split bf16 (ldmatrix.trans)
#define A_SS(st)  ((st) * 32768)              /* raw S fp32: 64 x 128 x 4B */
#define A_EH      65536                       /* E hi: 64 x 128 bf16, 256B rows */
#define A_EL      81920
#define A_SU(st)  (98304 + (st) * 16384)      /* Uh 8K + Ul 8K */
#define A_SM(st)  (131072 + (st) * 256)
#define A_SMEM    (131584 + 1024)

__global__ void __launch_bounds__(256) attn_mma(const float* __restrict__ x)
{
    extern __shared__ char smraw[];
    uint32_t smb = smem_u32(smraw);
    uint32_t pad = (1024u - (smb & 1023u)) & 1023u;
    char* smp = smraw + pad;
    smb += pad;

    const int tid = threadIdx.x, lane = tid & 31, warp = tid >> 5;
    const int wi = warp & 3, wd = warp >> 2;     // warp tile: 32 i x 32 d
    const int bh = blockIdx.y, b = bh >> 4, h = bh & 15;
    const int i0 = blockIdx.x * 128;

    const char* Sb = (const char*)(g_ST + (size_t)bh * L_ * L_ + i0);
    const char* Uhb = (const char*)(g_Uh + (size_t)bh * L_ * DH_);
    const char* Ulb = (const char*)(g_Ul + (size_t)bh * L_ * DH_);
    const char* mb  = (const char*)(g_m + (size_t)bh * L_);

    float acc[2][4][4] = {};

    auto loadStage = [&](int st, int j0) {
        // S tile: 64 rows x 512 bytes = 2048 cp16 (32 chunks per row)
        #pragma unroll
        for (int q = 0; q < 8; q++) {
            int id = tid + q * 256;
            int row = id >> 5, c16 = (id & 31) << 4;
            cp16(smb + A_SS(st) + row * 512 + c16,
                 Sb + (size_t)(j0 + row) * (L_ * 4) + c16);
        }
        // U tiles: 64 rows x 128 bytes (hi + lo), swizzled
        #pragma unroll
        for (int q = 0; q < 2; q++) {
            int id = tid + q * 256;
            int row = id >> 3, c16 = (id & 7) << 4;
            uint32_t off = row * 128 + (c16 ^ ((row & 7) << 4));
            cp16(smb + A_SU(st) + off,        Uhb + (size_t)(j0 + row) * 128 + c16);
            cp16(smb + A_SU(st) + 8192 + off, Ulb + (size_t)(j0 + row) * 128 + c16);
        }
        if (tid < 16) cp16(smb + A_SM(st) + tid * 16, mb + (size_t)j0 * 4 + tid * 16);
    };

    loadStage(0, 0);
    CP_COMMIT();

    for (int c = 0; c < L_ / 64; c++) {
        const int st = c & 1;
        if (c + 1 < L_ / 64) { loadStage(st ^ 1, (c + 1) * 64); CP_COMMIT(); CP_WAIT1(); }
        else                 { CP_WAIT0(); }
        __syncthreads();

        // convert: e = exp(s - m_j), split to bf16 hi/lo, store [j][i]
        {
            const float* ssrc = (const float*)(smp + A_SS(st));
            const float* msrc = (const float*)(smp + A_SM(st));
            #pragma unroll
            for (int q = 0; q < 8; q++) {
                int id = tid + q * 256;
                int j = id >> 5, i4 = (id & 31) << 2;
                float4 s4 = *(const float4*)(ssrc + (j << 7) + i4);
                float mj = msrc[j];
                float e0 = __expf(s4.x - mj), e1 = __expf(s4.y - mj);
                float e2 = __expf(s4.z - mj), e3 = __expf(s4.w - mj);
                __nv_bfloat16 h0 = __float2bfloat16(e0), h1 = __float2bfloat16(e1);
                __nv_bfloat16 h2 = __float2bfloat16(e2), h3 = __float2bfloat16(e3);
                uint32_t hi01 = pack_bf2(__bfloat162float(h0), __bfloat162float(h1));
                uint32_t hi23 = pack_bf2(__bfloat162float(h2), __bfloat162float(h3));
                uint32_t lo01 = pack_bf2(e0 - __bfloat162float(h0), e1 - __bfloat162float(h1));
                uint32_t lo23 = pack_bf2(e2 - __bfloat162float(h2), e3 - __bfloat162float(h3));
                uint32_t off = j * 256 + ((i4 * 2) ^ ((j & 7) << 4));
                *(uint2*)(smp + A_EH + off) = make_uint2(hi01, hi23);
                *(uint2*)(smp + A_EL + off) = make_uint2(lo01, lo23);
            }
        }
        __syncthreads();

        // mma over 4 k16 steps
        #pragma unroll
        for (int s = 0; s < 4; s++) {
            const int k0 = s * 16;
            uint32_t eH[2][4], eL[2][4], uH[4][2], uL[4][2];
            {
                const int r = k0 + (lane & 7) + ((lane >> 4) << 3);
                const int cbl = (((lane >> 3) & 1) << 4);
                #pragma unroll
                for (int mt = 0; mt < 2; mt++) {
                    int m0t = wi * 32 + mt * 16;
                    int cb = m0t * 2 + cbl;
                    uint32_t ad = smb + A_EH + r * 256 + (cb ^ ((r & 7) << 4));
                    ldsm_x4t(eH[mt], ad);
                    ldsm_x4t(eL[mt], ad + (A_EL - A_EH));
                }
            }
            {
                const int r = k0 + (lane & 7) + (((lane >> 3) & 1) << 3);
                #pragma unroll
                for (int nt = 0; nt < 4; nt++) {
                    int cb = (wd * 32 + nt * 8) * 2;
                    uint32_t ud = smb + A_SU(st) + r * 128 + (cb ^ ((r & 7) << 4));
                    ldsm_x2t(uH[nt], ud);
                    ldsm_x2t(uL[nt], ud + 8192);
                }
            }
            #pragma unroll
            for (int mt = 0; mt < 2; mt++)
                #pragma unroll
                for (int nt = 0; nt < 4; nt++) {
                    mma_bf16(acc[mt][nt], eH[mt], uH[nt]);
                    mma_bf16(acc[mt][nt], eH[mt], uL[nt]);
                    mma_bf16(acc[mt][nt], eL[mt], uH[nt]);
                }
        }
        __syncthreads();
    }

    // epilogue: O[b*L+i][h*64+d] = x_i * acc
    #pragma unroll
    for (int mt = 0; mt < 2; mt++) {
        #pragma unroll
        for (int nt = 0; nt < 4; nt++) {
            const int row = i0 + wi * 32 + mt * 16 + (lane >> 2);
            const int col = h * DH_ + wd * 32 + nt * 8 + 2 * (lane & 3);
            float x0 = __ldg(x + b * L_ + row);
            float x1 = __ldg(x + b * L_ + row + 8);
            *(float2*)(g_O + ((size_t)b * L_ + row) * E_ + col) =
                make_float2(acc[mt][nt][0] * x0, acc[mt][nt][1] * x0);
            *(float2*)(g_O + ((size_t)b * L_ + row + 8) * E_ + col) =
                make_float2(acc[mt][nt][2] * x1, acc[mt][nt][3] * x1);
        }
    }
}

// ---------------- final projection ----------------
__global__ void __launch_bounds__(256) final_kernel(const float* __restrict__ W2,
                                                    const float* __restrict__ b2,
                                                    float* __restrict__ out)
{
    __shared__ float red[8];
    const int r = blockIdx.x;
    const float* Y = g_Y1 + (size_t)r * HID_;
    float s = 0.0f;
    for (int c = threadIdx.x * 4; c < HID_; c += 256 * 4) {
        float4 y4 = *(const float4*)(Y + c);
        float4 w4 = *(const float4*)(W2 + c);
        s += y4.x * w4.x + y4.y * w4.y + y4.z * w4.z + y4.w * w4.w;
    }
    s = blockSum256(s, red);
    if (threadIdx.x == 0) out[r] = s + b2[0];
}

// ---------------- launch ----------------
extern "C" void kernel_launch(void* const* d_in, const int* in_sizes, int n_in,
                              void* d_out, int out_size)
{
    (void)in_sizes; (void)n_in; (void)out_size;
    const float* x  = (const float*)d_in[0];
    const float* z  = (const float*)d_in[1];
    const float* Wq = (const float*)d_in[2];
    const float* bq = (const float*)d_in[3];
    const float* Wk = (const float*)d_in[4];
    const float* bk = (const float*)d_in[5];
    const float* Wv = (const float*)d_in[6];
    const float* bv = (const float*)d_in[7];
    const float* W1 = (const float*)d_in[8];
    const float* b1 = (const float*)d_in[9];
    const float* W2 = (const float*)d_in[10];
    const float* b2 = (const float*)d_in[11];

    float *pV, *pO, *pY1, *pST;
    __nv_bfloat16 *pAhi, *pAlo, *pBhi, *pBlo, *pQhi, *pQlo, *pKhi, *pKlo;
    cudaGetSymbolAddress((void**)&pV,  g_V);
    cudaGetSymbolAddress((void**)&pO,  g_O);
    cudaGetSymbolAddress((void**)&pY1, g_Y1);
    cudaGetSymbolAddress((void**)&pST, g_ST);
    cudaGetSymbolAddress((void**)&pAhi, g_Ahi);
    cudaGetSymbolAddress((void**)&pAlo, g_Alo);
    cudaGetSymbolAddress((void**)&pBhi, g_Bthi);
    cudaGetSymbolAddress((void**)&pBlo, g_Btlo);
    cudaGetSymbolAddress((void**)&pQhi, g_Qhi);
    cudaGetSymbolAddress((void**)&pQlo, g_Qlo);
    cudaGetSymbolAddress((void**)&pKhi, g_Khi);
    cudaGetSymbolAddress((void**)&pKlo, g_Klo);

    cudaFuncSetAttribute(gemm_mma<false, true,  false, true >, cudaFuncAttributeMaxDynamicSharedMemorySize, G_SMEM);
    cudaFuncSetAttribute(gemm_mma<false, true,  false, false>, cudaFuncAttributeMaxDynamicSharedMemorySize, G_SMEM);
    cudaFuncSetAttribute(gemm_mma<false, false, true,  false>, cudaFuncAttributeMaxDynamicSharedMemorySize, G_SMEM);
    cudaFuncSetAttribute(gemm_mma<true,  true,  false, false>, cudaFuncAttributeMaxDynamicSharedMemorySize, G_SMEM);
    cudaFuncSetAttribute(attn_mma, cudaFuncAttributeMaxDynamicSharedMemorySize, A_SMEM);

    const size_t nZ = (size_t)ML_ * E_;
    dim3 gT(E_ / 32, E_ / 32);
    dim3 gProj(E_ / 128, ML_ / 128);

    // split z (A operand for QKV projections)
    split_kernel<<<nZ / 1024, 256>>>(z, pAhi, pAlo);

    // Q projection -> split bf16 output directly
    transpose_split<<<gT, 256>>>(Wq, pBhi, pBlo, E_, E_);
    gemm_mma<false, true, false, true><<<gProj, 256, G_SMEM>>>(
        pAhi, pAlo, pBhi, pBlo, bq, nullptr, pQhi, pQlo, E_, E_, E_, E_, 1.0f);
    // K projection -> split bf16
    transpose_split<<<gT, 256>>>(Wk, pBhi, pBlo, E_, E_);
    gemm_mma<false, true, false, true><<<gProj, 256, G_SMEM>>>(
        pAhi, pAlo, pBhi, pBlo, bk, nullptr, pKhi, pKlo, E_, E_, E_, E_, 1.0f);
    // V projection -> fp32 (needed by stats)
    transpose_split<<<gT, 256>>>(Wv, pBhi, pBlo, E_, E_);
    gemm_mma<false, true, false, false><<<gProj, 256, G_SMEM>>>(
        pAhi, pAlo, pBhi, pBlo, bv, pV, nullptr, nullptr, E_, E_, E_, E_, 1.0f);

    // S^T[bh][j][i] = K_j . Q_i / 8  (per-head, K=64)
    gemm_mma<false, false, true, false><<<dim3(L_ / 128, L_ / 128, BH_), 256, G_SMEM>>>(
        pKhi, pKlo, pQhi, pQlo, nullptr, pST, nullptr, nullptr, E_, E_, L_, DH_, 0.125f);

    // column softmax stats + split U
    stats_kernel<<<BH_ * L_, 256>>>(x);

    // tensorized attention output
    attn_mma<<<dim3(L_ / 128, BH_), 256, A_SMEM>>>(x);

    // MLP layer 1 (split-bf16 mma) with bias + exact GELU
    split_kernel<<<nZ / 1024, 256>>>(pO, pAhi, pAlo);
    transpose_split<<<dim3(HID_ / 32, E_ / 32), 256>>>(W1, pBhi, pBlo, E_, HID_);
    gemm_mma<true, true, false, false><<<dim3(HID_ / 128, ML_ / 128), 256, G_SMEM>>>(
        pAhi, pAlo, pBhi, pBlo, b1, pY1, nullptr, nullptr, E_, E_, HID_, E_, 1.0f);

    // final projection
    final_kernel<<<ML_, 256>>>(W2, b2, (float*)d_out);
}

// round 6
// speedup vs baseline: 2.6095x; 1.1985x over previous
#include <cuda_runtime.h>
#include <cuda_bf16.h>
#include <math.h>
#include <stdint.h>

#define B_   2
#define L_   2048
#define E_   1024
#define H_   16
#define DH_  64
#define HID_ 4096
#define BH_  (B_*H_)    /* 32   */
#define ML_  (B_*L_)    /* 4096 */
#define QKV_LD 3072

// ---------------- scratch (device globals; no allocation allowed) ----------------
__device__ __align__(128) __nv_bfloat16 g_Ehi[(size_t)BH_ * L_ * L_];   // 268 MB, [bh][j][i] = exp(S^T)
__device__ __align__(128) __nv_bfloat16 g_Elo[(size_t)BH_ * L_ * L_];
__device__ __align__(128) float g_den[(size_t)BH_ * L_];

__device__ __align__(128) __nv_bfloat16 g_Ahi [(size_t)ML_ * E_];       // z-split, later O-split
__device__ __align__(128) __nv_bfloat16 g_Alo [(size_t)ML_ * E_];
__device__ __align__(128) __nv_bfloat16 g_Bthi[(size_t)HID_ * E_];      // transposed weights [N,K]
__device__ __align__(128) __nv_bfloat16 g_Btlo[(size_t)HID_ * E_];
__device__ __align__(128) __nv_bfloat16 g_QKVhi[(size_t)ML_ * QKV_LD]; // [ML][Q|K|V]
__device__ __align__(128) __nv_bfloat16 g_QKVlo[(size_t)ML_ * QKV_LD];
__device__ __align__(128) __nv_bfloat16 g_Uh  [(size_t)BH_ * L_ * DH_];
__device__ __align__(128) __nv_bfloat16 g_Ul  [(size_t)BH_ * L_ * DH_];
__device__ __align__(128) float g_biasP[QKV_LD];

// ---------------- ptx helpers (sm_80-compatible PTX only) ----------------
__device__ __forceinline__ uint32_t smem_u32(const void* p) {
    uint32_t a;
    asm("{ .reg .u64 t; cvta.to.shared.u64 t, %1; cvt.u32.u64 %0, t; }" : "=r"(a) : "l"(p));
    return a;
}
__device__ __forceinline__ void cp16(uint32_t saddr, const void* g) {
    asm volatile("cp.async.cg.shared.global [%0], [%1], 16;" :: "r"(saddr), "l"(g));
}
#define CP_COMMIT() asm volatile("cp.async.commit_group;" ::: "memory")
#define CP_WAIT0()  asm volatile("cp.async.wait_group 0;" ::: "memory")
#define CP_WAIT1()  asm volatile("cp.async.wait_group 1;" ::: "memory")

__device__ __forceinline__ void ldsm_x4(uint32_t* r, uint32_t a) {
    asm volatile("ldmatrix.sync.aligned.m8n8.x4.shared.b16 {%0,%1,%2,%3}, [%4];"
        : "=r"(r[0]), "=r"(r[1]), "=r"(r[2]), "=r"(r[3]) : "r"(a));
}
__device__ __forceinline__ void ldsm_x4t(uint32_t* r, uint32_t a) {
    asm volatile("ldmatrix.sync.aligned.m8n8.x4.trans.shared.b16 {%0,%1,%2,%3}, [%4];"
        : "=r"(r[0]), "=r"(r[1]), "=r"(r[2]), "=r"(r[3]) : "r"(a));
}
__device__ __forceinline__ void ldsm_x2(uint32_t* r, uint32_t a) {
    asm volatile("ldmatrix.sync.aligned.m8n8.x2.shared.b16 {%0,%1}, [%2];"
        : "=r"(r[0]), "=r"(r[1]) : "r"(a));
}
__device__ __forceinline__ void ldsm_x2t(uint32_t* r, uint32_t a) {
    asm volatile("ldmatrix.sync.aligned.m8n8.x2.trans.shared.b16 {%0,%1}, [%2];"
        : "=r"(r[0]), "=r"(r[1]) : "r"(a));
}
__device__ __forceinline__ void mma_bf16(float* d, const uint32_t* a, const uint32_t* b) {
    asm volatile("mma.sync.aligned.m16n8k16.row.col.f32.bf16.bf16.f32 "
        "{%0,%1,%2,%3}, {%4,%5,%6,%7}, {%8,%9}, {%0,%1,%2,%3};"
        : "+f"(d[0]), "+f"(d[1]), "+f"(d[2]), "+f"(d[3])
        : "r"(a[0]), "r"(a[1]), "r"(a[2]), "r"(a[3]), "r"(b[0]), "r"(b[1]));
}

__device__ __forceinline__ float gelu_exact(float v) {
    return 0.5f * v * (1.0f + erff(v * 0.7071067811865476f));
}

// ---------------- init: pack bias, init out=b2, zero den ----------------
__global__ void __launch_bounds__(256) init_kernel(const float* __restrict__ bq,
                                                   const float* __restrict__ bk,
                                                   const float* __restrict__ bv,
                                                   const float* __restrict__ b2,
                                                   float* __restrict__ out)
{
    int i = blockIdx.x * 256 + threadIdx.x;    // grid covers 0..65535
    if (i < 1024)      g_biasP[i] = bq[i];
    else if (i < 2048) g_biasP[i] = bk[i - 1024];
    else if (i < 3072) g_biasP[i] = bv[i - 2048];
    if (i < ML_) out[i] = b2[0];
    if (i < BH_ * L_) g_den[i] = 0.0f;
}

// ---------------- conversion kernels ----------------
__global__ void __launch_bounds__(256) split_kernel(const float* __restrict__ in,
                                                    __nv_bfloat16* __restrict__ hi,
                                                    __nv_bfloat16* __restrict__ lo)
{
    size_t i = (size_t)blockIdx.x * 1024 + threadIdx.x * 4;
    float4 v = *(const float4*)(in + i);
    __nv_bfloat16 h0 = __float2bfloat16(v.x), h1 = __float2bfloat16(v.y);
    __nv_bfloat16 h2 = __float2bfloat16(v.z), h3 = __float2bfloat16(v.w);
    __nv_bfloat16 l0 = __float2bfloat16(v.x - __bfloat162float(h0));
    __nv_bfloat16 l1 = __float2bfloat16(v.y - __bfloat162float(h1));
    __nv_bfloat16 l2 = __float2bfloat16(v.z - __bfloat162float(h2));
    __nv_bfloat16 l3 = __float2bfloat16(v.w - __bfloat162float(h3));
    ((__nv_bfloat162*)(hi + i))[0] = __halves2bfloat162(h0, h1);
    ((__nv_bfloat162*)(hi + i))[1] = __halves2bfloat162(h2, h3);
    ((__nv_bfloat162*)(lo + i))[0] = __halves2bfloat162(l0, l1);
    ((__nv_bfloat162*)(lo + i))[1] = __halves2bfloat162(l2, l3);
}

// W[K,N] fp32 -> Th/Tl[N,K] bf16 (with N-offset for packing)
__global__ void __launch_bounds__(256) transpose_split(const float* __restrict__ W,
                                                       __nv_bfloat16* __restrict__ Th,
                                                       __nv_bfloat16* __restrict__ Tl,
                                                       int K, int N)
{
    __shared__ float sm[32][33];
    const int n0 = blockIdx.x * 32, k0 = blockIdx.y * 32;
    const int tx = threadIdx.x & 31, ty = threadIdx.x >> 5;
    #pragma unroll
    for (int i = 0; i < 4; i++)
        sm[ty + i * 8][tx] = W[(size_t)(k0 + ty + i * 8) * N + n0 + tx];
    __syncthreads();
    #pragma unroll
    for (int i = 0; i < 4; i++) {
        float v = sm[tx][ty + i * 8];
        __nv_bfloat16 h = __float2bfloat16(v);
        __nv_bfloat16 l = __float2bfloat16(v - __bfloat162float(h));
        size_t o = (size_t)(n0 + ty + i * 8) * K + k0 + tx;
        Th[o] = h;
        Tl[o] = l;
    }
}

// ---------------- mma.sync split-bf16 GEMM, 3 epilogue modes ----------------
// MODE 0: C = A@B^T + bias -> split bf16 out (QKV projection)
// MODE 1: per-head E = exp(A@B^T / 8) -> split bf16 out + atomic denom (QK)
// MODE 2: y = gelu(A@B^T + bias); atomicAdd(out[row], y . W2)  (MLP + final)
#define G_STAGE 65536   /* Ah 16K | Al 16K | Bh 16K | Bl 16K */
#define G_SMEM  (2*G_STAGE + 1024)

template<int MODE>
__global__ void __launch_bounds__(256) gemm_mma(
    const __nv_bfloat16* __restrict__ Ahi, const __nv_bfloat16* __restrict__ Alo,
    const __nv_bfloat16* __restrict__ Bhi, const __nv_bfloat16* __restrict__ Blo,
    const float* __restrict__ bias, const float* __restrict__ xw,
    __nv_bfloat16* __restrict__ Chi, __nv_bfloat16* __restrict__ Clo,
    float* __restrict__ aux,
    int lda, int ldb, int ldc, int K)
{
    extern __shared__ char smraw[];
    uint32_t smb = smem_u32(smraw);
    smb = (smb + 1023u) & ~1023u;

    const int tid = threadIdx.x, lane = tid & 31, warp = tid >> 5;
    const int wm = warp & 1, wn = warp >> 1;

    size_t aOff = 0, bOff = 0, eOff = 0;
    int bh = 0, bb = 0;
    if (MODE == 1) {
        bh = blockIdx.z; bb = bh >> 4;
        const int h = bh & 15;
        aOff = (size_t)bb * L_ * QKV_LD + 1024 + h * DH_;   // K vectors
        bOff = (size_t)bb * L_ * QKV_LD + h * DH_;          // Q vectors
        eOff = (size_t)bh * L_ * L_;
    }
    const int m0g = blockIdx.y * 128, n0g = blockIdx.x * 128;

    const char* gA[2] = { (const char*)(Ahi + aOff + (size_t)m0g * lda),
                          (const char*)(Alo + aOff + (size_t)m0g * lda) };
    const char* gB[2] = { (const char*)(Bhi + bOff + (size_t)n0g * ldb),
                          (const char*)(Blo + bOff + (size_t)n0g * ldb) };

    const int nCh = K >> 6;
    float acc[4][4][4] = {};

    auto loadStage = [&](int st, int k0) {
        #pragma unroll
        for (int arr = 0; arr < 4; arr++) {
            const char* base = (arr < 2) ? gA[arr] : gB[arr - 2];
            const int ld2 = ((arr < 2) ? lda : ldb) * 2;
            const uint32_t sb = smb + st * G_STAGE + arr * 16384;
            #pragma unroll
            for (int q = 0; q < 4; q++) {
                int id = tid + q * 256;
                int row = id >> 3, c16 = (id & 7) << 4;
                uint32_t sa = sb + row * 128 + (c16 ^ ((row & 7) << 4));
                cp16(sa, base + (size_t)row * ld2 + k0 * 2 + c16);
            }
        }
    };

    loadStage(0, 0);
    CP_COMMIT();

    for (int c = 0; c < nCh; c++) {
        const int st = c & 1;
        if (c + 1 < nCh) { loadStage(st ^ 1, (c + 1) << 6); CP_COMMIT(); CP_WAIT1(); }
        else             { CP_WAIT0(); }
        __syncthreads();

        const uint32_t sA = smb + st * G_STAGE;
        const uint32_t sB = sA + 32768;
        #pragma unroll
        for (int s = 0; s < 4; s++) {
            const int kb = s * 32;
            uint32_t aH[4][4], aL[4][4], bH[4][2], bL[4][2];
            const int lr = lane & 15, lc = lane >> 4;
            #pragma unroll
            for (int mt = 0; mt < 4; mt++) {
                int r = wm * 64 + mt * 16 + lr;
                int cb = kb + lc * 16;
                uint32_t ad = sA + r * 128 + (cb ^ ((r & 7) << 4));
                ldsm_x4(aH[mt], ad);
                ldsm_x4(aL[mt], ad + 16384);
            }
            const int br = lane & 7, bc = (lane >> 3) & 1;
            #pragma unroll
            for (int nt = 0; nt < 4; nt++) {
                int r = wn * 32 + nt * 8 + br;
                int cb = kb + bc * 16;
                uint32_t bd = sB + r * 128 + (cb ^ ((r & 7) << 4));
                ldsm_x2(bH[nt], bd);
                ldsm_x2(bL[nt], bd + 16384);
            }
            #pragma unroll
            for (int mt = 0; mt < 4; mt++)
                #pragma unroll
                for (int nt = 0; nt < 4; nt++) {
                    mma_bf16(acc[mt][nt], aH[mt], bH[nt]);
                    mma_bf16(acc[mt][nt], aH[mt], bL[nt]);
                    mma_bf16(acc[mt][nt], aL[mt], bH[nt]);
                }
        }
        __syncthreads();
    }

    // ---- epilogues ----
    if (MODE == 0) {
        #pragma unroll
        for (int mt = 0; mt < 4; mt++) {
            #pragma unroll
            for (int nt = 0; nt < 4; nt++) {
                const int row = m0g + wm * 64 + mt * 16 + (lane >> 2);
                const int col = n0g + wn * 32 + nt * 8 + 2 * (lane & 3);
                float b0 = __ldg(bias + col), b1 = __ldg(bias + col + 1);
                float v0 = acc[mt][nt][0] + b0, v1 = acc[mt][nt][1] + b1;
                float v2 = acc[mt][nt][2] + b0, v3 = acc[mt][nt][3] + b1;
                __nv_bfloat16 h0 = __float2bfloat16(v0), h1 = __float2bfloat16(v1);
                __nv_bfloat16 h2 = __float2bfloat16(v2), h3 = __float2bfloat16(v3);
                *(__nv_bfloat162*)(Chi + (size_t)row * ldc + col)       = __halves2bfloat162(h0, h1);
                *(__nv_bfloat162*)(Chi + (size_t)(row + 8) * ldc + col) = __halves2bfloat162(h2, h3);
                *(__nv_bfloat162*)(Clo + (size_t)row * ldc + col) = __halves2bfloat162(
                    __float2bfloat16(v0 - __bfloat162float(h0)),
                    __float2bfloat16(v1 - __bfloat162float(h1)));
                *(__nv_bfloat162*)(Clo + (size_t)(row + 8) * ldc + col) = __halves2bfloat162(
                    __float2bfloat16(v2 - __bfloat162float(h2)),
                    __float2bfloat16(v3 - __bfloat162float(h3)));
            }
        }
    } else if (MODE == 1) {
        const float* xb = xw + bb * L_;
        float xc[4][2];
        #pragma unroll
        for (int nt = 0; nt < 4; nt++) {
            int col = n0g + wn * 32 + nt * 8 + 2 * (lane & 3);
            xc[nt][0] = __ldg(xb + col);
            xc[nt][1] = __ldg(xb + col + 1);
        }
        #pragma unroll
        for (int mt = 0; mt < 4; mt++) {
            const int rg = m0g + wm * 64 + mt * 16 + (lane >> 2);
            float p0 = 0.0f, p8 = 0.0f;
            #pragma unroll
            for (int nt = 0; nt < 4; nt++) {
                const int col = n0g + wn * 32 + nt * 8 + 2 * (lane & 3);
                float e0 = __expf(acc[mt][nt][0] * 0.125f);
                float e1 = __expf(acc[mt][nt][1] * 0.125f);
                float e2 = __expf(acc[mt][nt][2] * 0.125f);
                float e3 = __expf(acc[mt][nt][3] * 0.125f);
                __nv_bfloat16 h0 = __float2bfloat16(e0), h1 = __float2bfloat16(e1);
                __nv_bfloat16 h2 = __float2bfloat16(e2), h3 = __float2bfloat16(e3);
                *(__nv_bfloat162*)(Chi + eOff + (size_t)rg * ldc + col)       = __halves2bfloat162(h0, h1);
                *(__nv_bfloat162*)(Chi + eOff + (size_t)(rg + 8) * ldc + col) = __halves2bfloat162(h2, h3);
                *(__nv_bfloat162*)(Clo + eOff + (size_t)rg * ldc + col) = __halves2bfloat162(
                    __float2bfloat16(e0 - __bfloat162float(h0)),
                    __float2bfloat16(e1 - __bfloat162float(h1)));
                *(__nv_bfloat162*)(Clo + eOff + (size_t)(rg + 8) * ldc + col) = __halves2bfloat162(
                    __float2bfloat16(e2 - __bfloat162float(h2)),
                    __float2bfloat16(e3 - __bfloat162float(h3)));
                p0 += xc[nt][0] * e0 + xc[nt][1] * e1;
                p8 += xc[nt][0] * e2 + xc[nt][1] * e3;
            }
            p0 += __shfl_xor_sync(0xffffffffu, p0, 1);
            p0 += __shfl_xor_sync(0xffffffffu, p0, 2);
            p8 += __shfl_xor_sync(0xffffffffu, p8, 1);
            p8 += __shfl_xor_sync(0xffffffffu, p8, 2);
            if ((lane & 3) == 0) {
                atomicAdd(aux + (size_t)bh * L_ + rg,     p0);
                atomicAdd(aux + (size_t)bh * L_ + rg + 8, p8);
            }
        }
    } else {  // MODE == 2
        #pragma unroll
        for (int mt = 0; mt < 4; mt++) {
            const int row = m0g + wm * 64 + mt * 16 + (lane >> 2);
            float p0 = 0.0f, p8 = 0.0f;
            #pragma unroll
            for (int nt = 0; nt < 4; nt++) {
                const int col = n0g + wn * 32 + nt * 8 + 2 * (lane & 3);
                float b0 = __ldg(bias + col), b1 = __ldg(bias + col + 1);
                float w0 = __ldg(xw + col),  w1 = __ldg(xw + col + 1);
                float v0 = gelu_exact(acc[mt][nt][0] + b0);
                float v1 = gelu_exact(acc[mt][nt][1] + b1);
                float v2 = gelu_exact(acc[mt][nt][2] + b0);
                float v3 = gelu_exact(acc[mt][nt][3] + b1);
                p0 += v0 * w0 + v1 * w1;
                p8 += v2 * w0 + v3 * w1;
            }
            p0 += __shfl_xor_sync(0xffffffffu, p0, 1);
            p0 += __shfl_xor_sync(0xffffffffu, p0, 2);
            p8 += __shfl_xor_sync(0xffffffffu, p8, 1);
            p8 += __shfl_xor_sync(0xffffffffu, p8, 2);
            if ((lane & 3) == 0) {
                atomicAdd(aux + row,     p0);
                atomicAdd(aux + row + 8, p8);
            }
        }
    }
}

// ---------------- U kernel: U[bh][j][d] = x_j * V[b,j,h,d] / den[bh][j] ----------------
__global__ void __launch_bounds__(256) u_kernel(const float* __restrict__ x)
{
    int gid = blockIdx.x * 256 + threadIdx.x;   // BH*L*64 total
    int d = gid & 63;
    int row = gid >> 6;                          // bh*L + j
    int bh = row >> 11, j = row & (L_ - 1);
    int b = bh >> 4, h = bh & 15;
    float den = g_den[row];
    size_t vo = ((size_t)b * L_ + j) * QKV_LD + 2048 + h * DH_ + d;
    float v = __bfloat162float(g_QKVhi[vo]) + __bfloat162float(g_QKVlo[vo]);
    float u = __ldg(x + b * L_ + j) * v / den;
    __nv_bfloat16 uh = __float2bfloat16(u);
    g_Uh[(size_t)row * DH_ + d] = uh;
    g_Ul[(size_t)row * DH_ + d] = __float2bfloat16(u - __bfloat162float(uh));
}

// ---------------- attention output: O[i,d] = x_i * sum_j E[j,i]*U[j,d] ----------------
#define AT_STAGE 49152  /* Eh 16K | El 16K | Uh 8K | Ul 8K */
#define AT_SMEM  (2*AT_STAGE + 1024)

__global__ void __launch_bounds__(256) attn_mma(const float* __restrict__ x)
{
    extern __shared__ char smraw[];
    uint32_t smb = smem_u32(smraw);
    smb = (smb + 1023u) & ~1023u;

    const int tid = threadIdx.x, lane = tid & 31, warp = tid >> 5;
    const int wi = warp & 3, wd = warp >> 2;     // warp tile: 32 i x 32 d
    const int bh = blockIdx.y, b = bh >> 4, h = bh & 15;
    const int i0 = blockIdx.x * 128;

    const char* Ehb = (const char*)(g_Ehi + (size_t)bh * L_ * L_);
    const char* Elb = (const char*)(g_Elo + (size_t)bh * L_ * L_);
    const char* Uhb = (const char*)(g_Uh + (size_t)bh * L_ * DH_);
    const char* Ulb = (const char*)(g_Ul + (size_t)bh * L_ * DH_);

    float acc[2][4][4] = {};

    auto loadStage = [&](int st, int j0) {
        const uint32_t sb = smb + st * AT_STAGE;
        // E tiles: 64 rows (j) x 256B (128 i bf16), swizzled
        #pragma unroll
        for (int q = 0; q < 4; q++) {
            int id = tid + q * 256;
            int row = id >> 4, c16 = (id & 15) << 4;
            uint32_t soff = row * 256 + (c16 ^ ((row & 7) << 4));
            size_t go = (size_t)(j0 + row) * (L_ * 2) + (size_t)i0 * 2 + c16;
            cp16(sb + soff,         Ehb + go);
            cp16(sb + 16384 + soff, Elb + go);
        }
        // U tiles: 64 rows x 128B, swizzled
        #pragma unroll
        for (int q = 0; q < 2; q++) {
            int id = tid + q * 256;
            int row = id >> 3, c16 = (id & 7) << 4;
            uint32_t uoff = row * 128 + (c16 ^ ((row & 7) << 4));
            cp16(sb + 32768 + uoff, Uhb + (size_t)(j0 + row) * 128 + c16);
            cp16(sb + 40960 + uoff, Ulb + (size_t)(j0 + row) * 128 + c16);
        }
    };

    loadStage(0, 0);
    CP_COMMIT();

    for (int c = 0; c < L_ / 64; c++) {
        const int st = c & 1;
        if (c + 1 < L_ / 64) { loadStage(st ^ 1, (c + 1) * 64); CP_COMMIT(); CP_WAIT1(); }
        else                 { CP_WAIT0(); }
        __syncthreads();

        const uint32_t sb = smb + st * AT_STAGE;
        #pragma unroll
        for (int s = 0; s < 4; s++) {
            const int k0 = s * 16;
            uint32_t eH[2][4], eL[2][4], uH[4][2], uL[4][2];
            {
                const int r = k0 + (lane & 7) + ((lane >> 4) << 3);
                const int cbl = (((lane >> 3) & 1) << 4);
                #pragma unroll
                for (int mt = 0; mt < 2; mt++) {
                    int cb = (wi * 32 + mt * 16) * 2 + cbl;
                    uint32_t ad = sb + r * 256 + (cb ^ ((r & 7) << 4));
                    ldsm_x4t(eH[mt], ad);
                    ldsm_x4t(eL[mt], ad + 16384);
                }
            }
            {
                const int r = k0 + (lane & 7) + (((lane >> 3) & 1) << 3);
                #pragma unroll
                for (int nt = 0; nt < 4; nt++) {
                    int cb = (wd * 32 + nt * 8) * 2;
                    uint32_t ud = sb + 32768 + r * 128 + (cb ^ ((r & 7) << 4));
                    ldsm_x2t(uH[nt], ud);
                    ldsm_x2t(uL[nt], ud + 8192);
                }
            }
            #pragma unroll
            for (int mt = 0; mt < 2; mt++)
                #pragma unroll
                for (int nt = 0; nt < 4; nt++) {
                    mma_bf16(acc[mt][nt], eH[mt], uH[nt]);
                    mma_bf16(acc[mt][nt], eH[mt], uL[nt]);
                    mma_bf16(acc[mt][nt], eL[mt], uH[nt]);
                }
        }
        __syncthreads();
    }

    // epilogue: O split-bf16 directly into g_Ahi/g_Alo [ML][E]
    #pragma unroll
    for (int mt = 0; mt < 2; mt++) {
        #pragma unroll
        for (int nt = 0; nt < 4; nt++) {
            const int row = i0 + wi * 32 + mt * 16 + (lane >> 2);
            const int col = h * DH_ + wd * 32 + nt * 8 + 2 * (lane & 3);
            float x0 = __ldg(x + b * L_ + row);
            float x1 = __ldg(x + b * L_ + row + 8);
            float o0 = acc[mt][nt][0] * x0, o1 = acc[mt][nt][1] * x0;
            float o2 = acc[mt][nt][2] * x1, o3 = acc[mt][nt][3] * x1;
            size_t r0 = ((size_t)b * L_ + row) * E_ + col;
            size_t r8 = ((size_t)b * L_ + row + 8) * E_ + col;
            __nv_bfloat16 h0 = __float2bfloat16(o0), h1 = __float2bfloat16(o1);
            __nv_bfloat16 h2 = __float2bfloat16(o2), h3 = __float2bfloat16(o3);
            *(__nv_bfloat162*)(g_Ahi + r0) = __halves2bfloat162(h0, h1);
            *(__nv_bfloat162*)(g_Ahi + r8) = __halves2bfloat162(h2, h3);
            *(__nv_bfloat162*)(g_Alo + r0) = __halves2bfloat162(
                __float2bfloat16(o0 - __bfloat162float(h0)),
                __float2bfloat16(o1 - __bfloat162float(h1)));
            *(__nv_bfloat162*)(g_Alo + r8) = __halves2bfloat162(
                __float2bfloat16(o2 - __bfloat162float(h2)),
                __float2bfloat16(o3 - __bfloat162float(h3)));
        }
    }
}

// ---------------- launch ----------------
extern "C" void kernel_launch(void* const* d_in, const int* in_sizes, int n_in,
                              void* d_out, int out_size)
{
    (void)in_sizes; (void)n_in; (void)out_size;
    const float* x  = (const float*)d_in[0];
    const float* z  = (const float*)d_in[1];
    const float* Wq = (const float*)d_in[2];
    const float* bq = (const float*)d_in[3];
    const float* Wk = (const float*)d_in[4];
    const float* bk = (const float*)d_in[5];
    const float* Wv = (const float*)d_in[6];
    const float* bv = (const float*)d_in[7];
    const float* W1 = (const float*)d_in[8];
    const float* b1 = (const float*)d_in[9];
    const float* W2 = (const float*)d_in[10];
    const float* b2 = (const float*)d_in[11];
    float* out = (float*)d_out;

    __nv_bfloat16 *pAhi, *pAlo, *pBhi, *pBlo, *pQKVhi, *pQKVlo, *pEhi, *pElo;
    float *pDen, *pBiasP;
    cudaGetSymbolAddress((void**)&pAhi, g_Ahi);
    cudaGetSymbolAddress((void**)&pAlo, g_Alo);
    cudaGetSymbolAddress((void**)&pBhi, g_Bthi);
    cudaGetSymbolAddress((void**)&pBlo, g_Btlo);
    cudaGetSymbolAddress((void**)&pQKVhi, g_QKVhi);
    cudaGetSymbolAddress((void**)&pQKVlo, g_QKVlo);
    cudaGetSymbolAddress((void**)&pEhi, g_Ehi);
    cudaGetSymbolAddress((void**)&pElo, g_Elo);
    cudaGetSymbolAddress((void**)&pDen, g_den);
    cudaGetSymbolAddress((void**)&pBiasP, g_biasP);

    cudaFuncSetAttribute(gemm_mma<0>, cudaFuncAttributeMaxDynamicSharedMemorySize, G_SMEM);
    cudaFuncSetAttribute(gemm_mma<1>, cudaFuncAttributeMaxDynamicSharedMemorySize, G_SMEM);
    cudaFuncSetAttribute(gemm_mma<2>, cudaFuncAttributeMaxDynamicSharedMemorySize, G_SMEM);
    cudaFuncSetAttribute(attn_mma, cudaFuncAttributeMaxDynamicSharedMemorySize, AT_SMEM);

    const size_t nZ = (size_t)ML_ * E_;

    // init: packed bias, out = b2, den = 0
    init_kernel<<<256, 256>>>(bq, bk, bv, b2, out);

    // split z
    split_kernel<<<nZ / 1024, 256>>>(z, pAhi, pAlo);

    // pack transposed QKV weights
    dim3 gT(E_ / 32, E_ / 32);
    transpose_split<<<gT, 256>>>(Wq, pBhi,                  pBlo,                  E_, E_);
    transpose_split<<<gT, 256>>>(Wk, pBhi + (size_t)E_*E_,  pBlo + (size_t)E_*E_,  E_, E_);
    transpose_split<<<gT, 256>>>(Wv, pBhi + (size_t)2*E_*E_,pBlo + (size_t)2*E_*E_,E_, E_);

    // fused QKV projection -> split bf16 [ML][3072]
    gemm_mma<0><<<dim3(QKV_LD / 128, ML_ / 128), 256, G_SMEM>>>(
        pAhi, pAlo, pBhi, pBlo, pBiasP, nullptr, pQKVhi, pQKVlo, nullptr,
        E_, E_, QKV_LD, E_);

    // QK: E = exp(K_j . Q_i / 8) split bf16 + atomic denom
    gemm_mma<1><<<dim3(L_ / 128, L_ / 128, BH_), 256, G_SMEM>>>(
        pQKVhi, pQKVlo, pQKVhi, pQKVlo, nullptr, x, pEhi, pElo, pDen,
        QKV_LD, QKV_LD, L_, DH_);

    // U = x_j * V / den, split bf16
    u_kernel<<<(BH_ * L_ * DH_) / 256, 256>>>(x);

    // attention output -> O split bf16 (into g_Ahi/g_Alo)
    attn_mma<<<dim3(L_ / 128, BH_), 256, AT_SMEM>>>(x);

    // W1 transpose (reuses BT buffers after projection done)
    transpose_split<<<dim3(HID_ / 32, E_ / 32), 256>>>(W1, pBhi, pBlo, E_, HID_);

    // MLP1 + fused W2 reduction -> out (atomic)
    gemm_mma<2><<<dim3(HID_ / 128, ML_ / 128), 256, G_SMEM>>>(
        pAhi, pAlo, pBhi, pBlo, b1, W2, nullptr, nullptr, out,
        E_, E_, 0, E_);
}

// round 9
// speedup vs baseline: 3.1076x; 1.1909x over previous
#include <cuda_runtime.h>
#include <cuda_fp16.h>
#include <math.h>
#include <stdint.h>

#define B_   2
#define L_   2048
#define E_   1024
#define H_   16
#define DH_  64
#define HID_ 4096
#define BH_  (B_*H_)    /* 32   */
#define ML_  (B_*L_)    /* 4096 */
#define QKV_LD 3072

// ---------------- scratch (device globals; no allocation allowed) ----------------
__device__ __align__(128) __half g_Ehi[(size_t)BH_ * L_ * L_];   // [bh][j][i] = exp(S^T) hi
__device__ __align__(128) __half g_Elo[(size_t)BH_ * L_ * L_];
__device__ __align__(128) float  g_den[(size_t)BH_ * L_];

__device__ __align__(128) __half g_Ahi [(size_t)ML_ * E_];       // z-split, later O-split
__device__ __align__(128) __half g_Alo [(size_t)ML_ * E_];
__device__ __align__(128) __half g_Bthi[(size_t)HID_ * E_];      // transposed weights [N,K]
__device__ __align__(128) __half g_Btlo[(size_t)HID_ * E_];
__device__ __align__(128) __half g_QKVhi[(size_t)ML_ * QKV_LD]; // [ML][Q|K|V]
__device__ __align__(128) __half g_QKVlo[(size_t)ML_ * QKV_LD];
__device__ __align__(128) __half g_Uh  [(size_t)BH_ * L_ * DH_];
__device__ __align__(128) float  g_biasP[QKV_LD];

// ---------------- ptx helpers (sm_80-compatible PTX only) ----------------
__device__ __forceinline__ uint32_t smem_u32(const void* p) {
    uint32_t a;
    asm("{ .reg .u64 t; cvta.to.shared.u64 t, %1; cvt.u32.u64 %0, t; }" : "=r"(a) : "l"(p));
    return a;
}
__device__ __forceinline__ void cp16(uint32_t saddr, const void* g) {
    asm volatile("cp.async.cg.shared.global [%0], [%1], 16;" :: "r"(saddr), "l"(g));
}
#define CP_COMMIT() asm volatile("cp.async.commit_group;" ::: "memory")
#define CP_WAIT0()  asm volatile("cp.async.wait_group 0;" ::: "memory")
#define CP_WAIT1()  asm volatile("cp.async.wait_group 1;" ::: "memory")

__device__ __forceinline__ void ldsm_x4(uint32_t* r, uint32_t a) {
    asm volatile("ldmatrix.sync.aligned.m8n8.x4.shared.b16 {%0,%1,%2,%3}, [%4];"
        : "=r"(r[0]), "=r"(r[1]), "=r"(r[2]), "=r"(r[3]) : "r"(a));
}
__device__ __forceinline__ void ldsm_x4t(uint32_t* r, uint32_t a) {
    asm volatile("ldmatrix.sync.aligned.m8n8.x4.trans.shared.b16 {%0,%1,%2,%3}, [%4];"
        : "=r"(r[0]), "=r"(r[1]), "=r"(r[2]), "=r"(r[3]) : "r"(a));
}
__device__ __forceinline__ void ldsm_x2(uint32_t* r, uint32_t a) {
    asm volatile("ldmatrix.sync.aligned.m8n8.x2.shared.b16 {%0,%1}, [%2];"
        : "=r"(r[0]), "=r"(r[1]) : "r"(a));
}
__device__ __forceinline__ void ldsm_x2t(uint32_t* r, uint32_t a) {
    asm volatile("ldmatrix.sync.aligned.m8n8.x2.trans.shared.b16 {%0,%1}, [%2];"
        : "=r"(r[0]), "=r"(r[1]) : "r"(a));
}
__device__ __forceinline__ void mma_f16(float* d, const uint32_t* a, const uint32_t* b) {
    asm volatile("mma.sync.aligned.m16n8k16.row.col.f32.f16.f16.f32 "
        "{%0,%1,%2,%3}, {%4,%5,%6,%7}, {%8,%9}, {%0,%1,%2,%3};"
        : "+f"(d[0]), "+f"(d[1]), "+f"(d[2]), "+f"(d[3])
        : "r"(a[0]), "r"(a[1]), "r"(a[2]), "r"(a[3]), "r"(b[0]), "r"(b[1]));
}

__device__ __forceinline__ float gelu_exact(float v) {
    return 0.5f * v * (1.0f + erff(v * 0.7071067811865476f));
}

// ---------------- init: pack bias, init out=b2, zero den ----------------
__global__ void __launch_bounds__(256) init_kernel(const float* __restrict__ bq,
                                                   const float* __restrict__ bk,
                                                   const float* __restrict__ bv,
                                                   const float* __restrict__ b2,
                                                   float* __restrict__ out)
{
    int i = blockIdx.x * 256 + threadIdx.x;
    if (i < 1024)      g_biasP[i] = bq[i];
    else if (i < 2048) g_biasP[i] = bk[i - 1024];
    else if (i < 3072) g_biasP[i] = bv[i - 2048];
    if (i < ML_) out[i] = b2[0];
    if (i < BH_ * L_) g_den[i] = 0.0f;
}

// ---------------- conversion kernels ----------------
__global__ void __launch_bounds__(256) split_kernel(const float* __restrict__ in,
                                                    __half* __restrict__ hi,
                                                    __half* __restrict__ lo)
{
    size_t i = (size_t)blockIdx.x * 1024 + threadIdx.x * 4;
    float4 v = *(const float4*)(in + i);
    __half h0 = __float2half_rn(v.x), h1 = __float2half_rn(v.y);
    __half h2 = __float2half_rn(v.z), h3 = __float2half_rn(v.w);
    __half l0 = __float2half_rn(v.x - __half2float(h0));
    __half l1 = __float2half_rn(v.y - __half2float(h1));
    __half l2 = __float2half_rn(v.z - __half2float(h2));
    __half l3 = __float2half_rn(v.w - __half2float(h3));
    ((__half2*)(hi + i))[0] = __halves2half2(h0, h1);
    ((__half2*)(hi + i))[1] = __halves2half2(h2, h3);
    ((__half2*)(lo + i))[0] = __halves2half2(l0, l1);
    ((__half2*)(lo + i))[1] = __halves2half2(l2, l3);
}

// W[K,N] fp32 -> Th/Tl[N,K] fp16
__global__ void __launch_bounds__(256) transpose_split(const float* __restrict__ W,
                                                       __half* __restrict__ Th,
                                                       __half* __restrict__ Tl,
                                                       int K, int N)
{
    __shared__ float sm[32][33];
    const int n0 = blockIdx.x * 32, k0 = blockIdx.y * 32;
    const int tx = threadIdx.x & 31, ty = threadIdx.x >> 5;
    #pragma unroll
    for (int i = 0; i < 4; i++)
        sm[ty + i * 8][tx] = W[(size_t)(k0 + ty + i * 8) * N + n0 + tx];
    __syncthreads();
    #pragma unroll
    for (int i = 0; i < 4; i++) {
        float v = sm[tx][ty + i * 8];
        __half h = __float2half_rn(v);
        __half l = __float2half_rn(v - __half2float(h));
        size_t o = (size_t)(n0 + ty + i * 8) * K + k0 + tx;
        Th[o] = h;
        Tl[o] = l;
    }
}

// ---------------- mma.sync split-fp16 GEMM ----------------
// TERMS==2: C = (Ah+Al) @ Bh^T (error A.Bl ~ 2^-12)
// TERMS==3: adds Ah @ Bl^T (error Al.Bl ~ 2^-22)
// MODE 0: C = A@B^T + bias -> split fp16 out (QKV projection)
// MODE 1: per-head E = exp(A@B^T / 8) -> split fp16 out + atomic denom (QK)
// MODE 2: y = gelu(A@B^T + bias); atomicAdd(out[row], y . W2)  (MLP + final)
#define G_STAGE(T) ((T) == 3 ? 65536 : 49152)
#define G_SMEM(T)  (2*G_STAGE(T) + 1024)

template<int MODE, int TERMS>
__global__ void __launch_bounds__(256) gemm_mma(
    const __half* __restrict__ Ahi, const __half* __restrict__ Alo,
    const __half* __restrict__ Bhi, const __half* __restrict__ Blo,
    const float* __restrict__ bias, const float* __restrict__ xw,
    __half* __restrict__ Chi, __half* __restrict__ Clo,
    float* __restrict__ aux,
    int lda, int ldb, int ldc, int K)
{
    extern __shared__ char smraw[];
    uint32_t smb = smem_u32(smraw);
    smb = (smb + 1023u) & ~1023u;

    const int tid = threadIdx.x, lane = tid & 31, warp = tid >> 5;
    const int wm = warp & 1, wn = warp >> 1;

    size_t aOff = 0, bOff = 0, eOff = 0;
    int bh = 0, bb = 0;
    if (MODE == 1) {
        bh = blockIdx.z; bb = bh >> 4;
        const int h = bh & 15;
        aOff = (size_t)bb * L_ * QKV_LD + 1024 + h * DH_;   // K vectors
        bOff = (size_t)bb * L_ * QKV_LD + h * DH_;          // Q vectors
        eOff = (size_t)bh * L_ * L_;
    }
    const int m0g = blockIdx.y * 128, n0g = blockIdx.x * 128;

    const char* gA[2] = { (const char*)(Ahi + aOff + (size_t)m0g * lda),
                          (const char*)(Alo + aOff + (size_t)m0g * lda) };
    const char* gB[2] = { (const char*)(Bhi + bOff + (size_t)n0g * ldb),
                          (const char*)(Blo + bOff + (size_t)n0g * ldb) };

    const int nCh = K >> 6;
    float acc[4][4][4] = {};
    const int NARR = (TERMS == 3) ? 4 : 3;

    auto loadStage = [&](int st, int k0) {
        #pragma unroll
        for (int arr = 0; arr < NARR; arr++) {
            const char* base = (arr < 2) ? gA[arr] : gB[arr - 2];
            const int ld2 = ((arr < 2) ? lda : ldb) * 2;
            const uint32_t sb = smb + st * G_STAGE(TERMS) + arr * 16384;
            #pragma unroll
            for (int q = 0; q < 4; q++) {
                int id = tid + q * 256;
                int row = id >> 3, c16 = (id & 7) << 4;
                uint32_t sa = sb + row * 128 + (c16 ^ ((row & 7) << 4));
                cp16(sa, base + (size_t)row * ld2 + k0 * 2 + c16);
            }
        }
    };

    loadStage(0, 0);
    CP_COMMIT();

    for (int c = 0; c < nCh; c++) {
        const int st = c & 1;
        if (c + 1 < nCh) { loadStage(st ^ 1, (c + 1) << 6); CP_COMMIT(); CP_WAIT1(); }
        else             { CP_WAIT0(); }
        __syncthreads();

        const uint32_t sA = smb + st * G_STAGE(TERMS);
        const uint32_t sB = sA + 32768;
        #pragma unroll
        for (int s = 0; s < 4; s++) {
            const int kb = s * 32;
            uint32_t aH[4][4], aL[4][4], bH[4][2], bL[4][2];
            const int lr = lane & 15, lc = lane >> 4;
            #pragma unroll
            for (int mt = 0; mt < 4; mt++) {
                int r = wm * 64 + mt * 16 + lr;
                int cb = kb + lc * 16;
                uint32_t ad = sA + r * 128 + (cb ^ ((r & 7) << 4));
                ldsm_x4(aH[mt], ad);
                ldsm_x4(aL[mt], ad + 16384);
            }
            const int br = lane & 7, bc = (lane >> 3) & 1;
            #pragma unroll
            for (int nt = 0; nt < 4; nt++) {
                int r = wn * 32 + nt * 8 + br;
                int cb = kb + bc * 16;
                uint32_t bd = sB + r * 128 + (cb ^ ((r & 7) << 4));
                ldsm_x2(bH[nt], bd);
                if (TERMS == 3) ldsm_x2(bL[nt], bd + 16384);
            }
            #pragma unroll
            for (int mt = 0; mt < 4; mt++)
                #pragma unroll
                for (int nt = 0; nt < 4; nt++) {
                    mma_f16(acc[mt][nt], aH[mt], bH[nt]);
                    mma_f16(acc[mt][nt], aL[mt], bH[nt]);
                    if (TERMS == 3) mma_f16(acc[mt][nt], aH[mt], bL[nt]);
                }
        }
        __syncthreads();
    }

    // ---- epilogues ----
    if (MODE == 0) {
        #pragma unroll
        for (int mt = 0; mt < 4; mt++) {
            #pragma unroll
            for (int nt = 0; nt < 4; nt++) {
                const int row = m0g + wm * 64 + mt * 16 + (lane >> 2);
                const int col = n0g + wn * 32 + nt * 8 + 2 * (lane & 3);
                float b0 = __ldg(bias + col), b1 = __ldg(bias + col + 1);
                float v0 = acc[mt][nt][0] + b0, v1 = acc[mt][nt][1] + b1;
                float v2 = acc[mt][nt][2] + b0, v3 = acc[mt][nt][3] + b1;
                __half h0 = __float2half_rn(v0), h1 = __float2half_rn(v1);
                __half h2 = __float2half_rn(v2), h3 = __float2half_rn(v3);
                *(__half2*)(Chi + (size_t)row * ldc + col)       = __halves2half2(h0, h1);
                *(__half2*)(Chi + (size_t)(row + 8) * ldc + col) = __halves2half2(h2, h3);
                *(__half2*)(Clo + (size_t)row * ldc + col) = __halves2half2(
                    __float2half_rn(v0 - __half2float(h0)),
                    __float2half_rn(v1 - __half2float(h1)));
                *(__half2*)(Clo + (size_t)(row + 8) * ldc + col) = __halves2half2(
                    __float2half_rn(v2 - __half2float(h2)),
                    __float2half_rn(v3 - __half2float(h3)));
            }
        }
    } else if (MODE == 1) {
        const float* xb = xw + bb * L_;
        float xc[4][2];
        #pragma unroll
        for (int nt = 0; nt < 4; nt++) {
            int col = n0g + wn * 32 + nt * 8 + 2 * (lane & 3);
            xc[nt][0] = __ldg(xb + col);
            xc[nt][1] = __ldg(xb + col + 1);
        }
        #pragma unroll
        for (int mt = 0; mt < 4; mt++) {
            const int rg = m0g + wm * 64 + mt * 16 + (lane >> 2);
            float p0 = 0.0f, p8 = 0.0f;
            #pragma unroll
            for (int nt = 0; nt < 4; nt++) {
                const int col = n0g + wn * 32 + nt * 8 + 2 * (lane & 3);
                float e0 = __expf(acc[mt][nt][0] * 0.125f);
                float e1 = __expf(acc[mt][nt][1] * 0.125f);
                float e2 = __expf(acc[mt][nt][2] * 0.125f);
                float e3 = __expf(acc[mt][nt][3] * 0.125f);
                __half h0 = __float2half_rn(e0), h1 = __float2half_rn(e1);
                __half h2 = __float2half_rn(e2), h3 = __float2half_rn(e3);
                *(__half2*)(Chi + eOff + (size_t)rg * ldc + col)       = __halves2half2(h0, h1);
                *(__half2*)(Chi + eOff + (size_t)(rg + 8) * ldc + col) = __halves2half2(h2, h3);
                *(__half2*)(Clo + eOff + (size_t)rg * ldc + col) = __halves2half2(
                    __float2half_rn(e0 - __half2float(h0)),
                    __float2half_rn(e1 - __half2float(h1)));
                *(__half2*)(Clo + eOff + (size_t)(rg + 8) * ldc + col) = __halves2half2(
                    __float2half_rn(e2 - __half2float(h2)),
                    __float2half_rn(e3 - __half2float(h3)));
                p0 += xc[nt][0] * e0 + xc[nt][1] * e1;
                p8 += xc[nt][0] * e2 + xc[nt][1] * e3;
            }
            p0 += __shfl_xor_sync(0xffffffffu, p0, 1);
            p0 += __shfl_xor_sync(0xffffffffu, p0, 2);
            p8 += __shfl_xor_sync(0xffffffffu, p8, 1);
            p8 += __shfl_xor_sync(0xffffffffu, p8, 2);
            if ((lane & 3) == 0) {
                atomicAdd(aux + (size_t)bh * L_ + rg,     p0);
                atomicAdd(aux + (size_t)bh * L_ + rg + 8, p8);
            }
        }
    } else {  // MODE == 2
        #pragma unroll
        for (int mt = 0; mt < 4; mt++) {
            const int row = m0g + wm * 64 + mt * 16 + (lane >> 2);
            float p0 = 0.0f, p8 = 0.0f;
            #pragma unroll
            for (int nt = 0; nt < 4; nt++) {
                const int col = n0g + wn * 32 + nt * 8 + 2 * (lane & 3);
                float b0 = __ldg(bias + col), b1 = __ldg(bias + col + 1);
                float w0 = __ldg(xw + col),  w1 = __ldg(xw + col + 1);
                float v0 = gelu_exact(acc[mt][nt][0] + b0);
                float v1 = gelu_exact(acc[mt][nt][1] + b1);
                float v2 = gelu_exact(acc[mt][nt][2] + b0);
                float v3 = gelu_exact(acc[mt][nt][3] + b1);
                p0 += v0 * w0 + v1 * w1;
                p8 += v2 * w0 + v3 * w1;
            }
            p0 += __shfl_xor_sync(0xffffffffu, p0, 1);
            p0 += __shfl_xor_sync(0xffffffffu, p0, 2);
            p8 += __shfl_xor_sync(0xffffffffu, p8, 1);
            p8 += __shfl_xor_sync(0xffffffffu, p8, 2);
            if ((lane & 3) == 0) {
                atomicAdd(aux + row,     p0);
                atomicAdd(aux + row + 8, p8);
            }
        }
    }
}

// ---------------- U kernel: U[bh][j][d] = x_j * V[b,j,h,d] / den[bh][j] (fp16) ----------------
__global__ void __launch_bounds__(256) u_kernel(const float* __restrict__ x)
{
    int gid = blockIdx.x * 256 + threadIdx.x;
    int d = gid & 63;
    int row = gid >> 6;                          // bh*L + j
    int bh = row >> 11, j = row & (L_ - 1);
    int b = bh >> 4, h = bh & 15;
    float den = g_den[row];
    size_t vo = ((size_t)b * L_ + j) * QKV_LD + 2048 + h * DH_ + d;
    float v = __half2float(g_QKVhi[vo]) + __half2float(g_QKVlo[vo]);
    float u = __ldg(x + b * L_ + j) * v / den;
    g_Uh[(size_t)row * DH_ + d] = __float2half_rn(u);
}

// ---------------- attention output: O[i,d] = x_i * sum_j E[j,i]*U[j,d] ----------------
// 2-term: (Eh+El).Uh — error E.Ul ~ 2^-12
#define AT_STAGE 40960  /* Eh 16K | El 16K | Uh 8K */
#define AT_SMEM  (2*AT_STAGE + 1024)

__global__ void __launch_bounds__(256) attn_mma(const float* __restrict__ x)
{
    extern __shared__ char smraw[];
    uint32_t smb = smem_u32(smraw);
    smb = (smb + 1023u) & ~1023u;

    const int tid = threadIdx.x, lane = tid & 31, warp = tid >> 5;
    const int wi = warp & 3, wd = warp >> 2;     // warp tile: 32 i x 32 d
    const int bh = blockIdx.y, b = bh >> 4, h = bh & 15;
    const int i0 = blockIdx.x * 128;

    const char* Ehb = (const char*)(g_Ehi + (size_t)bh * L_ * L_);
    const char* Elb = (const char*)(g_Elo + (size_t)bh * L_ * L_);
    const char* Uhb = (const char*)(g_Uh + (size_t)bh * L_ * DH_);

    float acc[2][4][4] = {};

    auto loadStage = [&](int st, int j0) {
        const uint32_t sb = smb + st * AT_STAGE;
        #pragma unroll
        for (int q = 0; q < 4; q++) {
            int id = tid + q * 256;
            int row = id >> 4, c16 = (id & 15) << 4;
            uint32_t soff = row * 256 + (c16 ^ ((row & 7) << 4));
            size_t go = (size_t)(j0 + row) * (L_ * 2) + (size_t)i0 * 2 + c16;
            cp16(sb + soff,         Ehb + go);
            cp16(sb + 16384 + soff, Elb + go);
        }
        #pragma unroll
        for (int q = 0; q < 2; q++) {
            int id = tid + q * 256;
            int row = id >> 3, c16 = (id & 7) << 4;
            uint32_t uoff = row * 128 + (c16 ^ ((row & 7) << 4));
            cp16(sb + 32768 + uoff, Uhb + (size_t)(j0 + row) * 128 + c16);
        }
    };

    loadStage(0, 0);
    CP_COMMIT();

    for (int c = 0; c < L_ / 64; c++) {
        const int st = c & 1;
        if (c + 1 < L_ / 64) { loadStage(st ^ 1, (c + 1) * 64); CP_COMMIT(); CP_WAIT1(); }
        else                 { CP_WAIT0(); }
        __syncthreads();

        const uint32_t sb = smb + st * AT_STAGE;
        #pragma unroll
        for (int s = 0; s < 4; s++) {
            const int k0 = s * 16;
            uint32_t eH[2][4], eL[2][4], uH[4][2];
            {
                const int r = k0 + (lane & 7) + ((lane >> 4) << 3);
                const int cbl = (((lane >> 3) & 1) << 4);
                #pragma unroll
                for (int mt = 0; mt < 2; mt++) {
                    int cb = (wi * 32 + mt * 16) * 2 + cbl;
                    uint32_t ad = sb + r * 256 + (cb ^ ((r & 7) << 4));
                    ldsm_x4t(eH[mt], ad);
                    ldsm_x4t(eL[mt], ad + 16384);
                }
            }
            {
                const int r = k0 + (lane & 7) + (((lane >> 3) & 1) << 3);
                #pragma unroll
                for (int nt = 0; nt < 4; nt++) {
                    int cb = (wd * 32 + nt * 8) * 2;
                    uint32_t ud = sb + 32768 + r * 128 + (cb ^ ((r & 7) << 4));
                    ldsm_x2t(uH[nt], ud);
                }
            }
            #pragma unroll
            for (int mt = 0; mt < 2; mt++)
                #pragma unroll
                for (int nt = 0; nt < 4; nt++) {
                    mma_f16(acc[mt][nt], eH[mt], uH[nt]);
                    mma_f16(acc[mt][nt], eL[mt], uH[nt]);
                }
        }
        __syncthreads();
    }

    // epilogue: O split-fp16 directly into g_Ahi/g_Alo [ML][E]
    #pragma unroll
    for (int mt = 0; mt < 2; mt++) {
        #pragma unroll
        for (int nt = 0; nt < 4; nt++) {
            const int row = i0 + wi * 32 + mt * 16 + (lane >> 2);
            const int col = h * DH_ + wd * 32 + nt * 8 + 2 * (lane & 3);
            float x0 = __ldg(x + b * L_ + row);
            float x1 = __ldg(x + b * L_ + row + 8);
            float o0 = acc[mt][nt][0] * x0, o1 = acc[mt][nt][1] * x0;
            float o2 = acc[mt][nt][2] * x1, o3 = acc[mt][nt][3] * x1;
            size_t r0 = ((size_t)b * L_ + row) * E_ + col;
            size_t r8 = ((size_t)b * L_ + row + 8) * E_ + col;
            __half h0 = __float2half_rn(o0), h1 = __float2half_rn(o1);
            __half h2 = __float2half_rn(o2), h3 = __float2half_rn(o3);
            *(__half2*)(g_Ahi + r0) = __halves2half2(h0, h1);
            *(__half2*)(g_Ahi + r8) = __halves2half2(h2, h3);
            *(__half2*)(g_Alo + r0) = __halves2half2(
                __float2half_rn(o0 - __half2float(h0)),
                __float2half_rn(o1 - __half2float(h1)));
            *(__half2*)(g_Alo + r8) = __halves2half2(
                __float2half_rn(o2 - __half2float(h2)),
                __float2half_rn(o3 - __half2float(h3)));
        }
    }
}

// ---------------- launch ----------------
extern "C" void kernel_launch(void* const* d_in, const int* in_sizes, int n_in,
                              void* d_out, int out_size)
{
    (void)in_sizes; (void)n_in; (void)out_size;
    const float* x  = (const float*)d_in[0];
    const float* z  = (const float*)d_in[1];
    const float* Wq = (const float*)d_in[2];
    const float* bq = (const float*)d_in[3];
    const float* Wk = (const float*)d_in[4];
    const float* bk = (const float*)d_in[5];
    const float* Wv = (const float*)d_in[6];
    const float* bv = (const float*)d_in[7];
    const float* W1 = (const float*)d_in[8];
    const float* b1 = (const float*)d_in[9];
    const float* W2 = (const float*)d_in[10];
    const float* b2 = (const float*)d_in[11];
    float* out = (float*)d_out;

    __half *pAhi, *pAlo, *pBhi, *pBlo, *pQKVhi, *pQKVlo, *pEhi, *pElo;
    float *pDen, *pBiasP;
    cudaGetSymbolAddress((void**)&pAhi, g_Ahi);
    cudaGetSymbolAddress((void**)&pAlo, g_Alo);
    cudaGetSymbolAddress((void**)&pBhi, g_Bthi);
    cudaGetSymbolAddress((void**)&pBlo, g_Btlo);
    cudaGetSymbolAddress((void**)&pQKVhi, g_QKVhi);
    cudaGetSymbolAddress((void**)&pQKVlo, g_QKVlo);
    cudaGetSymbolAddress((void**)&pEhi, g_Ehi);
    cudaGetSymbolAddress((void**)&pElo, g_Elo);
    cudaGetSymbolAddress((void**)&pDen, g_den);
    cudaGetSymbolAddress((void**)&pBiasP, g_biasP);

    cudaFuncSetAttribute(gemm_mma<0, 2>, cudaFuncAttributeMaxDynamicSharedMemorySize, G_SMEM(2));
    cudaFuncSetAttribute(gemm_mma<1, 2>, cudaFuncAttributeMaxDynamicSharedMemorySize, G_SMEM(2));
    cudaFuncSetAttribute(gemm_mma<2, 3>, cudaFuncAttributeMaxDynamicSharedMemorySize, G_SMEM(3));
    cudaFuncSetAttribute(attn_mma, cudaFuncAttributeMaxDynamicSharedMemorySize, AT_SMEM);

    const size_t nZ = (size_t)ML_ * E_;

    // init: packed bias, out = b2, den = 0
    init_kernel<<<256, 256>>>(bq, bk, bv, b2, out);

    // split z
    split_kernel<<<nZ / 1024, 256>>>(z, pAhi, pAlo);

    // pack transposed QKV weights
    dim3 gT(E_ / 32, E_ / 32);
    transpose_split<<<gT, 256>>>(Wq, pBhi,                  pBlo,                  E_, E_);
    transpose_split<<<gT, 256>>>(Wk, pBhi + (size_t)E_*E_,  pBlo + (size_t)E_*E_,  E_, E_);
    transpose_split<<<gT, 256>>>(Wv, pBhi + (size_t)2*E_*E_,pBlo + (size_t)2*E_*E_,E_, E_);

    // fused QKV projection -> split fp16 [ML][3072]  (2-term)
    gemm_mma<0, 2><<<dim3(QKV_LD / 128, ML_ / 128), 256, G_SMEM(2)>>>(
        pAhi, pAlo, pBhi, pBlo, pBiasP, nullptr, pQKVhi, pQKVlo, nullptr,
        E_, E_, QKV_LD, E_);

    // QK: E = exp(K_j . Q_i / 8) split fp16 + atomic denom  (2-term)
    gemm_mma<1, 2><<<dim3(L_ / 128, L_ / 128, BH_), 256, G_SMEM(2)>>>(
        pQKVhi, pQKVlo, pQKVhi, pQKVlo, nullptr, x, pEhi, pElo, pDen,
        QKV_LD, QKV_LD, L_, DH_);

    // U = x_j * V / den, fp16
    u_kernel<<<(BH_ * L_ * DH_) / 256, 256>>>(x);

    // attention output -> O split fp16 (into g_Ahi/g_Alo)  (2-term)
    attn_mma<<<dim3(L_ / 128, BH_), 256, AT_SMEM>>>(x);

    // W1 transpose (reuses BT buffers after projection done)
    transpose_split<<<dim3(HID_ / 32, E_ / 32), 256>>>(W1, pBhi, pBlo, E_, HID_);

    // MLP1 + fused W2 reduction -> out (atomic, 3-term)
    gemm_mma<2, 3><<<dim3(HID_ / 128, ML_ / 128), 256, G_SMEM(3)>>>(
        pAhi, pAlo, pBhi, pBlo, b1, W2, nullptr, nullptr, out,
        E_, E_, 0, E_);
}

// round 10
// speedup vs baseline: 4.6240x; 1.4880x over previous
#include <cuda_runtime.h>
#include <cuda_fp16.h>
#include <math.h>
#include <stdint.h>

#define B_   2
#define L_   2048
#define E_   1024
#define H_   16
#define DH_  64
#define HID_ 4096
#define BH_  (B_*H_)    /* 32   */
#define ML_  (B_*L_)    /* 4096 */
#define QKV_LD 3072

// ---------------- scratch (device globals; no allocation allowed) ----------------
__device__ __align__(128) __half g_Ehi[(size_t)BH_ * L_ * L_];   // [bh][j][i] = exp(S^T), fp16
__device__ __align__(128) float  g_den[(size_t)BH_ * L_];

__device__ __align__(128) __half g_Ahi [(size_t)ML_ * E_];       // z-split, later O-split
__device__ __align__(128) __half g_Alo [(size_t)ML_ * E_];
__device__ __align__(128) __half g_Bthi[(size_t)HID_ * E_];      // transposed weights [N,K]
__device__ __align__(128) __half g_Btlo[(size_t)HID_ * E_];
__device__ __align__(128) __half g_QKVhi[(size_t)ML_ * QKV_LD]; // [ML][Q|K|V]
__device__ __align__(128) __half g_QKVlo[(size_t)ML_ * QKV_LD];
__device__ __align__(128) __half g_Uh  [(size_t)BH_ * L_ * DH_];
__device__ __align__(128) float  g_biasP[QKV_LD];

// ---------------- ptx helpers (sm_80-compatible PTX only) ----------------
__device__ __forceinline__ uint32_t smem_u32(const void* p) {
    uint32_t a;
    asm("{ .reg .u64 t; cvta.to.shared.u64 t, %1; cvt.u32.u64 %0, t; }" : "=r"(a) : "l"(p));
    return a;
}
__device__ __forceinline__ void cp16(uint32_t saddr, const void* g) {
    asm volatile("cp.async.cg.shared.global [%0], [%1], 16;" :: "r"(saddr), "l"(g));
}
#define CP_COMMIT() asm volatile("cp.async.commit_group;" ::: "memory")
#define CP_WAIT0()  asm volatile("cp.async.wait_group 0;" ::: "memory")
#define CP_WAIT1()  asm volatile("cp.async.wait_group 1;" ::: "memory")

__device__ __forceinline__ void ldsm_x4(uint32_t* r, uint32_t a) {
    asm volatile("ldmatrix.sync.aligned.m8n8.x4.shared.b16 {%0,%1,%2,%3}, [%4];"
        : "=r"(r[0]), "=r"(r[1]), "=r"(r[2]), "=r"(r[3]) : "r"(a));
}
__device__ __forceinline__ void ldsm_x4t(uint32_t* r, uint32_t a) {
    asm volatile("ldmatrix.sync.aligned.m8n8.x4.trans.shared.b16 {%0,%1,%2,%3}, [%4];"
        : "=r"(r[0]), "=r"(r[1]), "=r"(r[2]), "=r"(r[3]) : "r"(a));
}
__device__ __forceinline__ void ldsm_x2(uint32_t* r, uint32_t a) {
    asm volatile("ldmatrix.sync.aligned.m8n8.x2.shared.b16 {%0,%1}, [%2];"
        : "=r"(r[0]), "=r"(r[1]) : "r"(a));
}
__device__ __forceinline__ void ldsm_x2t(uint32_t* r, uint32_t a) {
    asm volatile("ldmatrix.sync.aligned.m8n8.x2.trans.shared.b16 {%0,%1}, [%2];"
        : "=r"(r[0]), "=r"(r[1]) : "r"(a));
}
__device__ __forceinline__ void mma_f16(float* d, const uint32_t* a, const uint32_t* b) {
    asm volatile("mma.sync.aligned.m16n8k16.row.col.f32.f16.f16.f32 "
        "{%0,%1,%2,%3}, {%4,%5,%6,%7}, {%8,%9}, {%0,%1,%2,%3};"
        : "+f"(d[0]), "+f"(d[1]), "+f"(d[2]), "+f"(d[3])
        : "r"(a[0]), "r"(a[1]), "r"(a[2]), "r"(a[3]), "r"(b[0]), "r"(b[1]));
}

__device__ __forceinline__ float gelu_exact(float v) {
    return 0.5f * v * (1.0f + erff(v * 0.7071067811865476f));
}

// ---------------- init: pack bias, init out=b2, zero den ----------------
__global__ void __launch_bounds__(256) init_kernel(const float* __restrict__ bq,
                                                   const float* __restrict__ bk,
                                                   const float* __restrict__ bv,
                                                   const float* __restrict__ b2,
                                                   float* __restrict__ out)
{
    int i = blockIdx.x * 256 + threadIdx.x;
    if (i < 1024)      g_biasP[i] = bq[i];
    else if (i < 2048) g_biasP[i] = bk[i - 1024];
    else if (i < 3072) g_biasP[i] = bv[i - 2048];
    if (i < ML_) out[i] = b2[0];
    if (i < BH_ * L_) g_den[i] = 0.0f;
}

// ---------------- conversion kernels ----------------
__global__ void __launch_bounds__(256) split_kernel(const float* __restrict__ in,
                                                    __half* __restrict__ hi,
                                                    __half* __restrict__ lo)
{
    size_t i = (size_t)blockIdx.x * 1024 + threadIdx.x * 4;
    float4 v = *(const float4*)(in + i);
    __half h0 = __float2half_rn(v.x), h1 = __float2half_rn(v.y);
    __half h2 = __float2half_rn(v.z), h3 = __float2half_rn(v.w);
    __half l0 = __float2half_rn(v.x - __half2float(h0));
    __half l1 = __float2half_rn(v.y - __half2float(h1));
    __half l2 = __float2half_rn(v.z - __half2float(h2));
    __half l3 = __float2half_rn(v.w - __half2float(h3));
    ((__half2*)(hi + i))[0] = __halves2half2(h0, h1);
    ((__half2*)(hi + i))[1] = __halves2half2(h2, h3);
    ((__half2*)(lo + i))[0] = __halves2half2(l0, l1);
    ((__half2*)(lo + i))[1] = __halves2half2(l2, l3);
}

// W[K,N] fp32 -> Th/Tl[N,K] fp16
__global__ void __launch_bounds__(256) transpose_split(const float* __restrict__ W,
                                                       __half* __restrict__ Th,
                                                       __half* __restrict__ Tl,
                                                       int K, int N)
{
    __shared__ float sm[32][33];
    const int n0 = blockIdx.x * 32, k0 = blockIdx.y * 32;
    const int tx = threadIdx.x & 31, ty = threadIdx.x >> 5;
    #pragma unroll
    for (int i = 0; i < 4; i++)
        sm[ty + i * 8][tx] = W[(size_t)(k0 + ty + i * 8) * N + n0 + tx];
    __syncthreads();
    #pragma unroll
    for (int i = 0; i < 4; i++) {
        float v = sm[tx][ty + i * 8];
        __half h = __float2half_rn(v);
        __half l = __float2half_rn(v - __half2float(h));
        size_t o = (size_t)(n0 + ty + i * 8) * K + k0 + tx;
        Th[o] = h;
        Tl[o] = l;
    }
}

// ---------------- mma.sync split-fp16 GEMM (2-term: (Ah+Al) @ Bh^T) ----------------
// MODE 0: C = A@B^T + bias -> split fp16 out (QKV projection)
// MODE 1: per-head E = exp(A@B^T / 8) -> single fp16 out + atomic denom (QK)
// MODE 2: y = gelu(A@B^T + bias); atomicAdd(out[row], y . W2)  (MLP + final)
#define G_STAGE 49152   /* Ah 16K | Al 16K | Bh 16K */
#define G_SMEM  (2*G_STAGE + 1024)

template<int MODE>
__global__ void __launch_bounds__(256) gemm_mma(
    const __half* __restrict__ Ahi, const __half* __restrict__ Alo,
    const __half* __restrict__ Bhi,
    const float* __restrict__ bias, const float* __restrict__ xw,
    __half* __restrict__ Chi, __half* __restrict__ Clo,
    float* __restrict__ aux,
    int lda, int ldb, int ldc, int K)
{
    extern __shared__ char smraw[];
    uint32_t smb = smem_u32(smraw);
    smb = (smb + 1023u) & ~1023u;

    const int tid = threadIdx.x, lane = tid & 31, warp = tid >> 5;
    const int wm = warp & 1, wn = warp >> 1;

    size_t aOff = 0, bOff = 0, eOff = 0;
    int bh = 0, bb = 0;
    if (MODE == 1) {
        bh = blockIdx.z; bb = bh >> 4;
        const int h = bh & 15;
        aOff = (size_t)bb * L_ * QKV_LD + 1024 + h * DH_;   // K vectors
        bOff = (size_t)bb * L_ * QKV_LD + h * DH_;          // Q vectors
        eOff = (size_t)bh * L_ * L_;
    }
    const int m0g = blockIdx.y * 128, n0g = blockIdx.x * 128;

    const char* gA[2] = { (const char*)(Ahi + aOff + (size_t)m0g * lda),
                          (const char*)(Alo + aOff + (size_t)m0g * lda) };
    const char* gB = (const char*)(Bhi + bOff + (size_t)n0g * ldb);

    const int nCh = K >> 6;
    float acc[4][4][4] = {};

    auto loadStage = [&](int st, int k0) {
        #pragma unroll
        for (int arr = 0; arr < 3; arr++) {
            const char* base = (arr < 2) ? gA[arr] : gB;
            const int ld2 = ((arr < 2) ? lda : ldb) * 2;
            const uint32_t sb = smb + st * G_STAGE + arr * 16384;
            #pragma unroll
            for (int q = 0; q < 4; q++) {
                int id = tid + q * 256;
                int row = id >> 3, c16 = (id & 7) << 4;
                uint32_t sa = sb + row * 128 + (c16 ^ ((row & 7) << 4));
                cp16(sa, base + (size_t)row * ld2 + k0 * 2 + c16);
            }
        }
    };

    loadStage(0, 0);
    CP_COMMIT();

    for (int c = 0; c < nCh; c++) {
        const int st = c & 1;
        if (c + 1 < nCh) { loadStage(st ^ 1, (c + 1) << 6); CP_COMMIT(); CP_WAIT1(); }
        else             { CP_WAIT0(); }
        __syncthreads();

        const uint32_t sA = smb + st * G_STAGE;
        const uint32_t sB = sA + 32768;
        #pragma unroll
        for (int s = 0; s < 4; s++) {
            const int kb = s * 32;
            uint32_t aH[4][4], aL[4][4], bH[4][2];
            const int lr = lane & 15, lc = lane >> 4;
            #pragma unroll
            for (int mt = 0; mt < 4; mt++) {
                int r = wm * 64 + mt * 16 + lr;
                int cb = kb + lc * 16;
                uint32_t ad = sA + r * 128 + (cb ^ ((r & 7) << 4));
                ldsm_x4(aH[mt], ad);
                ldsm_x4(aL[mt], ad + 16384);
            }
            const int br = lane & 7, bc = (lane >> 3) & 1;
            #pragma unroll
            for (int nt = 0; nt < 4; nt++) {
                int r = wn * 32 + nt * 8 + br;
                int cb = kb + bc * 16;
                uint32_t bd = sB + r * 128 + (cb ^ ((r & 7) << 4));
                ldsm_x2(bH[nt], bd);
            }
            #pragma unroll
            for (int mt = 0; mt < 4; mt++)
                #pragma unroll
                for (int nt = 0; nt < 4; nt++) {
                    mma_f16(acc[mt][nt], aH[mt], bH[nt]);
                    mma_f16(acc[mt][nt], aL[mt], bH[nt]);
                }
        }
        __syncthreads();
    }

    // ---- epilogues ----
    if (MODE == 0) {
        #pragma unroll
        for (int mt = 0; mt < 4; mt++) {
            #pragma unroll
            for (int nt = 0; nt < 4; nt++) {
                const int row = m0g + wm * 64 + mt * 16 + (lane >> 2);
                const int col = n0g + wn * 32 + nt * 8 + 2 * (lane & 3);
                float b0 = __ldg(bias + col), b1 = __ldg(bias + col + 1);
                float v0 = acc[mt][nt][0] + b0, v1 = acc[mt][nt][1] + b1;
                float v2 = acc[mt][nt][2] + b0, v3 = acc[mt][nt][3] + b1;
                __half h0 = __float2half_rn(v0), h1 = __float2half_rn(v1);
                __half h2 = __float2half_rn(v2), h3 = __float2half_rn(v3);
                *(__half2*)(Chi + (size_t)row * ldc + col)       = __halves2half2(h0, h1);
                *(__half2*)(Chi + (size_t)(row + 8) * ldc + col) = __halves2half2(h2, h3);
                *(__half2*)(Clo + (size_t)row * ldc + col) = __halves2half2(
                    __float2half_rn(v0 - __half2float(h0)),
                    __float2half_rn(v1 - __half2float(h1)));
                *(__half2*)(Clo + (size_t)(row + 8) * ldc + col) = __halves2half2(
                    __float2half_rn(v2 - __half2float(h2)),
                    __float2half_rn(v3 - __half2float(h3)));
            }
        }
    } else if (MODE == 1) {
        const float* xb = xw + bb * L_;
        float xc[4][2];
        #pragma unroll
        for (int nt = 0; nt < 4; nt++) {
            int col = n0g + wn * 32 + nt * 8 + 2 * (lane & 3);
            xc[nt][0] = __ldg(xb + col);
            xc[nt][1] = __ldg(xb + col + 1);
        }
        #pragma unroll
        for (int mt = 0; mt < 4; mt++) {
            const int rg = m0g + wm * 64 + mt * 16 + (lane >> 2);
            float p0 = 0.0f, p8 = 0.0f;
            #pragma unroll
            for (int nt = 0; nt < 4; nt++) {
                const int col = n0g + wn * 32 + nt * 8 + 2 * (lane & 3);
                float e0 = __expf(acc[mt][nt][0] * 0.125f);
                float e1 = __expf(acc[mt][nt][1] * 0.125f);
                float e2 = __expf(acc[mt][nt][2] * 0.125f);
                float e3 = __expf(acc[mt][nt][3] * 0.125f);
                *(__half2*)(Chi + eOff + (size_t)rg * ldc + col) =
                    __halves2half2(__float2half_rn(e0), __float2half_rn(e1));
                *(__half2*)(Chi + eOff + (size_t)(rg + 8) * ldc + col) =
                    __halves2half2(__float2half_rn(e2), __float2half_rn(e3));
                p0 += xc[nt][0] * e0 + xc[nt][1] * e1;
                p8 += xc[nt][0] * e2 + xc[nt][1] * e3;
            }
            p0 += __shfl_xor_sync(0xffffffffu, p0, 1);
            p0 += __shfl_xor_sync(0xffffffffu, p0, 2);
            p8 += __shfl_xor_sync(0xffffffffu, p8, 1);
            p8 += __shfl_xor_sync(0xffffffffu, p8, 2);
            if ((lane & 3) == 0) {
                atomicAdd(aux + (size_t)bh * L_ + rg,     p0);
                atomicAdd(aux + (size_t)bh * L_ + rg + 8, p8);
            }
        }
    } else {  // MODE == 2
        #pragma unroll
        for (int mt = 0; mt < 4; mt++) {
            const int row = m0g + wm * 64 + mt * 16 + (lane >> 2);
            float p0 = 0.0f, p8 = 0.0f;
            #pragma unroll
            for (int nt = 0; nt < 4; nt++) {
                const int col = n0g + wn * 32 + nt * 8 + 2 * (lane & 3);
                float b0 = __ldg(bias + col), b1 = __ldg(bias + col + 1);
                float w0 = __ldg(xw + col),  w1 = __ldg(xw + col + 1);
                float v0 = gelu_exact(acc[mt][nt][0] + b0);
                float v1 = gelu_exact(acc[mt][nt][1] + b1);
                float v2 = gelu_exact(acc[mt][nt][2] + b0);
                float v3 = gelu_exact(acc[mt][nt][3] + b1);
                p0 += v0 * w0 + v1 * w1;
                p8 += v2 * w0 + v3 * w1;
            }
            p0 += __shfl_xor_sync(0xffffffffu, p0, 1);
            p0 += __shfl_xor_sync(0xffffffffu, p0, 2);
            p8 += __shfl_xor_sync(0xffffffffu, p8, 1);
            p8 += __shfl_xor_sync(0xffffffffu, p8, 2);
            if ((lane & 3) == 0) {
                atomicAdd(aux + row,     p0);
                atomicAdd(aux + row + 8, p8);
            }
        }
    }
}

// ---------------- U kernel: U[bh][j][d] = x_j * V[b,j,h,d] / den[bh][j] (fp16) ----------------
__global__ void __launch_bounds__(256) u_kernel(const float* __restrict__ x)
{
    int gid = blockIdx.x * 256 + threadIdx.x;
    int d = gid & 63;
    int row = gid >> 6;                          // bh*L + j
    int bh = row >> 11, j = row & (L_ - 1);
    int b = bh >> 4, h = bh & 15;
    float den = g_den[row];
    size_t vo = ((size_t)b * L_ + j) * QKV_LD + 2048 + h * DH_ + d;
    float v = __half2float(g_QKVhi[vo]) + __half2float(g_QKVlo[vo]);
    float u = __ldg(x + b * L_ + j) * v / den;
    g_Uh[(size_t)row * DH_ + d] = __float2half_rn(u);
}

// ---------------- attention output: O[i,d] = x_i * sum_j E[j,i]*U[j,d] ----------------
// single-term fp16 E and U
#define AT_STAGE 24576  /* Eh 16K | Uh 8K */
#define AT_SMEM  (2*AT_STAGE + 1024)

__global__ void __launch_bounds__(256) attn_mma(const float* __restrict__ x)
{
    extern __shared__ char smraw[];
    uint32_t smb = smem_u32(smraw);
    smb = (smb + 1023u) & ~1023u;

    const int tid = threadIdx.x, lane = tid & 31, warp = tid >> 5;
    const int wi = warp & 3, wd = warp >> 2;     // warp tile: 32 i x 32 d
    const int bh = blockIdx.y, b = bh >> 4, h = bh & 15;
    const int i0 = blockIdx.x * 128;

    const char* Ehb = (const char*)(g_Ehi + (size_t)bh * L_ * L_);
    const char* Uhb = (const char*)(g_Uh + (size_t)bh * L_ * DH_);

    float acc[2][4][4] = {};

    auto loadStage = [&](int st, int j0) {
        const uint32_t sb = smb + st * AT_STAGE;
        #pragma unroll
        for (int q = 0; q < 4; q++) {
            int id = tid + q * 256;
            int row = id >> 4, c16 = (id & 15) << 4;
            uint32_t soff = row * 256 + (c16 ^ ((row & 7) << 4));
            size_t go = (size_t)(j0 + row) * (L_ * 2) + (size_t)i0 * 2 + c16;
            cp16(sb + soff, Ehb + go);
        }
        #pragma unroll
        for (int q = 0; q < 2; q++) {
            int id = tid + q * 256;
            int row = id >> 3, c16 = (id & 7) << 4;
            uint32_t uoff = row * 128 + (c16 ^ ((row & 7) << 4));
            cp16(sb + 16384 + uoff, Uhb + (size_t)(j0 + row) * 128 + c16);
        }
    };

    loadStage(0, 0);
    CP_COMMIT();

    for (int c = 0; c < L_ / 64; c++) {
        const int st = c & 1;
        if (c + 1 < L_ / 64) { loadStage(st ^ 1, (c + 1) * 64); CP_COMMIT(); CP_WAIT1(); }
        else                 { CP_WAIT0(); }
        __syncthreads();

        const uint32_t sb = smb + st * AT_STAGE;
        #pragma unroll
        for (int s = 0; s < 4; s++) {
            const int k0 = s * 16;
            uint32_t eH[2][4], uH[4][2];
            {
                const int r = k0 + (lane & 7) + ((lane >> 4) << 3);
                const int cbl = (((lane >> 3) & 1) << 4);
                #pragma unroll
                for (int mt = 0; mt < 2; mt++) {
                    int cb = (wi * 32 + mt * 16) * 2 + cbl;
                    uint32_t ad = sb + r * 256 + (cb ^ ((r & 7) << 4));
                    ldsm_x4t(eH[mt], ad);
                }
            }
            {
                const int r = k0 + (lane & 7) + (((lane >> 3) & 1) << 3);
                #pragma unroll
                for (int nt = 0; nt < 4; nt++) {
                    int cb = (wd * 32 + nt * 8) * 2;
                    uint32_t ud = sb + 16384 + r * 128 + (cb ^ ((r & 7) << 4));
                    ldsm_x2t(uH[nt], ud);
                }
            }
            #pragma unroll
            for (int mt = 0; mt < 2; mt++)
                #pragma unroll
                for (int nt = 0; nt < 4; nt++)
                    mma_f16(acc[mt][nt], eH[mt], uH[nt]);
        }
        __syncthreads();
    }

    // epilogue: O split-fp16 directly into g_Ahi/g_Alo [ML][E]
    #pragma unroll
    for (int mt = 0; mt < 2; mt++) {
        #pragma unroll
        for (int nt = 0; nt < 4; nt++) {
            const int row = i0 + wi * 32 + mt * 16 + (lane >> 2);
            const int col = h * DH_ + wd * 32 + nt * 8 + 2 * (lane & 3);
            float x0 = __ldg(x + b * L_ + row);
            float x1 = __ldg(x + b * L_ + row + 8);
            float o0 = acc[mt][nt][0] * x0, o1 = acc[mt][nt][1] * x0;
            float o2 = acc[mt][nt][2] * x1, o3 = acc[mt][nt][3] * x1;
            size_t r0 = ((size_t)b * L_ + row) * E_ + col;
            size_t r8 = ((size_t)b * L_ + row + 8) * E_ + col;
            __half h0 = __float2half_rn(o0), h1 = __float2half_rn(o1);
            __half h2 = __float2half_rn(o2), h3 = __float2half_rn(o3);
            *(__half2*)(g_Ahi + r0) = __halves2half2(h0, h1);
            *(__half2*)(g_Ahi + r8) = __halves2half2(h2, h3);
            *(__half2*)(g_Alo + r0) = __halves2half2(
                __float2half_rn(o0 - __half2float(h0)),
                __float2half_rn(o1 - __half2float(h1)));
            *(__half2*)(g_Alo + r8) = __halves2half2(
                __float2half_rn(o2 - __half2float(h2)),
                __float2half_rn(o3 - __half2float(h3)));
        }
    }
}

// ---------------- launch ----------------
extern "C" void kernel_launch(void* const* d_in, const int* in_sizes, int n_in,
                              void* d_out, int out_size)
{
    (void)in_sizes; (void)n_in; (void)out_size;
    const float* x  = (const float*)d_in[0];
    const float* z  = (const float*)d_in[1];
    const float* Wq = (const float*)d_in[2];
    const float* bq = (const float*)d_in[3];
    const float* Wk = (const float*)d_in[4];
    const float* bk = (const float*)d_in[5];
    const float* Wv = (const float*)d_in[6];
    const float* bv = (const float*)d_in[7];
    const float* W1 = (const float*)d_in[8];
    const float* b1 = (const float*)d_in[9];
    const float* W2 = (const float*)d_in[10];
    const float* b2 = (const float*)d_in[11];
    float* out = (float*)d_out;

    __half *pAhi, *pAlo, *pBhi, *pBlo, *pQKVhi, *pQKVlo, *pEhi;
    float *pDen, *pBiasP;
    cudaGetSymbolAddress((void**)&pAhi, g_Ahi);
    cudaGetSymbolAddress((void**)&pAlo, g_Alo);
    cudaGetSymbolAddress((void**)&pBhi, g_Bthi);
    cudaGetSymbolAddress((void**)&pBlo, g_Btlo);
    cudaGetSymbolAddress((void**)&pQKVhi, g_QKVhi);
    cudaGetSymbolAddress((void**)&pQKVlo, g_QKVlo);
    cudaGetSymbolAddress((void**)&pEhi, g_Ehi);
    cudaGetSymbolAddress((void**)&pDen, g_den);
    cudaGetSymbolAddress((void**)&pBiasP, g_biasP);

    cudaFuncSetAttribute(gemm_mma<0>, cudaFuncAttributeMaxDynamicSharedMemorySize, G_SMEM);
    cudaFuncSetAttribute(gemm_mma<1>, cudaFuncAttributeMaxDynamicSharedMemorySize, G_SMEM);
    cudaFuncSetAttribute(gemm_mma<2>, cudaFuncAttributeMaxDynamicSharedMemorySize, G_SMEM);
    cudaFuncSetAttribute(attn_mma, cudaFuncAttributeMaxDynamicSharedMemorySize, AT_SMEM);

    const size_t nZ = (size_t)ML_ * E_;

    // init: packed bias, out = b2, den = 0
    init_kernel<<<256, 256>>>(bq, bk, bv, b2, out);

    // split z
    split_kernel<<<nZ / 1024, 256>>>(z, pAhi, pAlo);

    // pack transposed QKV weights (hi only used by GEMM; lo kept for layout reuse)
    dim3 gT(E_ / 32, E_ / 32);
    transpose_split<<<gT, 256>>>(Wq, pBhi,                  pBlo,                  E_, E_);
    transpose_split<<<gT, 256>>>(Wk, pBhi + (size_t)E_*E_,  pBlo + (size_t)E_*E_,  E_, E_);
    transpose_split<<<gT, 256>>>(Wv, pBhi + (size_t)2*E_*E_,pBlo + (size_t)2*E_*E_,E_, E_);

    // fused QKV projection -> split fp16 [ML][3072]  (2-term)
    gemm_mma<0><<<dim3(QKV_LD / 128, ML_ / 128), 256, G_SMEM>>>(
        pAhi, pAlo, pBhi, pBiasP, nullptr, pQKVhi, pQKVlo, nullptr,
        E_, E_, QKV_LD, E_);

    // QK: E = exp(K_j . Q_i / 8) single fp16 + atomic denom  (2-term)
    gemm_mma<1><<<dim3(L_ / 128, L_ / 128, BH_), 256, G_SMEM>>>(
        pQKVhi, pQKVlo, pQKVhi, nullptr, x, pEhi, nullptr, pDen,
        QKV_LD, QKV_LD, L_, DH_);

    // U = x_j * V / den, fp16
    u_kernel<<<(BH_ * L_ * DH_) / 256, 256>>>(x);

    // attention output -> O split fp16 (into g_Ahi/g_Alo)  (1-term)
    attn_mma<<<dim3(L_ / 128, BH_), 256, AT_SMEM>>>(x);

    // W1 transpose
    transpose_split<<<dim3(HID_ / 32, E_ / 32), 256>>>(W1, pBhi, pBlo, E_, HID_);

    // MLP1 + fused W2 reduction -> out (atomic, 2-term)
    gemm_mma<2><<<dim3(HID_ / 128, ML_ / 128), 256, G_SMEM>>>(
        pAhi, pAlo, pBhi, b1, W2, nullptr, nullptr, out,
        E_, E_, 0, E_);
}

// round 11
// speedup vs baseline: 5.2387x; 1.1329x over previous
#include <cuda_runtime.h>
#include <cuda_fp16.h>
#include <math.h>
#include <stdint.h>

#define B_   2
#define L_   2048
#define E_   1024
#define H_   16
#define DH_  64
#define HID_ 4096
#define BH_  (B_*H_)    /* 32   */
#define ML_  (B_*L_)    /* 4096 */
#define QKV_LD 3072

// ---------------- scratch (device globals; no allocation allowed) ----------------
__device__ __align__(128) __half g_Ehi[(size_t)BH_ * L_ * L_];   // [bh][j][i] = exp(S^T), fp16
__device__ __align__(128) float  g_den[(size_t)BH_ * L_];

__device__ __align__(128) __half g_Ahi [(size_t)ML_ * E_];       // z-split, later O
__device__ __align__(128) __half g_Alo [(size_t)ML_ * E_];       // z lo (QKV A operand)
__device__ __align__(128) __half g_Bthi[(size_t)HID_ * E_];      // transposed weights [N,K]
__device__ __align__(128) __half g_Btlo[(size_t)HID_ * E_];
__device__ __align__(128) __half g_QKVhi[(size_t)ML_ * QKV_LD]; // [ML][Q|K|V]
__device__ __align__(128) __half g_QKVlo[(size_t)ML_ * QKV_LD];
__device__ __align__(128) __half g_Uh  [(size_t)BH_ * L_ * DH_];
__device__ __align__(128) float  g_biasP[QKV_LD];

// ---------------- ptx helpers (sm_80-compatible PTX only) ----------------
__device__ __forceinline__ uint32_t smem_u32(const void* p) {
    uint32_t a;
    asm("{ .reg .u64 t; cvta.to.shared.u64 t, %1; cvt.u32.u64 %0, t; }" : "=r"(a) : "l"(p));
    return a;
}
__device__ __forceinline__ void cp16(uint32_t saddr, const void* g) {
    asm volatile("cp.async.cg.shared.global [%0], [%1], 16;" :: "r"(saddr), "l"(g));
}
#define CP_COMMIT() asm volatile("cp.async.commit_group;" ::: "memory")
#define CP_WAIT0()  asm volatile("cp.async.wait_group 0;" ::: "memory")
#define CP_WAIT1()  asm volatile("cp.async.wait_group 1;" ::: "memory")

__device__ __forceinline__ void ldsm_x4(uint32_t* r, uint32_t a) {
    asm volatile("ldmatrix.sync.aligned.m8n8.x4.shared.b16 {%0,%1,%2,%3}, [%4];"
        : "=r"(r[0]), "=r"(r[1]), "=r"(r[2]), "=r"(r[3]) : "r"(a));
}
__device__ __forceinline__ void ldsm_x4t(uint32_t* r, uint32_t a) {
    asm volatile("ldmatrix.sync.aligned.m8n8.x4.trans.shared.b16 {%0,%1,%2,%3}, [%4];"
        : "=r"(r[0]), "=r"(r[1]), "=r"(r[2]), "=r"(r[3]) : "r"(a));
}
__device__ __forceinline__ void ldsm_x2(uint32_t* r, uint32_t a) {
    asm volatile("ldmatrix.sync.aligned.m8n8.x2.shared.b16 {%0,%1}, [%2];"
        : "=r"(r[0]), "=r"(r[1]) : "r"(a));
}
__device__ __forceinline__ void ldsm_x2t(uint32_t* r, uint32_t a) {
    asm volatile("ldmatrix.sync.aligned.m8n8.x2.trans.shared.b16 {%0,%1}, [%2];"
        : "=r"(r[0]), "=r"(r[1]) : "r"(a));
}
__device__ __forceinline__ void mma_f16(float* d, const uint32_t* a, const uint32_t* b) {
    asm volatile("mma.sync.aligned.m16n8k16.row.col.f32.f16.f16.f32 "
        "{%0,%1,%2,%3}, {%4,%5,%6,%7}, {%8,%9}, {%0,%1,%2,%3};"
        : "+f"(d[0]), "+f"(d[1]), "+f"(d[2]), "+f"(d[3])
        : "r"(a[0]), "r"(a[1]), "r"(a[2]), "r"(a[3]), "r"(b[0]), "r"(b[1]));
}

__device__ __forceinline__ float gelu_exact(float v) {
    return 0.5f * v * (1.0f + erff(v * 0.7071067811865476f));
}

// ---------------- init: pack bias, init out=b2, zero den ----------------
__global__ void __launch_bounds__(256) init_kernel(const float* __restrict__ bq,
                                                   const float* __restrict__ bk,
                                                   const float* __restrict__ bv,
                                                   const float* __restrict__ b2,
                                                   float* __restrict__ out)
{
    int i = blockIdx.x * 256 + threadIdx.x;
    if (i < 1024)      g_biasP[i] = bq[i];
    else if (i < 2048) g_biasP[i] = bk[i - 1024];
    else if (i < 3072) g_biasP[i] = bv[i - 2048];
    if (i < ML_) out[i] = b2[0];
    if (i < BH_ * L_) g_den[i] = 0.0f;
}

// ---------------- conversion kernels ----------------
__global__ void __launch_bounds__(256) split_kernel(const float* __restrict__ in,
                                                    __half* __restrict__ hi,
                                                    __half* __restrict__ lo)
{
    size_t i = (size_t)blockIdx.x * 1024 + threadIdx.x * 4;
    float4 v = *(const float4*)(in + i);
    __half h0 = __float2half_rn(v.x), h1 = __float2half_rn(v.y);
    __half h2 = __float2half_rn(v.z), h3 = __float2half_rn(v.w);
    __half l0 = __float2half_rn(v.x - __half2float(h0));
    __half l1 = __float2half_rn(v.y - __half2float(h1));
    __half l2 = __float2half_rn(v.z - __half2float(h2));
    __half l3 = __float2half_rn(v.w - __half2float(h3));
    ((__half2*)(hi + i))[0] = __halves2half2(h0, h1);
    ((__half2*)(hi + i))[1] = __halves2half2(h2, h3);
    ((__half2*)(lo + i))[0] = __halves2half2(l0, l1);
    ((__half2*)(lo + i))[1] = __halves2half2(l2, l3);
}

// W[K,N] fp32 -> Th[N,K] fp16 (hi only; 2-term GEMMs use single-precision B)
__global__ void __launch_bounds__(256) transpose_hi(const float* __restrict__ W,
                                                    __half* __restrict__ Th,
                                                    int K, int N)
{
    __shared__ float sm[32][33];
    const int n0 = blockIdx.x * 32, k0 = blockIdx.y * 32;
    const int tx = threadIdx.x & 31, ty = threadIdx.x >> 5;
    #pragma unroll
    for (int i = 0; i < 4; i++)
        sm[ty + i * 8][tx] = W[(size_t)(k0 + ty + i * 8) * N + n0 + tx];
    __syncthreads();
    #pragma unroll
    for (int i = 0; i < 4; i++) {
        float v = sm[tx][ty + i * 8];
        size_t o = (size_t)(n0 + ty + i * 8) * K + k0 + tx;
        Th[o] = __float2half_rn(v);
    }
}

// ---------------- mma.sync split-fp16 GEMM ----------------
// TERMS==2: C = (Ah+Al) @ Bh^T ; TERMS==1: C = Ah @ Bh^T
// MODE 0: C = A@B^T + bias -> split fp16 out (QKV projection)
// MODE 1: per-head E = exp(A@B^T / 8) -> single fp16 out + atomic denom (QK)
// MODE 2: y = gelu(A@B^T + bias); atomicAdd(out[row], y . W2)  (MLP + final)
#define G_STAGE(T) ((T) == 2 ? 49152 : 32768)
#define G_SMEM(T)  (2*G_STAGE(T) + 1024)

template<int MODE, int TERMS>
__global__ void __launch_bounds__(256) gemm_mma(
    const __half* __restrict__ Ahi, const __half* __restrict__ Alo,
    const __half* __restrict__ Bhi,
    const float* __restrict__ bias, const float* __restrict__ xw,
    __half* __restrict__ Chi, __half* __restrict__ Clo,
    float* __restrict__ aux,
    int lda, int ldb, int ldc, int K)
{
    extern __shared__ char smraw[];
    uint32_t smb = smem_u32(smraw);
    smb = (smb + 1023u) & ~1023u;

    const int tid = threadIdx.x, lane = tid & 31, warp = tid >> 5;
    const int wm = warp & 1, wn = warp >> 1;

    size_t aOff = 0, bOff = 0, eOff = 0;
    int bh = 0, bb = 0;
    if (MODE == 1) {
        bh = blockIdx.z; bb = bh >> 4;
        const int h = bh & 15;
        aOff = (size_t)bb * L_ * QKV_LD + 1024 + h * DH_;   // K vectors
        bOff = (size_t)bb * L_ * QKV_LD + h * DH_;          // Q vectors
        eOff = (size_t)bh * L_ * L_;
    }
    const int m0g = blockIdx.y * 128, n0g = blockIdx.x * 128;

    const char* gA[2] = { (const char*)(Ahi + aOff + (size_t)m0g * lda),
                          (const char*)(Alo + aOff + (size_t)m0g * lda) };
    const char* gB = (const char*)(Bhi + bOff + (size_t)n0g * ldb);

    const int nCh = K >> 6;
    float acc[4][4][4] = {};
    const int NARR = TERMS + 1;            // A arrays + B
    const uint32_t B_OFF = TERMS * 16384;  // B follows A arrays

    auto loadStage = [&](int st, int k0) {
        #pragma unroll
        for (int arr = 0; arr < NARR; arr++) {
            const char* base = (arr < TERMS) ? gA[arr] : gB;
            const int ld2 = ((arr < TERMS) ? lda : ldb) * 2;
            const uint32_t sb = smb + st * G_STAGE(TERMS) + arr * 16384;
            #pragma unroll
            for (int q = 0; q < 4; q++) {
                int id = tid + q * 256;
                int row = id >> 3, c16 = (id & 7) << 4;
                uint32_t sa = sb + row * 128 + (c16 ^ ((row & 7) << 4));
                cp16(sa, base + (size_t)row * ld2 + k0 * 2 + c16);
            }
        }
    };

    loadStage(0, 0);
    CP_COMMIT();

    for (int c = 0; c < nCh; c++) {
        const int st = c & 1;
        if (c + 1 < nCh) { loadStage(st ^ 1, (c + 1) << 6); CP_COMMIT(); CP_WAIT1(); }
        else             { CP_WAIT0(); }
        __syncthreads();

        const uint32_t sA = smb + st * G_STAGE(TERMS);
        const uint32_t sB = sA + B_OFF;
        #pragma unroll
        for (int s = 0; s < 4; s++) {
            const int kb = s * 32;
            uint32_t aH[4][4], aL[4][4], bH[4][2];
            const int lr = lane & 15, lc = lane >> 4;
            #pragma unroll
            for (int mt = 0; mt < 4; mt++) {
                int r = wm * 64 + mt * 16 + lr;
                int cb = kb + lc * 16;
                uint32_t ad = sA + r * 128 + (cb ^ ((r & 7) << 4));
                ldsm_x4(aH[mt], ad);
                if (TERMS == 2) ldsm_x4(aL[mt], ad + 16384);
            }
            const int br = lane & 7, bc = (lane >> 3) & 1;
            #pragma unroll
            for (int nt = 0; nt < 4; nt++) {
                int r = wn * 32 + nt * 8 + br;
                int cb = kb + bc * 16;
                uint32_t bd = sB + r * 128 + (cb ^ ((r & 7) << 4));
                ldsm_x2(bH[nt], bd);
            }
            #pragma unroll
            for (int mt = 0; mt < 4; mt++)
                #pragma unroll
                for (int nt = 0; nt < 4; nt++) {
                    mma_f16(acc[mt][nt], aH[mt], bH[nt]);
                    if (TERMS == 2) mma_f16(acc[mt][nt], aL[mt], bH[nt]);
                }
        }
        __syncthreads();
    }

    // ---- epilogues ----
    if (MODE == 0) {
        #pragma unroll
        for (int mt = 0; mt < 4; mt++) {
            #pragma unroll
            for (int nt = 0; nt < 4; nt++) {
                const int row = m0g + wm * 64 + mt * 16 + (lane >> 2);
                const int col = n0g + wn * 32 + nt * 8 + 2 * (lane & 3);
                float b0 = __ldg(bias + col), b1 = __ldg(bias + col + 1);
                float v0 = acc[mt][nt][0] + b0, v1 = acc[mt][nt][1] + b1;
                float v2 = acc[mt][nt][2] + b0, v3 = acc[mt][nt][3] + b1;
                __half h0 = __float2half_rn(v0), h1 = __float2half_rn(v1);
                __half h2 = __float2half_rn(v2), h3 = __float2half_rn(v3);
                *(__half2*)(Chi + (size_t)row * ldc + col)       = __halves2half2(h0, h1);
                *(__half2*)(Chi + (size_t)(row + 8) * ldc + col) = __halves2half2(h2, h3);
                *(__half2*)(Clo + (size_t)row * ldc + col) = __halves2half2(
                    __float2half_rn(v0 - __half2float(h0)),
                    __float2half_rn(v1 - __half2float(h1)));
                *(__half2*)(Clo + (size_t)(row + 8) * ldc + col) = __halves2half2(
                    __float2half_rn(v2 - __half2float(h2)),
                    __float2half_rn(v3 - __half2float(h3)));
            }
        }
    } else if (MODE == 1) {
        const float* xb = xw + bb * L_;
        float xc[4][2];
        #pragma unroll
        for (int nt = 0; nt < 4; nt++) {
            int col = n0g + wn * 32 + nt * 8 + 2 * (lane & 3);
            xc[nt][0] = __ldg(xb + col);
            xc[nt][1] = __ldg(xb + col + 1);
        }
        #pragma unroll
        for (int mt = 0; mt < 4; mt++) {
            const int rg = m0g + wm * 64 + mt * 16 + (lane >> 2);
            float p0 = 0.0f, p8 = 0.0f;
            #pragma unroll
            for (int nt = 0; nt < 4; nt++) {
                const int col = n0g + wn * 32 + nt * 8 + 2 * (lane & 3);
                float e0 = __expf(acc[mt][nt][0] * 0.125f);
                float e1 = __expf(acc[mt][nt][1] * 0.125f);
                float e2 = __expf(acc[mt][nt][2] * 0.125f);
                float e3 = __expf(acc[mt][nt][3] * 0.125f);
                *(__half2*)(Chi + eOff + (size_t)rg * ldc + col) =
                    __halves2half2(__float2half_rn(e0), __float2half_rn(e1));
                *(__half2*)(Chi + eOff + (size_t)(rg + 8) * ldc + col) =
                    __halves2half2(__float2half_rn(e2), __float2half_rn(e3));
                p0 += xc[nt][0] * e0 + xc[nt][1] * e1;
                p8 += xc[nt][0] * e2 + xc[nt][1] * e3;
            }
            p0 += __shfl_xor_sync(0xffffffffu, p0, 1);
            p0 += __shfl_xor_sync(0xffffffffu, p0, 2);
            p8 += __shfl_xor_sync(0xffffffffu, p8, 1);
            p8 += __shfl_xor_sync(0xffffffffu, p8, 2);
            if ((lane & 3) == 0) {
                atomicAdd(aux + (size_t)bh * L_ + rg,     p0);
                atomicAdd(aux + (size_t)bh * L_ + rg + 8, p8);
            }
        }
    } else {  // MODE == 2
        #pragma unroll
        for (int mt = 0; mt < 4; mt++) {
            const int row = m0g + wm * 64 + mt * 16 + (lane >> 2);
            float p0 = 0.0f, p8 = 0.0f;
            #pragma unroll
            for (int nt = 0; nt < 4; nt++) {
                const int col = n0g + wn * 32 + nt * 8 + 2 * (lane & 3);
                float b0 = __ldg(bias + col), b1 = __ldg(bias + col + 1);
                float w0 = __ldg(xw + col),  w1 = __ldg(xw + col + 1);
                float v0 = gelu_exact(acc[mt][nt][0] + b0);
                float v1 = gelu_exact(acc[mt][nt][1] + b1);
                float v2 = gelu_exact(acc[mt][nt][2] + b0);
                float v3 = gelu_exact(acc[mt][nt][3] + b1);
                p0 += v0 * w0 + v1 * w1;
                p8 += v2 * w0 + v3 * w1;
            }
            p0 += __shfl_xor_sync(0xffffffffu, p0, 1);
            p0 += __shfl_xor_sync(0xffffffffu, p0, 2);
            p8 += __shfl_xor_sync(0xffffffffu, p8, 1);
            p8 += __shfl_xor_sync(0xffffffffu, p8, 2);
            if ((lane & 3) == 0) {
                atomicAdd(aux + row,     p0);
                atomicAdd(aux + row + 8, p8);
            }
        }
    }
}

// ---------------- U kernel: U[bh][j][d] = x_j * V[b,j,h,d] / den[bh][j] (fp16) ----------------
__global__ void __launch_bounds__(256) u_kernel(const float* __restrict__ x)
{
    int gid = blockIdx.x * 256 + threadIdx.x;
    int d = gid & 63;
    int row = gid >> 6;                          // bh*L + j
    int bh = row >> 11, j = row & (L_ - 1);
    int b = bh >> 4, h = bh & 15;
    float den = g_den[row];
    size_t vo = ((size_t)b * L_ + j) * QKV_LD + 2048 + h * DH_ + d;
    float v = __half2float(g_QKVhi[vo]) + __half2float(g_QKVlo[vo]);
    float u = __ldg(x + b * L_ + j) * v / den;
    g_Uh[(size_t)row * DH_ + d] = __float2half_rn(u);
}

// ---------------- attention output: O[i,d] = x_i * sum_j E[j,i]*U[j,d] ----------------
// single-term fp16 E and U; O stored hi-only (MLP is 1-term)
#define AT_STAGE 24576  /* Eh 16K | Uh 8K */
#define AT_SMEM  (2*AT_STAGE + 1024)

__global__ void __launch_bounds__(256) attn_mma(const float* __restrict__ x)
{
    extern __shared__ char smraw[];
    uint32_t smb = smem_u32(smraw);
    smb = (smb + 1023u) & ~1023u;

    const int tid = threadIdx.x, lane = tid & 31, warp = tid >> 5;
    const int wi = warp & 3, wd = warp >> 2;     // warp tile: 32 i x 32 d
    const int bh = blockIdx.y, b = bh >> 4, h = bh & 15;
    const int i0 = blockIdx.x * 128;

    const char* Ehb = (const char*)(g_Ehi + (size_t)bh * L_ * L_);
    const char* Uhb = (const char*)(g_Uh + (size_t)bh * L_ * DH_);

    float acc[2][4][4] = {};

    auto loadStage = [&](int st, int j0) {
        const uint32_t sb = smb + st * AT_STAGE;
        #pragma unroll
        for (int q = 0; q < 4; q++) {
            int id = tid + q * 256;
            int row = id >> 4, c16 = (id & 15) << 4;
            uint32_t soff = row * 256 + (c16 ^ ((row & 7) << 4));
            size_t go = (size_t)(j0 + row) * (L_ * 2) + (size_t)i0 * 2 + c16;
            cp16(sb + soff, Ehb + go);
        }
        #pragma unroll
        for (int q = 0; q < 2; q++) {
            int id = tid + q * 256;
            int row = id >> 3, c16 = (id & 7) << 4;
            uint32_t uoff = row * 128 + (c16 ^ ((row & 7) << 4));
            cp16(sb + 16384 + uoff, Uhb + (size_t)(j0 + row) * 128 + c16);
        }
    };

    loadStage(0, 0);
    CP_COMMIT();

    for (int c = 0; c < L_ / 64; c++) {
        const int st = c & 1;
        if (c + 1 < L_ / 64) { loadStage(st ^ 1, (c + 1) * 64); CP_COMMIT(); CP_WAIT1(); }
        else                 { CP_WAIT0(); }
        __syncthreads();

        const uint32_t sb = smb + st * AT_STAGE;
        #pragma unroll
        for (int s = 0; s < 4; s++) {
            const int k0 = s * 16;
            uint32_t eH[2][4], uH[4][2];
            {
                const int r = k0 + (lane & 7) + ((lane >> 4) << 3);
                const int cbl = (((lane >> 3) & 1) << 4);
                #pragma unroll
                for (int mt = 0; mt < 2; mt++) {
                    int cb = (wi * 32 + mt * 16) * 2 + cbl;
                    uint32_t ad = sb + r * 256 + (cb ^ ((r & 7) << 4));
                    ldsm_x4t(eH[mt], ad);
                }
            }
            {
                const int r = k0 + (lane & 7) + (((lane >> 3) & 1) << 3);
                #pragma unroll
                for (int nt = 0; nt < 4; nt++) {
                    int cb = (wd * 32 + nt * 8) * 2;
                    uint32_t ud = sb + 16384 + r * 128 + (cb ^ ((r & 7) << 4));
                    ldsm_x2t(uH[nt], ud);
                }
            }
            #pragma unroll
            for (int mt = 0; mt < 2; mt++)
                #pragma unroll
                for (int nt = 0; nt < 4; nt++)
                    mma_f16(acc[mt][nt], eH[mt], uH[nt]);
        }
        __syncthreads();
    }

    // epilogue: O fp16 hi-only into g_Ahi [ML][E]
    #pragma unroll
    for (int mt = 0; mt < 2; mt++) {
        #pragma unroll
        for (int nt = 0; nt < 4; nt++) {
            const int row = i0 + wi * 32 + mt * 16 + (lane >> 2);
            const int col = h * DH_ + wd * 32 + nt * 8 + 2 * (lane & 3);
            float x0 = __ldg(x + b * L_ + row);
            float x1 = __ldg(x + b * L_ + row + 8);
            size_t r0 = ((size_t)b * L_ + row) * E_ + col;
            size_t r8 = ((size_t)b * L_ + row + 8) * E_ + col;
            *(__half2*)(g_Ahi + r0) = __halves2half2(
                __float2half_rn(acc[mt][nt][0] * x0),
                __float2half_rn(acc[mt][nt][1] * x0));
            *(__half2*)(g_Ahi + r8) = __halves2half2(
                __float2half_rn(acc[mt][nt][2] * x1),
                __float2half_rn(acc[mt][nt][3] * x1));
        }
    }
}

// ---------------- launch ----------------
extern "C" void kernel_launch(void* const* d_in, const int* in_sizes, int n_in,
                              void* d_out, int out_size)
{
    (void)in_sizes; (void)n_in; (void)out_size;
    const float* x  = (const float*)d_in[0];
    const float* z  = (const float*)d_in[1];
    const float* Wq = (const float*)d_in[2];
    const float* bq = (const float*)d_in[3];
    const float* Wk = (const float*)d_in[4];
    const float* bk = (const float*)d_in[5];
    const float* Wv = (const float*)d_in[6];
    const float* bv = (const float*)d_in[7];
    const float* W1 = (const float*)d_in[8];
    const float* b1 = (const float*)d_in[9];
    const float* W2 = (const float*)d_in[10];
    const float* b2 = (const float*)d_in[11];
    float* out = (float*)d_out;

    __half *pAhi, *pAlo, *pBhi, *pQKVhi, *pQKVlo, *pEhi;
    float *pDen, *pBiasP;
    cudaGetSymbolAddress((void**)&pAhi, g_Ahi);
    cudaGetSymbolAddress((void**)&pAlo, g_Alo);
    cudaGetSymbolAddress((void**)&pBhi, g_Bthi);
    cudaGetSymbolAddress((void**)&pQKVhi, g_QKVhi);
    cudaGetSymbolAddress((void**)&pQKVlo, g_QKVlo);
    cudaGetSymbolAddress((void**)&pEhi, g_Ehi);
    cudaGetSymbolAddress((void**)&pDen, g_den);
    cudaGetSymbolAddress((void**)&pBiasP, g_biasP);

    cudaFuncSetAttribute(gemm_mma<0, 2>, cudaFuncAttributeMaxDynamicSharedMemorySize, G_SMEM(2));
    cudaFuncSetAttribute(gemm_mma<1, 2>, cudaFuncAttributeMaxDynamicSharedMemorySize, G_SMEM(2));
    cudaFuncSetAttribute(gemm_mma<2, 1>, cudaFuncAttributeMaxDynamicSharedMemorySize, G_SMEM(1));
    cudaFuncSetAttribute(attn_mma, cudaFuncAttributeMaxDynamicSharedMemorySize, AT_SMEM);

    const size_t nZ = (size_t)ML_ * E_;

    // init: packed bias, out = b2, den = 0
    init_kernel<<<256, 256>>>(bq, bk, bv, b2, out);

    // split z (2-term A operand for QKV)
    split_kernel<<<nZ / 1024, 256>>>(z, pAhi, pAlo);

    // pack transposed QKV weights (hi only — 2-term uses single-precision B)
    dim3 gT(E_ / 32, E_ / 32);
    transpose_hi<<<gT, 256>>>(Wq, pBhi,                   E_, E_);
    transpose_hi<<<gT, 256>>>(Wk, pBhi + (size_t)E_*E_,   E_, E_);
    transpose_hi<<<gT, 256>>>(Wv, pBhi + (size_t)2*E_*E_, E_, E_);

    // fused QKV projection -> split fp16 [ML][3072]  (2-term)
    gemm_mma<0, 2><<<dim3(QKV_LD / 128, ML_ / 128), 256, G_SMEM(2)>>>(
        pAhi, pAlo, pBhi, pBiasP, nullptr, pQKVhi, pQKVlo, nullptr,
        E_, E_, QKV_LD, E_);

    // QK: E = exp(K_j . Q_i / 8) single fp16 + atomic denom  (2-term)
    gemm_mma<1, 2><<<dim3(L_ / 128, L_ / 128, BH_), 256, G_SMEM(2)>>>(
        pQKVhi, pQKVlo, pQKVhi, nullptr, x, pEhi, nullptr, pDen,
        QKV_LD, QKV_LD, L_, DH_);

    // U = x_j * V / den, fp16
    u_kernel<<<(BH_ * L_ * DH_) / 256, 256>>>(x);

    // attention output -> O fp16 (hi only, into g_Ahi)  (1-term)
    attn_mma<<<dim3(L_ / 128, BH_), 256, AT_SMEM>>>(x);

    // W1 transpose (hi only)
    transpose_hi<<<dim3(HID_ / 32, E_ / 32), 256>>>(W1, pBhi, E_, HID_);

    // MLP1 + fused W2 reduction -> out (atomic, 1-term)
    gemm_mma<2, 1><<<dim3(HID_ / 128, ML_ / 128), 256, G_SMEM(1)>>>(
        pAhi, nullptr, pBhi, b1, W2, nullptr, nullptr, out,
        E_, E_, 0, E_);
}

// round 12
// speedup vs baseline: 5.9871x; 1.1429x over previous
#include <cuda_runtime.h>
#include <cuda_fp16.h>
#include <math.h>
#include <stdint.h>

#define B_   2
#define L_   2048
#define E_   1024
#define H_   16
#define DH_  64
#define HID_ 4096
#define BH_  (B_*H_)    /* 32   */
#define ML_  (B_*L_)    /* 4096 */
#define QKV_LD 3072

// ---------------- scratch (device globals; no allocation allowed) ----------------
__device__ __align__(128) __half g_Ehi[(size_t)BH_ * L_ * L_];   // [bh][j][i] = exp(S^T), fp16
__device__ __align__(128) float  g_den[(size_t)BH_ * L_];

__device__ __align__(128) __half g_Ahi [(size_t)ML_ * E_];       // z hi, later O
__device__ __align__(128) __half g_Bthi[(size_t)HID_ * E_];      // transposed weights [N,K]
__device__ __align__(128) __half g_QKVhi[(size_t)ML_ * QKV_LD]; // [ML][Q|K|V] hi
__device__ __align__(128) __half g_QKVlo[(size_t)ML_ * QKV_LD]; // lo (for 2-term QK)
__device__ __align__(128) __half g_Uh  [(size_t)BH_ * L_ * DH_];
__device__ __align__(128) float  g_biasP[QKV_LD];

// ---------------- ptx helpers (sm_80-compatible PTX only) ----------------
__device__ __forceinline__ uint32_t smem_u32(const void* p) {
    uint32_t a;
    asm("{ .reg .u64 t; cvta.to.shared.u64 t, %1; cvt.u32.u64 %0, t; }" : "=r"(a) : "l"(p));
    return a;
}
__device__ __forceinline__ void cp16(uint32_t saddr, const void* g) {
    asm volatile("cp.async.cg.shared.global [%0], [%1], 16;" :: "r"(saddr), "l"(g));
}
#define CP_COMMIT() asm volatile("cp.async.commit_group;" ::: "memory")
#define CP_WAIT0()  asm volatile("cp.async.wait_group 0;" ::: "memory")
#define CP_WAIT1()  asm volatile("cp.async.wait_group 1;" ::: "memory")

__device__ __forceinline__ void ldsm_x4(uint32_t* r, uint32_t a) {
    asm volatile("ldmatrix.sync.aligned.m8n8.x4.shared.b16 {%0,%1,%2,%3}, [%4];"
        : "=r"(r[0]), "=r"(r[1]), "=r"(r[2]), "=r"(r[3]) : "r"(a));
}
__device__ __forceinline__ void ldsm_x4t(uint32_t* r, uint32_t a) {
    asm volatile("ldmatrix.sync.aligned.m8n8.x4.trans.shared.b16 {%0,%1,%2,%3}, [%4];"
        : "=r"(r[0]), "=r"(r[1]), "=r"(r[2]), "=r"(r[3]) : "r"(a));
}
__device__ __forceinline__ void ldsm_x2(uint32_t* r, uint32_t a) {
    asm volatile("ldmatrix.sync.aligned.m8n8.x2.shared.b16 {%0,%1}, [%2];"
        : "=r"(r[0]), "=r"(r[1]) : "r"(a));
}
__device__ __forceinline__ void ldsm_x2t(uint32_t* r, uint32_t a) {
    asm volatile("ldmatrix.sync.aligned.m8n8.x2.trans.shared.b16 {%0,%1}, [%2];"
        : "=r"(r[0]), "=r"(r[1]) : "r"(a));
}
__device__ __forceinline__ void mma_f16(float* d, const uint32_t* a, const uint32_t* b) {
    asm volatile("mma.sync.aligned.m16n8k16.row.col.f32.f16.f16.f32 "
        "{%0,%1,%2,%3}, {%4,%5,%6,%7}, {%8,%9}, {%0,%1,%2,%3};"
        : "+f"(d[0]), "+f"(d[1]), "+f"(d[2]), "+f"(d[3])
        : "r"(a[0]), "r"(a[1]), "r"(a[2]), "r"(a[3]), "r"(b[0]), "r"(b[1]));
}

__device__ __forceinline__ float gelu_exact(float v) {
    return 0.5f * v * (1.0f + erff(v * 0.7071067811865476f));
}

// ---------------- init: pack bias, init out=b2, zero den ----------------
__global__ void __launch_bounds__(256) init_kernel(const float* __restrict__ bq,
                                                   const float* __restrict__ bk,
                                                   const float* __restrict__ bv,
                                                   const float* __restrict__ b2,
                                                   float* __restrict__ out)
{
    int i = blockIdx.x * 256 + threadIdx.x;
    if (i < 1024)      g_biasP[i] = bq[i];
    else if (i < 2048) g_biasP[i] = bk[i - 1024];
    else if (i < 3072) g_biasP[i] = bv[i - 2048];
    if (i < ML_) out[i] = b2[0];
    if (i < BH_ * L_) g_den[i] = 0.0f;
}

// ---------------- conversion kernels ----------------
// fp32 -> fp16 (hi only)
__global__ void __launch_bounds__(256) convert_hi(const float* __restrict__ in,
                                                  __half* __restrict__ hi)
{
    size_t i = (size_t)blockIdx.x * 1024 + threadIdx.x * 4;
    float4 v = *(const float4*)(in + i);
    ((__half2*)(hi + i))[0] = __floats2half2_rn(v.x, v.y);
    ((__half2*)(hi + i))[1] = __floats2half2_rn(v.z, v.w);
}

// Wq/Wk/Wv fp32 [K,N] -> packed Th[N,K] fp16 (z selects matrix)
__global__ void __launch_bounds__(256) transpose_qkv(const float* __restrict__ Wq,
                                                     const float* __restrict__ Wk,
                                                     const float* __restrict__ Wv,
                                                     __half* __restrict__ Th)
{
    __shared__ float sm[32][33];
    const float* W = (blockIdx.z == 0) ? Wq : (blockIdx.z == 1) ? Wk : Wv;
    __half* T = Th + (size_t)blockIdx.z * E_ * E_;
    const int n0 = blockIdx.x * 32, k0 = blockIdx.y * 32;
    const int tx = threadIdx.x & 31, ty = threadIdx.x >> 5;
    #pragma unroll
    for (int i = 0; i < 4; i++)
        sm[ty + i * 8][tx] = W[(size_t)(k0 + ty + i * 8) * E_ + n0 + tx];
    __syncthreads();
    #pragma unroll
    for (int i = 0; i < 4; i++) {
        float v = sm[tx][ty + i * 8];
        T[(size_t)(n0 + ty + i * 8) * E_ + k0 + tx] = __float2half_rn(v);
    }
}

// W[K,N] fp32 -> Th[N,K] fp16
__global__ void __launch_bounds__(256) transpose_hi(const float* __restrict__ W,
                                                    __half* __restrict__ Th,
                                                    int K, int N)
{
    __shared__ float sm[32][33];
    const int n0 = blockIdx.x * 32, k0 = blockIdx.y * 32;
    const int tx = threadIdx.x & 31, ty = threadIdx.x >> 5;
    #pragma unroll
    for (int i = 0; i < 4; i++)
        sm[ty + i * 8][tx] = W[(size_t)(k0 + ty + i * 8) * N + n0 + tx];
    __syncthreads();
    #pragma unroll
    for (int i = 0; i < 4; i++) {
        float v = sm[tx][ty + i * 8];
        Th[(size_t)(n0 + ty + i * 8) * K + k0 + tx] = __float2half_rn(v);
    }
}

// ---------------- mma.sync split-fp16 GEMM ----------------
// TERMS==2: C = (Ah+Al) @ Bh^T ; TERMS==1: C = Ah @ Bh^T
// MODE 0: C = A@B^T + bias -> split fp16 out (QKV projection)
// MODE 1: per-head E = exp(A@B^T / 8) -> single fp16 out + atomic denom (QK)
// MODE 2: y = gelu(A@B^T + bias); atomicAdd(out[row], y . W2)  (MLP + final)
#define G_STAGE(T) ((T) == 2 ? 49152 : 32768)
#define G_SMEM(T)  (2*G_STAGE(T) + 1024)

template<int MODE, int TERMS>
__global__ void __launch_bounds__(256) gemm_mma(
    const __half* __restrict__ Ahi, const __half* __restrict__ Alo,
    const __half* __restrict__ Bhi,
    const float* __restrict__ bias, const float* __restrict__ xw,
    __half* __restrict__ Chi, __half* __restrict__ Clo,
    float* __restrict__ aux,
    int lda, int ldb, int ldc, int K)
{
    extern __shared__ char smraw[];
    uint32_t smb = smem_u32(smraw);
    smb = (smb + 1023u) & ~1023u;

    const int tid = threadIdx.x, lane = tid & 31, warp = tid >> 5;
    const int wm = warp & 1, wn = warp >> 1;

    size_t aOff = 0, bOff = 0, eOff = 0;
    int bh = 0, bb = 0;
    if (MODE == 1) {
        bh = blockIdx.z; bb = bh >> 4;
        const int h = bh & 15;
        aOff = (size_t)bb * L_ * QKV_LD + 1024 + h * DH_;   // K vectors
        bOff = (size_t)bb * L_ * QKV_LD + h * DH_;          // Q vectors
        eOff = (size_t)bh * L_ * L_;
    }
    const int m0g = blockIdx.y * 128, n0g = blockIdx.x * 128;

    const char* gA[2] = { (const char*)(Ahi + aOff + (size_t)m0g * lda),
                          (const char*)(Alo + aOff + (size_t)m0g * lda) };
    const char* gB = (const char*)(Bhi + bOff + (size_t)n0g * ldb);

    const int nCh = K >> 6;
    float acc[4][4][4] = {};
    const int NARR = TERMS + 1;            // A arrays + B
    const uint32_t B_OFF = TERMS * 16384;  // B follows A arrays

    auto loadStage = [&](int st, int k0) {
        #pragma unroll
        for (int arr = 0; arr < NARR; arr++) {
            const char* base = (arr < TERMS) ? gA[arr] : gB;
            const int ld2 = ((arr < TERMS) ? lda : ldb) * 2;
            const uint32_t sb = smb + st * G_STAGE(TERMS) + arr * 16384;
            #pragma unroll
            for (int q = 0; q < 4; q++) {
                int id = tid + q * 256;
                int row = id >> 3, c16 = (id & 7) << 4;
                uint32_t sa = sb + row * 128 + (c16 ^ ((row & 7) << 4));
                cp16(sa, base + (size_t)row * ld2 + k0 * 2 + c16);
            }
        }
    };

    loadStage(0, 0);
    CP_COMMIT();

    for (int c = 0; c < nCh; c++) {
        const int st = c & 1;
        if (c + 1 < nCh) { loadStage(st ^ 1, (c + 1) << 6); CP_COMMIT(); CP_WAIT1(); }
        else             { CP_WAIT0(); }
        __syncthreads();

        const uint32_t sA = smb + st * G_STAGE(TERMS);
        const uint32_t sB = sA + B_OFF;
        #pragma unroll
        for (int s = 0; s < 4; s++) {
            const int kb = s * 32;
            uint32_t aH[4][4], aL[4][4], bH[4][2];
            const int lr = lane & 15, lc = lane >> 4;
            #pragma unroll
            for (int mt = 0; mt < 4; mt++) {
                int r = wm * 64 + mt * 16 + lr;
                int cb = kb + lc * 16;
                uint32_t ad = sA + r * 128 + (cb ^ ((r & 7) << 4));
                ldsm_x4(aH[mt], ad);
                if (TERMS == 2) ldsm_x4(aL[mt], ad + 16384);
            }
            const int br = lane & 7, bc = (lane >> 3) & 1;
            #pragma unroll
            for (int nt = 0; nt < 4; nt++) {
                int r = wn * 32 + nt * 8 + br;
                int cb = kb + bc * 16;
                uint32_t bd = sB + r * 128 + (cb ^ ((r & 7) << 4));
                ldsm_x2(bH[nt], bd);
            }
            #pragma unroll
            for (int mt = 0; mt < 4; mt++)
                #pragma unroll
                for (int nt = 0; nt < 4; nt++) {
                    mma_f16(acc[mt][nt], aH[mt], bH[nt]);
                    if (TERMS == 2) mma_f16(acc[mt][nt], aL[mt], bH[nt]);
                }
        }
        __syncthreads();
    }

    // ---- epilogues ----
    if (MODE == 0) {
        #pragma unroll
        for (int mt = 0; mt < 4; mt++) {
            #pragma unroll
            for (int nt = 0; nt < 4; nt++) {
                const int row = m0g + wm * 64 + mt * 16 + (lane >> 2);
                const int col = n0g + wn * 32 + nt * 8 + 2 * (lane & 3);
                float b0 = __ldg(bias + col), b1 = __ldg(bias + col + 1);
                float v0 = acc[mt][nt][0] + b0, v1 = acc[mt][nt][1] + b1;
                float v2 = acc[mt][nt][2] + b0, v3 = acc[mt][nt][3] + b1;
                __half h0 = __float2half_rn(v0), h1 = __float2half_rn(v1);
                __half h2 = __float2half_rn(v2), h3 = __float2half_rn(v3);
                *(__half2*)(Chi + (size_t)row * ldc + col)       = __halves2half2(h0, h1);
                *(__half2*)(Chi + (size_t)(row + 8) * ldc + col) = __halves2half2(h2, h3);
                *(__half2*)(Clo + (size_t)row * ldc + col) = __halves2half2(
                    __float2half_rn(v0 - __half2float(h0)),
                    __float2half_rn(v1 - __half2float(h1)));
                *(__half2*)(Clo + (size_t)(row + 8) * ldc + col) = __halves2half2(
                    __float2half_rn(v2 - __half2float(h2)),
                    __float2half_rn(v3 - __half2float(h3)));
            }
        }
    } else if (MODE == 1) {
        const float* xb = xw + bb * L_;
        float xc[4][2];
        #pragma unroll
        for (int nt = 0; nt < 4; nt++) {
            int col = n0g + wn * 32 + nt * 8 + 2 * (lane & 3);
            xc[nt][0] = __ldg(xb + col);
            xc[nt][1] = __ldg(xb + col + 1);
        }
        #pragma unroll
        for (int mt = 0; mt < 4; mt++) {
            const int rg = m0g + wm * 64 + mt * 16 + (lane >> 2);
            float p0 = 0.0f, p8 = 0.0f;
            #pragma unroll
            for (int nt = 0; nt < 4; nt++) {
                const int col = n0g + wn * 32 + nt * 8 + 2 * (lane & 3);
                float e0 = __expf(acc[mt][nt][0] * 0.125f);
                float e1 = __expf(acc[mt][nt][1] * 0.125f);
                float e2 = __expf(acc[mt][nt][2] * 0.125f);
                float e3 = __expf(acc[mt][nt][3] * 0.125f);
                *(__half2*)(Chi + eOff + (size_t)rg * ldc + col) =
                    __halves2half2(__float2half_rn(e0), __float2half_rn(e1));
                *(__half2*)(Chi + eOff + (size_t)(rg + 8) * ldc + col) =
                    __halves2half2(__float2half_rn(e2), __float2half_rn(e3));
                p0 += xc[nt][0] * e0 + xc[nt][1] * e1;
                p8 += xc[nt][0] * e2 + xc[nt][1] * e3;
            }
            p0 += __shfl_xor_sync(0xffffffffu, p0, 1);
            p0 += __shfl_xor_sync(0xffffffffu, p0, 2);
            p8 += __shfl_xor_sync(0xffffffffu, p8, 1);
            p8 += __shfl_xor_sync(0xffffffffu, p8, 2);
            if ((lane & 3) == 0) {
                atomicAdd(aux + (size_t)bh * L_ + rg,     p0);
                atomicAdd(aux + (size_t)bh * L_ + rg + 8, p8);
            }
        }
    } else {  // MODE == 2
        #pragma unroll
        for (int mt = 0; mt < 4; mt++) {
            const int row = m0g + wm * 64 + mt * 16 + (lane >> 2);
            float p0 = 0.0f, p8 = 0.0f;
            #pragma unroll
            for (int nt = 0; nt < 4; nt++) {
                const int col = n0g + wn * 32 + nt * 8 + 2 * (lane & 3);
                float b0 = __ldg(bias + col), b1 = __ldg(bias + col + 1);
                float w0 = __ldg(xw + col),  w1 = __ldg(xw + col + 1);
                float v0 = gelu_exact(acc[mt][nt][0] + b0);
                float v1 = gelu_exact(acc[mt][nt][1] + b1);
                float v2 = gelu_exact(acc[mt][nt][2] + b0);
                float v3 = gelu_exact(acc[mt][nt][3] + b1);
                p0 += v0 * w0 + v1 * w1;
                p8 += v2 * w0 + v3 * w1;
            }
            p0 += __shfl_xor_sync(0xffffffffu, p0, 1);
            p0 += __shfl_xor_sync(0xffffffffu, p0, 2);
            p8 += __shfl_xor_sync(0xffffffffu, p8, 1);
            p8 += __shfl_xor_sync(0xffffffffu, p8, 2);
            if ((lane & 3) == 0) {
                atomicAdd(aux + row,     p0);
                atomicAdd(aux + row + 8, p8);
            }
        }
    }
}

// ---------------- U kernel: U[bh][j][d] = x_j * V[b,j,h,d] / den[bh][j] (fp16) ----------------
__global__ void __launch_bounds__(256) u_kernel(const float* __restrict__ x)
{
    int gid = blockIdx.x * 256 + threadIdx.x;
    int d = gid & 63;
    int row = gid >> 6;                          // bh*L + j
    int bh = row >> 11, j = row & (L_ - 1);
    int b = bh >> 4, h = bh & 15;
    float den = g_den[row];
    size_t vo = ((size_t)b * L_ + j) * QKV_LD + 2048 + h * DH_ + d;
    float v = __half2float(g_QKVhi[vo]) + __half2float(g_QKVlo[vo]);
    float u = __ldg(x + b * L_ + j) * v / den;
    g_Uh[(size_t)row * DH_ + d] = __float2half_rn(u);
}

// ---------------- attention output: O[i,d] = x_i * sum_j E[j,i]*U[j,d] ----------------
// single-term fp16 E and U; O stored hi-only (MLP is 1-term)
#define AT_STAGE 24576  /* Eh 16K | Uh 8K */
#define AT_SMEM  (2*AT_STAGE + 1024)

__global__ void __launch_bounds__(256) attn_mma(const float* __restrict__ x)
{
    extern __shared__ char smraw[];
    uint32_t smb = smem_u32(smraw);
    smb = (smb + 1023u) & ~1023u;

    const int tid = threadIdx.x, lane = tid & 31, warp = tid >> 5;
    const int wi = warp & 3, wd = warp >> 2;     // warp tile: 32 i x 32 d
    const int bh = blockIdx.y, b = bh >> 4, h = bh & 15;
    const int i0 = blockIdx.x * 128;

    const char* Ehb = (const char*)(g_Ehi + (size_t)bh * L_ * L_);
    const char* Uhb = (const char*)(g_Uh + (size_t)bh * L_ * DH_);

    float acc[2][4][4] = {};

    auto loadStage = [&](int st, int j0) {
        const uint32_t sb = smb + st * AT_STAGE;
        #pragma unroll
        for (int q = 0; q < 4; q++) {
            int id = tid + q * 256;
            int row = id >> 4, c16 = (id & 15) << 4;
            uint32_t soff = row * 256 + (c16 ^ ((row & 7) << 4));
            size_t go = (size_t)(j0 + row) * (L_ * 2) + (size_t)i0 * 2 + c16;
            cp16(sb + soff, Ehb + go);
        }
        #pragma unroll
        for (int q = 0; q < 2; q++) {
            int id = tid + q * 256;
            int row = id >> 3, c16 = (id & 7) << 4;
            uint32_t uoff = row * 128 + (c16 ^ ((row & 7) << 4));
            cp16(sb + 16384 + uoff, Uhb + (size_t)(j0 + row) * 128 + c16);
        }
    };

    loadStage(0, 0);
    CP_COMMIT();

    for (int c = 0; c < L_ / 64; c++) {
        const int st = c & 1;
        if (c + 1 < L_ / 64) { loadStage(st ^ 1, (c + 1) * 64); CP_COMMIT(); CP_WAIT1(); }
        else                 { CP_WAIT0(); }
        __syncthreads();

        const uint32_t sb = smb + st * AT_STAGE;
        #pragma unroll
        for (int s = 0; s < 4; s++) {
            const int k0 = s * 16;
            uint32_t eH[2][4], uH[4][2];
            {
                const int r = k0 + (lane & 7) + ((lane >> 4) << 3);
                const int cbl = (((lane >> 3) & 1) << 4);
                #pragma unroll
                for (int mt = 0; mt < 2; mt++) {
                    int cb = (wi * 32 + mt * 16) * 2 + cbl;
                    uint32_t ad = sb + r * 256 + (cb ^ ((r & 7) << 4));
                    ldsm_x4t(eH[mt], ad);
                }
            }
            {
                const int r = k0 + (lane & 7) + (((lane >> 3) & 1) << 3);
                #pragma unroll
                for (int nt = 0; nt < 4; nt++) {
                    int cb = (wd * 32 + nt * 8) * 2;
                    uint32_t ud = sb + 16384 + r * 128 + (cb ^ ((r & 7) << 4));
                    ldsm_x2t(uH[nt], ud);
                }
            }
            #pragma unroll
            for (int mt = 0; mt < 2; mt++)
                #pragma unroll
                for (int nt = 0; nt < 4; nt++)
                    mma_f16(acc[mt][nt], eH[mt], uH[nt]);
        }
        __syncthreads();
    }

    // epilogue: O fp16 hi-only into g_Ahi [ML][E]
    #pragma unroll
    for (int mt = 0; mt < 2; mt++) {
        #pragma unroll
        for (int nt = 0; nt < 4; nt++) {
            const int row = i0 + wi * 32 + mt * 16 + (lane >> 2);
            const int col = h * DH_ + wd * 32 + nt * 8 + 2 * (lane & 3);
            float x0 = __ldg(x + b * L_ + row);
            float x1 = __ldg(x + b * L_ + row + 8);
            size_t r0 = ((size_t)b * L_ + row) * E_ + col;
            size_t r8 = ((size_t)b * L_ + row + 8) * E_ + col;
            *(__half2*)(g_Ahi + r0) = __halves2half2(
                __float2half_rn(acc[mt][nt][0] * x0),
                __float2half_rn(acc[mt][nt][1] * x0));
            *(__half2*)(g_Ahi + r8) = __halves2half2(
                __float2half_rn(acc[mt][nt][2] * x1),
                __float2half_rn(acc[mt][nt][3] * x1));
        }
    }
}

// ---------------- launch ----------------
extern "C" void kernel_launch(void* const* d_in, const int* in_sizes, int n_in,
                              void* d_out, int out_size)
{
    (void)in_sizes; (void)n_in; (void)out_size;
    const float* x  = (const float*)d_in[0];
    const float* z  = (const float*)d_in[1];
    const float* Wq = (const float*)d_in[2];
    const float* bq = (const float*)d_in[3];
    const float* Wk = (const float*)d_in[4];
    const float* bk = (const float*)d_in[5];
    const float* Wv = (const float*)d_in[6];
    const float* bv = (const float*)d_in[7];
    const float* W1 = (const float*)d_in[8];
    const float* b1 = (const float*)d_in[9];
    const float* W2 = (const float*)d_in[10];
    const float* b2 = (const float*)d_in[11];
    float* out = (float*)d_out;

    __half *pAhi, *pBhi, *pQKVhi, *pQKVlo, *pEhi;
    float *pDen, *pBiasP;
    cudaGetSymbolAddress((void**)&pAhi, g_Ahi);
    cudaGetSymbolAddress((void**)&pBhi, g_Bthi);
    cudaGetSymbolAddress((void**)&pQKVhi, g_QKVhi);
    cudaGetSymbolAddress((void**)&pQKVlo, g_QKVlo);
    cudaGetSymbolAddress((void**)&pEhi, g_Ehi);
    cudaGetSymbolAddress((void**)&pDen, g_den);
    cudaGetSymbolAddress((void**)&pBiasP, g_biasP);

    cudaFuncSetAttribute(gemm_mma<0, 1>, cudaFuncAttributeMaxDynamicSharedMemorySize, G_SMEM(1));
    cudaFuncSetAttribute(gemm_mma<1, 2>, cudaFuncAttributeMaxDynamicSharedMemorySize, G_SMEM(2));
    cudaFuncSetAttribute(gemm_mma<2, 1>, cudaFuncAttributeMaxDynamicSharedMemorySize, G_SMEM(1));
    cudaFuncSetAttribute(attn_mma, cudaFuncAttributeMaxDynamicSharedMemorySize, AT_SMEM);

    const size_t nZ = (size_t)ML_ * E_;

    // init: packed bias, out = b2, den = 0
    init_kernel<<<256, 256>>>(bq, bk, bv, b2, out);

    // convert z -> fp16 hi (1-term A operand for QKV)
    convert_hi<<<nZ / 1024, 256>>>(z, pAhi);

    // pack transposed QKV weights (fused, hi only)
    transpose_qkv<<<dim3(E_ / 32, E_ / 32, 3), 256>>>(Wq, Wk, Wv, pBhi);

    // fused QKV projection -> split fp16 [ML][3072]  (1-term GEMM, split output)
    gemm_mma<0, 1><<<dim3(QKV_LD / 128, ML_ / 128), 256, G_SMEM(1)>>>(
        pAhi, nullptr, pBhi, pBiasP, nullptr, pQKVhi, pQKVlo, nullptr,
        E_, E_, QKV_LD, E_);

    // QK: E = exp(K_j . Q_i / 8) single fp16 + atomic denom  (2-term)
    gemm_mma<1, 2><<<dim3(L_ / 128, L_ / 128, BH_), 256, G_SMEM(2)>>>(
        pQKVhi, pQKVlo, pQKVhi, nullptr, x, pEhi, nullptr, pDen,
        QKV_LD, QKV_LD, L_, DH_);

    // U = x_j * V / den, fp16
    u_kernel<<<(BH_ * L_ * DH_) / 256, 256>>>(x);

    // attention output -> O fp16 (hi only, into g_Ahi)  (1-term)
    attn_mma<<<dim3(L_ / 128, BH_), 256, AT_SMEM>>>(x);

    // W1 transpose (hi only)
    transpose_hi<<<dim3(HID_ / 32, E_ / 32), 256>>>(W1, pBhi, E_, HID_);

    // MLP1 + fused W2 reduction -> out (atomic, 1-term)
    gemm_mma<2, 1><<<dim3(HID_ / 128, ML_ / 128), 256, G_SMEM(1)>>>(
        pAhi, nullptr, pBhi, b1, W2, nullptr, nullptr, out,
        E_, E_, 0, E_);
}

// round 13
// speedup vs baseline: 6.4322x; 1.0743x over previous
#include <cuda_runtime.h>
#include <cuda_fp16.h>
#include <math.h>
#include <stdint.h>

#define B_   2
#define L_   2048
#define E_   1024
#define H_   16
#define DH_  64
#define HID_ 4096
#define BH_  (B_*H_)    /* 32   */
#define ML_  (B_*L_)    /* 4096 */
#define QKV_LD 3072

// ---------------- scratch (device globals; no allocation allowed) ----------------
__device__ __align__(128) __half g_Ehi[(size_t)BH_ * L_ * L_];   // [bh][j][i] = exp(S^T), fp16
__device__ __align__(128) float  g_den[(size_t)BH_ * L_];

__device__ __align__(128) __half g_Ahi [(size_t)ML_ * E_];       // z hi, later O
__device__ __align__(128) __half g_Bthi[(size_t)HID_ * E_];      // transposed weights [N,K]
__device__ __align__(128) __half g_QKVhi[(size_t)ML_ * QKV_LD]; // [ML][Q|K|V] hi
__device__ __align__(128) __half g_Uh  [(size_t)BH_ * L_ * DH_];
__device__ __align__(128) float  g_biasP[QKV_LD];

// ---------------- ptx helpers (sm_80-compatible PTX only) ----------------
__device__ __forceinline__ uint32_t smem_u32(const void* p) {
    uint32_t a;
    asm("{ .reg .u64 t; cvta.to.shared.u64 t, %1; cvt.u32.u64 %0, t; }" : "=r"(a) : "l"(p));
    return a;
}
__device__ __forceinline__ void cp16(uint32_t saddr, const void* g) {
    asm volatile("cp.async.cg.shared.global [%0], [%1], 16;" :: "r"(saddr), "l"(g));
}
#define CP_COMMIT() asm volatile("cp.async.commit_group;" ::: "memory")
#define CP_WAIT0()  asm volatile("cp.async.wait_group 0;" ::: "memory")
#define CP_WAIT1()  asm volatile("cp.async.wait_group 1;" ::: "memory")

__device__ __forceinline__ void ldsm_x4(uint32_t* r, uint32_t a) {
    asm volatile("ldmatrix.sync.aligned.m8n8.x4.shared.b16 {%0,%1,%2,%3}, [%4];"
        : "=r"(r[0]), "=r"(r[1]), "=r"(r[2]), "=r"(r[3]) : "r"(a));
}
__device__ __forceinline__ void ldsm_x4t(uint32_t* r, uint32_t a) {
    asm volatile("ldmatrix.sync.aligned.m8n8.x4.trans.shared.b16 {%0,%1,%2,%3}, [%4];"
        : "=r"(r[0]), "=r"(r[1]), "=r"(r[2]), "=r"(r[3]) : "r"(a));
}
__device__ __forceinline__ void mma_f16(float* d, const uint32_t* a, const uint32_t* b) {
    asm volatile("mma.sync.aligned.m16n8k16.row.col.f32.f16.f16.f32 "
        "{%0,%1,%2,%3}, {%4,%5,%6,%7}, {%8,%9}, {%0,%1,%2,%3};"
        : "+f"(d[0]), "+f"(d[1]), "+f"(d[2]), "+f"(d[3])
        : "r"(a[0]), "r"(a[1]), "r"(a[2]), "r"(a[3]), "r"(b[0]), "r"(b[1]));
}

__device__ __forceinline__ float gelu_exact(float v) {
    return 0.5f * v * (1.0f + erff(v * 0.7071067811865476f));
}

// ---------------- init: pack bias, init out=b2, zero den ----------------
__global__ void __launch_bounds__(256) init_kernel(const float* __restrict__ bq,
                                                   const float* __restrict__ bk,
                                                   const float* __restrict__ bv,
                                                   const float* __restrict__ b2,
                                                   float* __restrict__ out)
{
    int i = blockIdx.x * 256 + threadIdx.x;
    if (i < 1024)      g_biasP[i] = bq[i];
    else if (i < 2048) g_biasP[i] = bk[i - 1024];
    else if (i < 3072) g_biasP[i] = bv[i - 2048];
    if (i < ML_) out[i] = b2[0];
    if (i < BH_ * L_) g_den[i] = 0.0f;
}

// ---------------- conversion kernels ----------------
__global__ void __launch_bounds__(256) convert_hi(const float* __restrict__ in,
                                                  __half* __restrict__ hi)
{
    size_t i = (size_t)blockIdx.x * 1024 + threadIdx.x * 4;
    float4 v = *(const float4*)(in + i);
    ((__half2*)(hi + i))[0] = __floats2half2_rn(v.x, v.y);
    ((__half2*)(hi + i))[1] = __floats2half2_rn(v.z, v.w);
}

// Wq/Wk/Wv fp32 [K,N] -> packed Th[N,K] fp16 (z selects matrix)
__global__ void __launch_bounds__(256) transpose_qkv(const float* __restrict__ Wq,
                                                     const float* __restrict__ Wk,
                                                     const float* __restrict__ Wv,
                                                     __half* __restrict__ Th)
{
    __shared__ float sm[32][33];
    const float* W = (blockIdx.z == 0) ? Wq : (blockIdx.z == 1) ? Wk : Wv;
    __half* T = Th + (size_t)blockIdx.z * E_ * E_;
    const int n0 = blockIdx.x * 32, k0 = blockIdx.y * 32;
    const int tx = threadIdx.x & 31, ty = threadIdx.x >> 5;
    #pragma unroll
    for (int i = 0; i < 4; i++)
        sm[ty + i * 8][tx] = W[(size_t)(k0 + ty + i * 8) * E_ + n0 + tx];
    __syncthreads();
    #pragma unroll
    for (int i = 0; i < 4; i++) {
        float v = sm[tx][ty + i * 8];
        T[(size_t)(n0 + ty + i * 8) * E_ + k0 + tx] = __float2half_rn(v);
    }
}

// W[K,N] fp32 -> Th[N,K] fp16
__global__ void __launch_bounds__(256) transpose_hi(const float* __restrict__ W,
                                                    __half* __restrict__ Th,
                                                    int K, int N)
{
    __shared__ float sm[32][33];
    const int n0 = blockIdx.x * 32, k0 = blockIdx.y * 32;
    const int tx = threadIdx.x & 31, ty = threadIdx.x >> 5;
    #pragma unroll
    for (int i = 0; i < 4; i++)
        sm[ty + i * 8][tx] = W[(size_t)(k0 + ty + i * 8) * N + n0 + tx];
    __syncthreads();
    #pragma unroll
    for (int i = 0; i < 4; i++) {
        float v = sm[tx][ty + i * 8];
        Th[(size_t)(n0 + ty + i * 8) * K + k0 + tx] = __float2half_rn(v);
    }
}

// ---------------- mma.sync fp16 GEMM (1-term: C = Ah @ Bh^T) ----------------
// MODE 0: C = A@B^T + bias -> fp16 out (QKV projection)
// MODE 1: per-head E = exp(A@B^T / 8) -> fp16 out + atomic denom (QK)
// MODE 2: y = gelu(A@B^T + bias); atomicAdd(out[row], y . W2)  (MLP + final)
#define G_STAGE 32768   /* Ah 16K | Bh 16K */
#define G_SMEM  (2*G_STAGE + 1024)

template<int MODE>
__global__ void __launch_bounds__(256) gemm_mma(
    const __half* __restrict__ Ahi,
    const __half* __restrict__ Bhi,
    const float* __restrict__ bias, const float* __restrict__ xw,
    __half* __restrict__ Chi,
    float* __restrict__ aux,
    int lda, int ldb, int ldc, int K)
{
    extern __shared__ char smraw[];
    uint32_t smb = smem_u32(smraw);
    smb = (smb + 1023u) & ~1023u;

    const int tid = threadIdx.x, lane = tid & 31, warp = tid >> 5;
    const int wm = warp & 1, wn = warp >> 1;

    size_t aOff = 0, bOff = 0, eOff = 0;
    int bh = 0, bb = 0;
    if (MODE == 1) {
        bh = blockIdx.z; bb = bh >> 4;
        const int h = bh & 15;
        aOff = (size_t)bb * L_ * QKV_LD + 1024 + h * DH_;   // K vectors
        bOff = (size_t)bb * L_ * QKV_LD + h * DH_;          // Q vectors
        eOff = (size_t)bh * L_ * L_;
    }
    const int m0g = blockIdx.y * 128, n0g = blockIdx.x * 128;

    const char* gA = (const char*)(Ahi + aOff + (size_t)m0g * lda);
    const char* gB = (const char*)(Bhi + bOff + (size_t)n0g * ldb);

    const int nCh = K >> 6;
    float acc[4][4][4] = {};

    auto loadStage = [&](int st, int k0) {
        #pragma unroll
        for (int arr = 0; arr < 2; arr++) {
            const char* base = (arr == 0) ? gA : gB;
            const int ld2 = ((arr == 0) ? lda : ldb) * 2;
            const uint32_t sb = smb + st * G_STAGE + arr * 16384;
            #pragma unroll
            for (int q = 0; q < 4; q++) {
                int id = tid + q * 256;
                int row = id >> 3, c16 = (id & 7) << 4;
                uint32_t sa = sb + row * 128 + (c16 ^ ((row & 7) << 4));
                cp16(sa, base + (size_t)row * ld2 + k0 * 2 + c16);
            }
        }
    };

    loadStage(0, 0);
    CP_COMMIT();

    for (int c = 0; c < nCh; c++) {
        const int st = c & 1;
        if (c + 1 < nCh) { loadStage(st ^ 1, (c + 1) << 6); CP_COMMIT(); CP_WAIT1(); }
        else             { CP_WAIT0(); }
        __syncthreads();

        const uint32_t sA = smb + st * G_STAGE;
        const uint32_t sB = sA + 16384;
        #pragma unroll
        for (int s = 0; s < 4; s++) {
            const int kb = s * 32;
            uint32_t aH[4][4], bH[4][2];
            const int lr = lane & 15, lc = lane >> 4;
            #pragma unroll
            for (int mt = 0; mt < 4; mt++) {
                int r = wm * 64 + mt * 16 + lr;
                int cb = kb + lc * 16;
                uint32_t ad = sA + r * 128 + (cb ^ ((r & 7) << 4));
                ldsm_x4(aH[mt], ad);
            }
            // B: two x4 loads, each covering a pair of n-tiles
            #pragma unroll
            for (int np = 0; np < 2; np++) {
                int r = wn * 32 + np * 16 + ((lane >> 4) << 3) + (lane & 7);
                int cb = kb + (((lane >> 3) & 1) << 4);
                uint32_t bd = sB + r * 128 + (cb ^ ((r & 7) << 4));
                uint32_t t[4];
                ldsm_x4(t, bd);
                bH[np * 2 + 0][0] = t[0]; bH[np * 2 + 0][1] = t[1];
                bH[np * 2 + 1][0] = t[2]; bH[np * 2 + 1][1] = t[3];
            }
            #pragma unroll
            for (int mt = 0; mt < 4; mt++)
                #pragma unroll
                for (int nt = 0; nt < 4; nt++)
                    mma_f16(acc[mt][nt], aH[mt], bH[nt]);
        }
        __syncthreads();
    }

    // ---- epilogues ----
    if (MODE == 0) {
        #pragma unroll
        for (int mt = 0; mt < 4; mt++) {
            #pragma unroll
            for (int nt = 0; nt < 4; nt++) {
                const int row = m0g + wm * 64 + mt * 16 + (lane >> 2);
                const int col = n0g + wn * 32 + nt * 8 + 2 * (lane & 3);
                float b0 = __ldg(bias + col), b1 = __ldg(bias + col + 1);
                *(__half2*)(Chi + (size_t)row * ldc + col) = __halves2half2(
                    __float2half_rn(acc[mt][nt][0] + b0),
                    __float2half_rn(acc[mt][nt][1] + b1));
                *(__half2*)(Chi + (size_t)(row + 8) * ldc + col) = __halves2half2(
                    __float2half_rn(acc[mt][nt][2] + b0),
                    __float2half_rn(acc[mt][nt][3] + b1));
            }
        }
    } else if (MODE == 1) {
        const float* xb = xw + bb * L_;
        float xc[4][2];
        #pragma unroll
        for (int nt = 0; nt < 4; nt++) {
            int col = n0g + wn * 32 + nt * 8 + 2 * (lane & 3);
            xc[nt][0] = __ldg(xb + col);
            xc[nt][1] = __ldg(xb + col + 1);
        }
        #pragma unroll
        for (int mt = 0; mt < 4; mt++) {
            const int rg = m0g + wm * 64 + mt * 16 + (lane >> 2);
            float p0 = 0.0f, p8 = 0.0f;
            #pragma unroll
            for (int nt = 0; nt < 4; nt++) {
                const int col = n0g + wn * 32 + nt * 8 + 2 * (lane & 3);
                float e0 = __expf(acc[mt][nt][0] * 0.125f);
                float e1 = __expf(acc[mt][nt][1] * 0.125f);
                float e2 = __expf(acc[mt][nt][2] * 0.125f);
                float e3 = __expf(acc[mt][nt][3] * 0.125f);
                *(__half2*)(Chi + eOff + (size_t)rg * ldc + col) =
                    __halves2half2(__float2half_rn(e0), __float2half_rn(e1));
                *(__half2*)(Chi + eOff + (size_t)(rg + 8) * ldc + col) =
                    __halves2half2(__float2half_rn(e2), __float2half_rn(e3));
                p0 += xc[nt][0] * e0 + xc[nt][1] * e1;
                p8 += xc[nt][0] * e2 + xc[nt][1] * e3;
            }
            p0 += __shfl_xor_sync(0xffffffffu, p0, 1);
            p0 += __shfl_xor_sync(0xffffffffu, p0, 2);
            p8 += __shfl_xor_sync(0xffffffffu, p8, 1);
            p8 += __shfl_xor_sync(0xffffffffu, p8, 2);
            if ((lane & 3) == 0) {
                atomicAdd(aux + (size_t)bh * L_ + rg,     p0);
                atomicAdd(aux + (size_t)bh * L_ + rg + 8, p8);
            }
        }
    } else {  // MODE == 2
        #pragma unroll
        for (int mt = 0; mt < 4; mt++) {
            const int row = m0g + wm * 64 + mt * 16 + (lane >> 2);
            float p0 = 0.0f, p8 = 0.0f;
            #pragma unroll
            for (int nt = 0; nt < 4; nt++) {
                const int col = n0g + wn * 32 + nt * 8 + 2 * (lane & 3);
                float b0 = __ldg(bias + col), b1 = __ldg(bias + col + 1);
                float w0 = __ldg(xw + col),  w1 = __ldg(xw + col + 1);
                float v0 = gelu_exact(acc[mt][nt][0] + b0);
                float v1 = gelu_exact(acc[mt][nt][1] + b1);
                float v2 = gelu_exact(acc[mt][nt][2] + b0);
                float v3 = gelu_exact(acc[mt][nt][3] + b1);
                p0 += v0 * w0 + v1 * w1;
                p8 += v2 * w0 + v3 * w1;
            }
            p0 += __shfl_xor_sync(0xffffffffu, p0, 1);
            p0 += __shfl_xor_sync(0xffffffffu, p0, 2);
            p8 += __shfl_xor_sync(0xffffffffu, p8, 1);
            p8 += __shfl_xor_sync(0xffffffffu, p8, 2);
            if ((lane & 3) == 0) {
                atomicAdd(aux + row,     p0);
                atomicAdd(aux + row + 8, p8);
            }
        }
    }
}

// ---------------- U kernel: U[bh][j][d] = x_j * V[b,j,h,d] / den[bh][j] (fp16) ----------------
__global__ void __launch_bounds__(256) u_kernel(const float* __restrict__ x)
{
    int gid = blockIdx.x * 256 + threadIdx.x;
    int d = gid & 63;
    int row = gid >> 6;                          // bh*L + j
    int bh = row >> 11, j = row & (L_ - 1);
    int b = bh >> 4, h = bh & 15;
    float den = g_den[row];
    size_t vo = ((size_t)b * L_ + j) * QKV_LD + 2048 + h * DH_ + d;
    float v = __half2float(g_QKVhi[vo]);
    float u = __ldg(x + b * L_ + j) * v / den;
    g_Uh[(size_t)row * DH_ + d] = __float2half_rn(u);
}

// ---------------- attention output: O[i,d] = x_i * sum_j E[j,i]*U[j,d] ----------------
#define AT_STAGE 24576  /* Eh 16K | Uh 8K */
#define AT_SMEM  (2*AT_STAGE + 1024)

__global__ void __launch_bounds__(256) attn_mma(const float* __restrict__ x)
{
    extern __shared__ char smraw[];
    uint32_t smb = smem_u32(smraw);
    smb = (smb + 1023u) & ~1023u;

    const int tid = threadIdx.x, lane = tid & 31, warp = tid >> 5;
    const int wi = warp & 3, wd = warp >> 2;     // warp tile: 32 i x 32 d
    const int bh = blockIdx.y, b = bh >> 4, h = bh & 15;
    const int i0 = blockIdx.x * 128;

    const char* Ehb = (const char*)(g_Ehi + (size_t)bh * L_ * L_);
    const char* Uhb = (const char*)(g_Uh + (size_t)bh * L_ * DH_);

    float acc[2][4][4] = {};

    auto loadStage = [&](int st, int j0) {
        const uint32_t sb = smb + st * AT_STAGE;
        #pragma unroll
        for (int q = 0; q < 4; q++) {
            int id = tid + q * 256;
            int row = id >> 4, c16 = (id & 15) << 4;
            uint32_t soff = row * 256 + (c16 ^ ((row & 7) << 4));
            size_t go = (size_t)(j0 + row) * (L_ * 2) + (size_t)i0 * 2 + c16;
            cp16(sb + soff, Ehb + go);
        }
        #pragma unroll
        for (int q = 0; q < 2; q++) {
            int id = tid + q * 256;
            int row = id >> 3, c16 = (id & 7) << 4;
            uint32_t uoff = row * 128 + (c16 ^ ((row & 7) << 4));
            cp16(sb + 16384 + uoff, Uhb + (size_t)(j0 + row) * 128 + c16);
        }
    };

    loadStage(0, 0);
    CP_COMMIT();

    for (int c = 0; c < L_ / 64; c++) {
        const int st = c & 1;
        if (c + 1 < L_ / 64) { loadStage(st ^ 1, (c + 1) * 64); CP_COMMIT(); CP_WAIT1(); }
        else                 { CP_WAIT0(); }
        __syncthreads();

        const uint32_t sb = smb + st * AT_STAGE;
        #pragma unroll
        for (int s = 0; s < 4; s++) {
            const int k0 = s * 16;
            uint32_t eH[2][4], uH[4][2];
            {
                const int r = k0 + (lane & 7) + ((lane >> 4) << 3);
                const int cbl = (((lane >> 3) & 1) << 4);
                #pragma unroll
                for (int mt = 0; mt < 2; mt++) {
                    int cb = (wi * 32 + mt * 16) * 2 + cbl;
                    uint32_t ad = sb + r * 256 + (cb ^ ((r & 7) << 4));
                    ldsm_x4t(eH[mt], ad);
                }
            }
            // U: two x4t loads, each covering a pair of n(d)-tiles
            {
                const int r = k0 + (lane & 7) + (((lane >> 3) & 1) << 3);
                #pragma unroll
                for (int np = 0; np < 2; np++) {
                    int cb = (wd * 32 + np * 16 + ((lane >> 4) << 3)) * 2;
                    uint32_t ud = sb + 16384 + r * 128 + (cb ^ ((r & 7) << 4));
                    uint32_t t[4];
                    ldsm_x4t(t, ud);
                    uH[np * 2 + 0][0] = t[0]; uH[np * 2 + 0][1] = t[1];
                    uH[np * 2 + 1][0] = t[2]; uH[np * 2 + 1][1] = t[3];
                }
            }
            #pragma unroll
            for (int mt = 0; mt < 2; mt++)
                #pragma unroll
                for (int nt = 0; nt < 4; nt++)
                    mma_f16(acc[mt][nt], eH[mt], uH[nt]);
        }
        __syncthreads();
    }

    // epilogue: O fp16 hi-only into g_Ahi [ML][E]
    #pragma unroll
    for (int mt = 0; mt < 2; mt++) {
        #pragma unroll
        for (int nt = 0; nt < 4; nt++) {
            const int row = i0 + wi * 32 + mt * 16 + (lane >> 2);
            const int col = h * DH_ + wd * 32 + nt * 8 + 2 * (lane & 3);
            float x0 = __ldg(x + b * L_ + row);
            float x1 = __ldg(x + b * L_ + row + 8);
            size_t r0 = ((size_t)b * L_ + row) * E_ + col;
            size_t r8 = ((size_t)b * L_ + row + 8) * E_ + col;
            *(__half2*)(g_Ahi + r0) = __halves2half2(
                __float2half_rn(acc[mt][nt][0] * x0),
                __float2half_rn(acc[mt][nt][1] * x0));
            *(__half2*)(g_Ahi + r8) = __halves2half2(
                __float2half_rn(acc[mt][nt][2] * x1),
                __float2half_rn(acc[mt][nt][3] * x1));
        }
    }
}

// ---------------- launch ----------------
extern "C" void kernel_launch(void* const* d_in, const int* in_sizes, int n_in,
                              void* d_out, int out_size)
{
    (void)in_sizes; (void)n_in; (void)out_size;
    const float* x  = (const float*)d_in[0];
    const float* z  = (const float*)d_in[1];
    const float* Wq = (const float*)d_in[2];
    const float* bq = (const float*)d_in[3];
    const float* Wk = (const float*)d_in[4];
    const float* bk = (const float*)d_in[5];
    const float* Wv = (const float*)d_in[6];
    const float* bv = (const float*)d_in[7];
    const float* W1 = (const float*)d_in[8];
    const float* b1 = (const float*)d_in[9];
    const float* W2 = (const float*)d_in[10];
    const float* b2 = (const float*)d_in[11];
    float* out = (float*)d_out;

    __half *pAhi, *pBhi, *pQKVhi, *pEhi;
    float *pDen, *pBiasP;
    cudaGetSymbolAddress((void**)&pAhi, g_Ahi);
    cudaGetSymbolAddress((void**)&pBhi, g_Bthi);
    cudaGetSymbolAddress((void**)&pQKVhi, g_QKVhi);
    cudaGetSymbolAddress((void**)&pEhi, g_Ehi);
    cudaGetSymbolAddress((void**)&pDen, g_den);
    cudaGetSymbolAddress((void**)&pBiasP, g_biasP);

    cudaFuncSetAttribute(gemm_mma<0>, cudaFuncAttributeMaxDynamicSharedMemorySize, G_SMEM);
    cudaFuncSetAttribute(gemm_mma<1>, cudaFuncAttributeMaxDynamicSharedMemorySize, G_SMEM);
    cudaFuncSetAttribute(gemm_mma<2>, cudaFuncAttributeMaxDynamicSharedMemorySize, G_SMEM);
    cudaFuncSetAttribute(attn_mma, cudaFuncAttributeMaxDynamicSharedMemorySize, AT_SMEM);

    const size_t nZ = (size_t)ML_ * E_;

    // init: packed bias, out = b2, den = 0
    init_kernel<<<256, 256>>>(bq, bk, bv, b2, out);

    // convert z -> fp16 hi
    convert_hi<<<nZ / 1024, 256>>>(z, pAhi);

    // pack transposed QKV weights (fused, hi only)
    transpose_qkv<<<dim3(E_ / 32, E_ / 32, 3), 256>>>(Wq, Wk, Wv, pBhi);

    // fused QKV projection -> fp16 [ML][3072]  (1-term, hi out)
    gemm_mma<0><<<dim3(QKV_LD / 128, ML_ / 128), 256, G_SMEM>>>(
        pAhi, pBhi, pBiasP, nullptr, pQKVhi, nullptr,
        E_, E_, QKV_LD, E_);

    // QK: E = exp(K_j . Q_i / 8) fp16 + atomic denom  (1-term)
    gemm_mma<1><<<dim3(L_ / 128, L_ / 128, BH_), 256, G_SMEM>>>(
        pQKVhi, pQKVhi, nullptr, x, pEhi, pDen,
        QKV_LD, QKV_LD, L_, DH_);

    // U = x_j * V / den, fp16
    u_kernel<<<(BH_ * L_ * DH_) / 256, 256>>>(x);

    // attention output -> O fp16 (hi only, into g_Ahi)  (1-term)
    attn_mma<<<dim3(L_ / 128, BH_), 256, AT_SMEM>>>(x);

    // W1 transpose (hi only)
    transpose_hi<<<dim3(HID_ / 32, E_ / 32), 256>>>(W1, pBhi, E_, HID_);

    // MLP1 + fused W2 reduction -> out (atomic, 1-term)
    gemm_mma<2><<<dim3(HID_ / 128, ML_ / 128), 256, G_SMEM>>>(
        pAhi, pBhi, b1, W2, nullptr, out,
        E_, E_, 0, E_);
}